// round 6
// baseline (speedup 1.0000x reference)
#include <cuda_runtime.h>
#include <cuda_fp16.h>
#include <math.h>
#include <stdint.h>

// Problem constants
#define BATCH   16
#define SEQ     1024
#define TOKENS  (BATCH*SEQ)     // 16384
#define CDIM    768
#define C3      (3*CDIM)        // 2304
#define HID     3072
#define NHEADS  12
#define HDIM    64
#define LN_EPS  1e-5f

// ---------------------------------------------------------------------------
// Scratch (device globals; allocation APIs are forbidden)
// ---------------------------------------------------------------------------
__device__ __half g_xn1 [ (size_t)TOKENS * CDIM ];
__device__ __half g_qkv [ (size_t)TOKENS * C3   ];
__device__ __half g_attn[ (size_t)TOKENS * CDIM ];
__device__ float  g_x2  [ (size_t)TOKENS * CDIM ];
__device__ __half g_hn  [ (size_t)TOKENS * CDIM ];
__device__ __half g_h1  [ (size_t)TOKENS * HID  ];
// fp16, TRANSPOSED weights: wT[n][k]
__device__ __half g_wq  [ (size_t)C3   * CDIM ];
__device__ __half g_wp  [ (size_t)CDIM * CDIM ];
__device__ __half g_w1  [ (size_t)HID  * CDIM ];
__device__ __half g_w2  [ (size_t)CDIM * HID  ];

// ---------------------------------------------------------------------------
// Helpers
// ---------------------------------------------------------------------------
__device__ __forceinline__ float ex2f(float x) {
    float y;
    asm("ex2.approx.f32 %0, %1;" : "=f"(y) : "f"(x));
    return y;
}
__device__ __forceinline__ void mma_f16(float* c, const uint32_t* a, const uint32_t* b) {
    asm volatile(
        "mma.sync.aligned.m16n8k16.row.col.f32.f16.f16.f32 "
        "{%0,%1,%2,%3}, {%4,%5,%6,%7}, {%8,%9}, {%0,%1,%2,%3};"
        : "+f"(c[0]), "+f"(c[1]), "+f"(c[2]), "+f"(c[3])
        : "r"(a[0]), "r"(a[1]), "r"(a[2]), "r"(a[3]), "r"(b[0]), "r"(b[1]));
}
__device__ __forceinline__ void cpasync16(void* smem_ptr, const void* gmem_ptr) {
    uint32_t s = (uint32_t)__cvta_generic_to_shared(smem_ptr);
    asm volatile("cp.async.cg.shared.global [%0], [%1], 16;" :: "r"(s), "l"(gmem_ptr));
}
__device__ __forceinline__ void ldmx4(uint32_t* r, uint32_t saddr) {
    asm volatile("ldmatrix.sync.aligned.m8n8.x4.shared.b16 {%0,%1,%2,%3}, [%4];"
                 : "=r"(r[0]), "=r"(r[1]), "=r"(r[2]), "=r"(r[3]) : "r"(saddr));
}
__device__ __forceinline__ uint32_t h2pack(float lo, float hi) {
    __half2 h = __floats2half2_rn(lo, hi);
    return *reinterpret_cast<uint32_t*>(&h);
}

// ---------------------------------------------------------------------------
// Weight prep: transpose + fp16. out[n*K + k] = half(in[k*N + n])
// ---------------------------------------------------------------------------
__global__ __launch_bounds__(256)
void wprep_kernel(const float* __restrict__ in, __half* __restrict__ out, int K, int N)
{
    __shared__ float t[32][33];
    int n0 = blockIdx.x * 32, k0 = blockIdx.y * 32;
    int tx = threadIdx.x, ty = threadIdx.y;
    #pragma unroll
    for (int j = 0; j < 4; j++) {
        int kk = j * 8 + ty;
        t[kk][tx] = in[(size_t)(k0 + kk) * N + n0 + tx];
    }
    __syncthreads();
    #pragma unroll
    for (int j = 0; j < 4; j++) {
        int nn = j * 8 + ty;
        out[(size_t)(n0 + nn) * K + k0 + tx] = __float2half_rn(t[tx][nn]);
    }
}

// ---------------------------------------------------------------------------
// LayerNorm: fp32 in, half out
// ---------------------------------------------------------------------------
__global__ __launch_bounds__(256)
void ln_kernel(const float* __restrict__ x, const float* __restrict__ gam,
               const float* __restrict__ bet, __half* __restrict__ out)
{
    int row = blockIdx.x;
    int tid = threadIdx.x;
    const float* xr = x + (size_t)row * CDIM;

    float v0 = xr[tid], v1 = xr[tid + 256], v2 = xr[tid + 512];

    __shared__ float red[8];
    __shared__ float mu_s, rs_s;

    float s = v0 + v1 + v2;
    #pragma unroll
    for (int off = 16; off > 0; off >>= 1) s += __shfl_xor_sync(0xffffffffu, s, off);
    if ((tid & 31) == 0) red[tid >> 5] = s;
    __syncthreads();
    if (tid == 0) {
        float t = 0.f;
        #pragma unroll
        for (int i = 0; i < 8; i++) t += red[i];
        mu_s = t * (1.0f / CDIM);
    }
    __syncthreads();
    float mu = mu_s;
    float d0 = v0 - mu, d1 = v1 - mu, d2 = v2 - mu;

    float q = d0*d0 + d1*d1 + d2*d2;
    #pragma unroll
    for (int off = 16; off > 0; off >>= 1) q += __shfl_xor_sync(0xffffffffu, q, off);
    __syncthreads();
    if ((tid & 31) == 0) red[tid >> 5] = q;
    __syncthreads();
    if (tid == 0) {
        float t = 0.f;
        #pragma unroll
        for (int i = 0; i < 8; i++) t += red[i];
        rs_s = rsqrtf(t * (1.0f / CDIM) + LN_EPS);
    }
    __syncthreads();
    float rs = rs_s;

    __half* orow = out + (size_t)row * CDIM;
    orow[tid      ] = __float2half_rn(d0 * rs * gam[tid      ] + bet[tid      ]);
    orow[tid + 256] = __float2half_rn(d1 * rs * gam[tid + 256] + bet[tid + 256]);
    orow[tid + 512] = __float2half_rn(d2 * rs * gam[tid + 512] + bet[tid + 512]);
}

// ---------------------------------------------------------------------------
// FP16 tensor-core GEMM: C[M,N] = A[M,K] @ Bt[N,K]^T + bias (+GELU)(+resid)
// CTA tile 128x256, 8 warps (64x64 warp tiles, 2Mx4N grid), BK=64,
// ldmatrix.x4 fragment loads, 3-stage cp.async pipeline.
// Smem rows padded to 144B: cp.async stores and ldmatrix phases conflict-free.
// M%128==0, N%256==0, K%64==0.
// ---------------------------------------------------------------------------
#define BK 64
#define ROWW 36                       // words per smem row (72 halves = 144 B)
#define ROWB 144
#define STAGE_W ((128 + 256) * ROWW)  // 13824 words / stage
#define BOFF_W (128 * ROWW)           // B rows start after 128 A rows
#define GEMM_SMEM_BYTES (3 * STAGE_W * 4)   // 165888

template<bool DO_GELU, bool DO_RESID, bool OUT_HALF>
__global__ __launch_bounds__(256, 1)
void hgemm(const __half* __restrict__ A, const __half* __restrict__ Bt,
           const float* __restrict__ bias, const float* __restrict__ resid,
           void* __restrict__ Cv, int M, int N, int K)
{
    extern __shared__ __align__(16) uint32_t smw[];

    int tid  = threadIdx.x;
    int warp = tid >> 5;
    int lane = tid & 31;
    int gr   = lane >> 2;          // 0..7
    int t4   = lane & 3;           // 0..3
    int row0 = blockIdx.y * 128;
    int col0 = blockIdx.x * 256;
    int wm   = (warp >> 2) * 64;   // 0 or 64
    int wn   = (warp & 3) * 64;    // 0,64,128,192

    uint32_t sbase = (uint32_t)__cvta_generic_to_shared(smw);

    // ldmatrix per-lane byte offsets (within a stage)
    // A tile (mt,ks): row = wm + mt*16 + (lane&15); col halves = ks*16 + (lane>>4)*8
    uint32_t aoff = (uint32_t)(wm + (lane & 15)) * ROWB + (uint32_t)(lane >> 4) * 16;
    // B tile (nt,ks): row = wn + nt*16 + (lane&7) + (lane>>4)*8 ; col halves = ks*16 + ((lane>>3)&1)*8
    uint32_t boff = BOFF_W * 4 +
                    (uint32_t)(wn + (lane & 7) + (lane >> 4) * 8) * ROWB +
                    (uint32_t)((lane >> 3) & 1) * 16;

    float acc[4][8][4];
    #pragma unroll
    for (int i = 0; i < 4; i++)
        #pragma unroll
        for (int j = 0; j < 8; j++)
            #pragma unroll
            for (int r = 0; r < 4; r++) acc[i][j][r] = 0.f;

    int ldr = tid >> 3;            // 0..31
    int ldc = tid & 7;             // 16B chunk 0..7

    auto load_tiles = [&](int st, int kt) {
        int k0 = kt * BK;
        const __half* Ab = A  + (size_t)row0 * K + k0;
        const __half* Bb = Bt + (size_t)col0 * K + k0;
        uint32_t* sa = &smw[st * STAGE_W];
        uint32_t* sb = &smw[st * STAGE_W + BOFF_W];
        #pragma unroll
        for (int i = 0; i < 4; i++) {
            int r = ldr + i * 32;                 // 0..127
            cpasync16(&sa[r * ROWW + ldc * 4], Ab + (size_t)r * K + ldc * 8);
        }
        #pragma unroll
        for (int i = 0; i < 8; i++) {
            int r = ldr + i * 32;                 // 0..255
            cpasync16(&sb[r * ROWW + ldc * 4], Bb + (size_t)r * K + ldc * 8);
        }
        asm volatile("cp.async.commit_group;");
    };

    int KT = K / BK;
    load_tiles(0, 0);
    load_tiles(1, 1);

    for (int kt = 0; kt < KT; kt++) {
        if (kt + 1 < KT) asm volatile("cp.async.wait_group 1;" ::: "memory");
        else             asm volatile("cp.async.wait_group 0;" ::: "memory");
        __syncthreads();
        if (kt + 2 < KT) load_tiles((kt + 2) % 3, kt + 2);

        uint32_t stb = sbase + (uint32_t)((kt % 3) * STAGE_W * 4);
        #pragma unroll
        for (int ks = 0; ks < 4; ks++) {
            uint32_t af[4][4], bf[4][4];
            #pragma unroll
            for (int mt = 0; mt < 4; mt++)
                ldmx4(af[mt], stb + aoff + (uint32_t)(mt * 16 * ROWB + ks * 32));
            #pragma unroll
            for (int nt = 0; nt < 4; nt++)
                ldmx4(bf[nt], stb + boff + (uint32_t)(nt * 16 * ROWB + ks * 32));
            #pragma unroll
            for (int mt = 0; mt < 4; mt++)
                #pragma unroll
                for (int nt = 0; nt < 4; nt++) {
                    mma_f16(acc[mt][2*nt    ], af[mt], &bf[nt][0]);
                    mma_f16(acc[mt][2*nt + 1], af[mt], &bf[nt][2]);
                }
        }
        __syncthreads();
    }

    // Epilogue
    #pragma unroll
    for (int i = 0; i < 4; i++) {
        int r0 = row0 + wm + i * 16 + gr;
        #pragma unroll
        for (int j = 0; j < 8; j++) {
            int cc = col0 + wn + j * 8 + 2 * t4;
            float2 bb = *(const float2*)&bias[cc];
            float v0 = acc[i][j][0] + bb.x;
            float v1 = acc[i][j][1] + bb.y;
            float v2 = acc[i][j][2] + bb.x;
            float v3 = acc[i][j][3] + bb.y;
            if (DO_GELU) {
                v0 = 0.5f * v0 * (1.0f + erff(v0 * 0.70710678118654752f));
                v1 = 0.5f * v1 * (1.0f + erff(v1 * 0.70710678118654752f));
                v2 = 0.5f * v2 * (1.0f + erff(v2 * 0.70710678118654752f));
                v3 = 0.5f * v3 * (1.0f + erff(v3 * 0.70710678118654752f));
            }
            size_t o0 = (size_t)r0 * N + cc;
            size_t o1 = (size_t)(r0 + 8) * N + cc;
            if (DO_RESID) {
                float2 ra = *(const float2*)&resid[o0];
                float2 rb = *(const float2*)&resid[o1];
                v0 += ra.x; v1 += ra.y; v2 += rb.x; v3 += rb.y;
            }
            if (OUT_HALF) {
                uint32_t* C = (uint32_t*)Cv;
                C[o0 >> 1] = h2pack(v0, v1);
                C[o1 >> 1] = h2pack(v2, v3);
            } else {
                float* C = (float*)Cv;
                *(float2*)&C[o0] = make_float2(v0, v1);
                *(float2*)&C[o1] = make_float2(v2, v3);
            }
        }
    }
}

// ---------------------------------------------------------------------------
// FP16 tensor-core flash attention (unchanged from R5).
// ---------------------------------------------------------------------------
#define AQ_W 0
#define AK_W 2304
#define AV_W 4608
#define ATTN_SMEM (3 * 2304 * 4)    // 27648 B

__global__ __launch_bounds__(128)
void attn_h(const __half* __restrict__ qkv, __half* __restrict__ outp)
{
    extern __shared__ uint32_t smq[];

    int tid  = threadIdx.x;
    int warp = tid >> 5;
    int lane = tid & 31;
    int gr   = lane >> 2;
    int t4   = lane & 3;
    int qb   = blockIdx.x * 64;
    int b    = blockIdx.y / NHEADS;
    int h    = blockIdx.y % NHEADS;
    const __half* base = qkv + (size_t)b * SEQ * C3 + h * HDIM;

    const float SCL = 0.125f * 1.4426950408889634f;

    #pragma unroll
    for (int i = 0; i < 4; i++) {
        int idx = tid + i * 128;
        int r = idx >> 3, c8 = idx & 7;
        uint4 v = *(const uint4*)(base + (size_t)(qb + r) * C3 + c8 * 8);
        *(uint4*)&smq[AQ_W + r * ROWW + c8 * 4] = v;
    }
    __syncthreads();

    uint32_t qf[4][4];
    #pragma unroll
    for (int ks = 0; ks < 4; ks++) {
        int bidx = AQ_W + (16 * warp + gr) * ROWW + ks * 8 + t4;
        qf[ks][0] = smq[bidx];
        qf[ks][1] = smq[bidx + 8 * ROWW];
        qf[ks][2] = smq[bidx + 4];
        qf[ks][3] = smq[bidx + 8 * ROWW + 4];
    }

    float m1 = -1e30f, m2 = -1e30f, l1 = 0.f, l2 = 0.f;
    float oc[8][4];
    #pragma unroll
    for (int j = 0; j < 8; j++)
        #pragma unroll
        for (int r = 0; r < 4; r++) oc[j][r] = 0.f;

    for (int kt = 0; kt < SEQ / 64; kt++) {
        __syncthreads();
        #pragma unroll
        for (int i = 0; i < 4; i++) {
            int idx = tid + i * 128;
            int r = idx >> 3, c8 = idx & 7;
            uint4 v = *(const uint4*)(base + (size_t)(kt * 64 + r) * C3 + CDIM + c8 * 8);
            *(uint4*)&smq[AK_W + r * ROWW + c8 * 4] = v;
        }
        #pragma unroll
        for (int i = 0; i < 2; i++) {
            int idx = tid + i * 128;
            int c8 = idx >> 5;
            int rp = idx & 31;
            const __half* s0 = base + (size_t)(kt * 64 + 2 * rp) * C3 + 2 * CDIM + c8 * 8;
            uint4 va = *(const uint4*)s0;
            uint4 vb = *(const uint4*)(s0 + C3);
            __half a[8], c[8];
            *(uint4*)a = va; *(uint4*)c = vb;
            #pragma unroll
            for (int j = 0; j < 8; j++) {
                __half2 p = __halves2half2(a[j], c[j]);
                smq[AV_W + (c8 * 8 + j) * ROWW + rp] = *reinterpret_cast<uint32_t*>(&p);
            }
        }
        __syncthreads();

        float sc[8][4];
        #pragma unroll
        for (int j = 0; j < 8; j++)
            #pragma unroll
            for (int r = 0; r < 4; r++) sc[j][r] = 0.f;

        #pragma unroll
        for (int ks = 0; ks < 4; ks++) {
            int kw = ks * 8 + t4;
            uint32_t kf[8][2];
            #pragma unroll
            for (int j = 0; j < 8; j++) {
                int bidx = AK_W + (j * 8 + gr) * ROWW + kw;
                kf[j][0] = smq[bidx];
                kf[j][1] = smq[bidx + 4];
            }
            #pragma unroll
            for (int j = 0; j < 8; j++)
                mma_f16(sc[j], qf[ks], kf[j]);
        }
        #pragma unroll
        for (int j = 0; j < 8; j++) {
            sc[j][0] *= SCL; sc[j][1] *= SCL; sc[j][2] *= SCL; sc[j][3] *= SCL;
        }

        float mx1 = -1e30f, mx2 = -1e30f;
        #pragma unroll
        for (int j = 0; j < 8; j++) {
            mx1 = fmaxf(mx1, fmaxf(sc[j][0], sc[j][1]));
            mx2 = fmaxf(mx2, fmaxf(sc[j][2], sc[j][3]));
        }
        mx1 = fmaxf(mx1, __shfl_xor_sync(0xffffffffu, mx1, 1));
        mx1 = fmaxf(mx1, __shfl_xor_sync(0xffffffffu, mx1, 2));
        mx2 = fmaxf(mx2, __shfl_xor_sync(0xffffffffu, mx2, 1));
        mx2 = fmaxf(mx2, __shfl_xor_sync(0xffffffffu, mx2, 2));

        float nm1 = fmaxf(m1, mx1), nm2 = fmaxf(m2, mx2);
        float a1 = ex2f(m1 - nm1), a2 = ex2f(m2 - nm2);
        float s1 = 0.f, s2 = 0.f;
        uint32_t ph[8][2];
        #pragma unroll
        for (int j = 0; j < 8; j++) {
            float p0 = ex2f(sc[j][0] - nm1);
            float p1 = ex2f(sc[j][1] - nm1);
            float p2 = ex2f(sc[j][2] - nm2);
            float p3 = ex2f(sc[j][3] - nm2);
            s1 += p0 + p1; s2 += p2 + p3;
            ph[j][0] = h2pack(p0, p1);
            ph[j][1] = h2pack(p2, p3);
        }
        s1 += __shfl_xor_sync(0xffffffffu, s1, 1);
        s1 += __shfl_xor_sync(0xffffffffu, s1, 2);
        s2 += __shfl_xor_sync(0xffffffffu, s2, 1);
        s2 += __shfl_xor_sync(0xffffffffu, s2, 2);
        l1 = l1 * a1 + s1;  l2 = l2 * a2 + s2;
        m1 = nm1;           m2 = nm2;
        #pragma unroll
        for (int j = 0; j < 8; j++) {
            oc[j][0] *= a1; oc[j][1] *= a1;
            oc[j][2] *= a2; oc[j][3] *= a2;
        }

        #pragma unroll
        for (int ks = 0; ks < 4; ks++) {
            uint32_t pf[4] = { ph[2*ks][0], ph[2*ks][1], ph[2*ks+1][0], ph[2*ks+1][1] };
            int kw = ks * 8 + t4;
            uint32_t vf[8][2];
            #pragma unroll
            for (int j = 0; j < 8; j++) {
                int bidx = AV_W + (j * 8 + gr) * ROWW + kw;
                vf[j][0] = smq[bidx];
                vf[j][1] = smq[bidx + 4];
            }
            #pragma unroll
            for (int j = 0; j < 8; j++)
                mma_f16(oc[j], pf, vf[j]);
        }
    }

    float il1 = 1.0f / l1, il2 = 1.0f / l2;
    int r1 = qb + 16 * warp + gr;
    uint32_t* o32 = (uint32_t*)outp;
    #pragma unroll
    for (int j = 0; j < 8; j++) {
        int cc = h * HDIM + j * 8 + 2 * t4;
        size_t o0 = ((size_t)(b * SEQ + r1) * CDIM + cc) >> 1;
        size_t o1 = o0 + 4 * CDIM;
        o32[o0] = h2pack(oc[j][0] * il1, oc[j][1] * il1);
        o32[o1] = h2pack(oc[j][2] * il2, oc[j][3] * il2);
    }
}

// ---------------------------------------------------------------------------
// Launch
// ---------------------------------------------------------------------------
extern "C" void kernel_launch(void* const* d_in, const int* in_sizes, int n_in,
                              void* d_out, int out_size)
{
    const float* x      = (const float*)d_in[0];
    const float* ln1_g  = (const float*)d_in[1];
    const float* ln1_b  = (const float*)d_in[2];
    const float* qkv_w  = (const float*)d_in[3];
    const float* qkv_b  = (const float*)d_in[4];
    const float* proj_w = (const float*)d_in[5];
    const float* proj_b = (const float*)d_in[6];
    const float* ln2_g  = (const float*)d_in[7];
    const float* ln2_b  = (const float*)d_in[8];
    const float* fc1_w  = (const float*)d_in[9];
    const float* fc1_b  = (const float*)d_in[10];
    const float* fc2_w  = (const float*)d_in[11];
    const float* fc2_b  = (const float*)d_in[12];
    float* out = (float*)d_out;

    __half *p_xn1, *p_qkv, *p_attn, *p_hn, *p_h1;
    __half *p_wq, *p_wp, *p_w1, *p_w2;
    float  *p_x2;
    cudaGetSymbolAddress((void**)&p_xn1,  g_xn1);
    cudaGetSymbolAddress((void**)&p_qkv,  g_qkv);
    cudaGetSymbolAddress((void**)&p_attn, g_attn);
    cudaGetSymbolAddress((void**)&p_x2,   g_x2);
    cudaGetSymbolAddress((void**)&p_hn,   g_hn);
    cudaGetSymbolAddress((void**)&p_h1,   g_h1);
    cudaGetSymbolAddress((void**)&p_wq,   g_wq);
    cudaGetSymbolAddress((void**)&p_wp,   g_wp);
    cudaGetSymbolAddress((void**)&p_w1,   g_w1);
    cudaGetSymbolAddress((void**)&p_w2,   g_w2);

    cudaFuncSetAttribute(attn_h,
                         cudaFuncAttributeMaxDynamicSharedMemorySize, ATTN_SMEM);
    cudaFuncSetAttribute(hgemm<false,false,true>,
                         cudaFuncAttributeMaxDynamicSharedMemorySize, GEMM_SMEM_BYTES);
    cudaFuncSetAttribute(hgemm<false,true,false>,
                         cudaFuncAttributeMaxDynamicSharedMemorySize, GEMM_SMEM_BYTES);
    cudaFuncSetAttribute(hgemm<true,false,true>,
                         cudaFuncAttributeMaxDynamicSharedMemorySize, GEMM_SMEM_BYTES);

    // 0) Weight prep: transpose + fp16
    wprep_kernel<<<dim3(C3/32,   CDIM/32), dim3(32,8)>>>(qkv_w,  p_wq, CDIM, C3);
    wprep_kernel<<<dim3(CDIM/32, CDIM/32), dim3(32,8)>>>(proj_w, p_wp, CDIM, CDIM);
    wprep_kernel<<<dim3(HID/32,  CDIM/32), dim3(32,8)>>>(fc1_w,  p_w1, CDIM, HID);
    wprep_kernel<<<dim3(CDIM/32, HID/32 ), dim3(32,8)>>>(fc2_w,  p_w2, HID,  CDIM);

    // 1) LN1
    ln_kernel<<<TOKENS, 256>>>(x, ln1_g, ln1_b, p_xn1);

    // 2) qkv = xn1 @ qkv_w + qkv_b  (half out)
    hgemm<false,false,true><<<dim3(C3/256, TOKENS/128), 256, GEMM_SMEM_BYTES>>>(
        p_xn1, p_wq, qkv_b, nullptr, p_qkv, TOKENS, C3, CDIM);

    // 3) attention (half out)
    attn_h<<<dim3(SEQ/64, BATCH*NHEADS), 128, ATTN_SMEM>>>(p_qkv, p_attn);

    // 4) x2 = x + attn @ proj_w + proj_b  (fp32 out)
    hgemm<false,true,false><<<dim3(CDIM/256, TOKENS/128), 256, GEMM_SMEM_BYTES>>>(
        p_attn, p_wp, proj_b, x, p_x2, TOKENS, CDIM, CDIM);

    // 5) LN2
    ln_kernel<<<TOKENS, 256>>>(p_x2, ln2_g, ln2_b, p_hn);

    // 6) h1 = gelu(hn @ fc1_w + fc1_b)  (half out)
    hgemm<true,false,true><<<dim3(HID/256, TOKENS/128), 256, GEMM_SMEM_BYTES>>>(
        p_hn, p_w1, fc1_b, nullptr, p_h1, TOKENS, HID, CDIM);

    // 7) out = x2 + h1 @ fc2_w + fc2_b  (fp32 out)
    hgemm<false,true,false><<<dim3(CDIM/256, TOKENS/128), 256, GEMM_SMEM_BYTES>>>(
        p_h1, p_w2, fc2_b, p_x2, out, TOKENS, CDIM, HID);
}

// round 7
// speedup vs baseline: 1.2057x; 1.2057x over previous
#include <cuda_runtime.h>
#include <cuda_fp16.h>
#include <math.h>
#include <stdint.h>

// Problem constants
#define BATCH   16
#define SEQ     1024
#define TOKENS  (BATCH*SEQ)     // 16384
#define CDIM    768
#define C3      (3*CDIM)        // 2304
#define HID     3072
#define NHEADS  12
#define HDIM    64
#define LN_EPS  1e-5f

// ---------------------------------------------------------------------------
// Scratch (device globals; allocation APIs are forbidden)
// ---------------------------------------------------------------------------
__device__ __half g_xn1 [ (size_t)TOKENS * CDIM ];
__device__ __half g_qkv [ (size_t)TOKENS * C3   ];
__device__ __half g_attn[ (size_t)TOKENS * CDIM ];
__device__ float  g_x2  [ (size_t)TOKENS * CDIM ];
__device__ __half g_hn  [ (size_t)TOKENS * CDIM ];
__device__ __half g_h1  [ (size_t)TOKENS * HID  ];
// fp16, TRANSPOSED weights: wT[n][k]
__device__ __half g_wq  [ (size_t)C3   * CDIM ];
__device__ __half g_wp  [ (size_t)CDIM * CDIM ];
__device__ __half g_w1  [ (size_t)HID  * CDIM ];
__device__ __half g_w2  [ (size_t)CDIM * HID  ];

// ---------------------------------------------------------------------------
// Helpers
// ---------------------------------------------------------------------------
__device__ __forceinline__ float ex2f(float x) {
    float y;
    asm("ex2.approx.f32 %0, %1;" : "=f"(y) : "f"(x));
    return y;
}
__device__ __forceinline__ void mma_f16(float* c, const uint32_t* a, const uint32_t* b) {
    asm volatile(
        "mma.sync.aligned.m16n8k16.row.col.f32.f16.f16.f32 "
        "{%0,%1,%2,%3}, {%4,%5,%6,%7}, {%8,%9}, {%0,%1,%2,%3};"
        : "+f"(c[0]), "+f"(c[1]), "+f"(c[2]), "+f"(c[3])
        : "r"(a[0]), "r"(a[1]), "r"(a[2]), "r"(a[3]), "r"(b[0]), "r"(b[1]));
}
__device__ __forceinline__ void cpasync16(void* smem_ptr, const void* gmem_ptr) {
    uint32_t s = (uint32_t)__cvta_generic_to_shared(smem_ptr);
    asm volatile("cp.async.cg.shared.global [%0], [%1], 16;" :: "r"(s), "l"(gmem_ptr));
}
__device__ __forceinline__ void ldmx4(uint32_t* r, uint32_t saddr) {
    asm volatile("ldmatrix.sync.aligned.m8n8.x4.shared.b16 {%0,%1,%2,%3}, [%4];"
                 : "=r"(r[0]), "=r"(r[1]), "=r"(r[2]), "=r"(r[3]) : "r"(saddr));
}
__device__ __forceinline__ void ldmx4t(uint32_t* r, uint32_t saddr) {
    asm volatile("ldmatrix.sync.aligned.m8n8.x4.trans.shared.b16 {%0,%1,%2,%3}, [%4];"
                 : "=r"(r[0]), "=r"(r[1]), "=r"(r[2]), "=r"(r[3]) : "r"(saddr));
}
__device__ __forceinline__ uint32_t h2pack(float lo, float hi) {
    __half2 h = __floats2half2_rn(lo, hi);
    return *reinterpret_cast<uint32_t*>(&h);
}

// ---------------------------------------------------------------------------
// Weight prep: transpose + fp16. out[n*K + k] = half(in[k*N + n])
// ---------------------------------------------------------------------------
__global__ __launch_bounds__(256)
void wprep_kernel(const float* __restrict__ in, __half* __restrict__ out, int K, int N)
{
    __shared__ float t[32][33];
    int n0 = blockIdx.x * 32, k0 = blockIdx.y * 32;
    int tx = threadIdx.x, ty = threadIdx.y;
    #pragma unroll
    for (int j = 0; j < 4; j++) {
        int kk = j * 8 + ty;
        t[kk][tx] = in[(size_t)(k0 + kk) * N + n0 + tx];
    }
    __syncthreads();
    #pragma unroll
    for (int j = 0; j < 4; j++) {
        int nn = j * 8 + ty;
        out[(size_t)(n0 + nn) * K + k0 + tx] = __float2half_rn(t[tx][nn]);
    }
}

// ---------------------------------------------------------------------------
// LayerNorm: fp32 in, half out
// ---------------------------------------------------------------------------
__global__ __launch_bounds__(256)
void ln_kernel(const float* __restrict__ x, const float* __restrict__ gam,
               const float* __restrict__ bet, __half* __restrict__ out)
{
    int row = blockIdx.x;
    int tid = threadIdx.x;
    const float* xr = x + (size_t)row * CDIM;

    float v0 = xr[tid], v1 = xr[tid + 256], v2 = xr[tid + 512];

    __shared__ float red[8];
    __shared__ float mu_s, rs_s;

    float s = v0 + v1 + v2;
    #pragma unroll
    for (int off = 16; off > 0; off >>= 1) s += __shfl_xor_sync(0xffffffffu, s, off);
    if ((tid & 31) == 0) red[tid >> 5] = s;
    __syncthreads();
    if (tid == 0) {
        float t = 0.f;
        #pragma unroll
        for (int i = 0; i < 8; i++) t += red[i];
        mu_s = t * (1.0f / CDIM);
    }
    __syncthreads();
    float mu = mu_s;
    float d0 = v0 - mu, d1 = v1 - mu, d2 = v2 - mu;

    float q = d0*d0 + d1*d1 + d2*d2;
    #pragma unroll
    for (int off = 16; off > 0; off >>= 1) q += __shfl_xor_sync(0xffffffffu, q, off);
    __syncthreads();
    if ((tid & 31) == 0) red[tid >> 5] = q;
    __syncthreads();
    if (tid == 0) {
        float t = 0.f;
        #pragma unroll
        for (int i = 0; i < 8; i++) t += red[i];
        rs_s = rsqrtf(t * (1.0f / CDIM) + LN_EPS);
    }
    __syncthreads();
    float rs = rs_s;

    __half* orow = out + (size_t)row * CDIM;
    orow[tid      ] = __float2half_rn(d0 * rs * gam[tid      ] + bet[tid      ]);
    orow[tid + 256] = __float2half_rn(d1 * rs * gam[tid + 256] + bet[tid + 256]);
    orow[tid + 512] = __float2half_rn(d2 * rs * gam[tid + 512] + bet[tid + 512]);
}

// ---------------------------------------------------------------------------
// FP16 tensor-core GEMM: 128x128x64 tiles, 8 warps (64x32), ldmatrix frags,
// 3-stage cp.async, 2 CTAs/SM. M%128==0, N%128==0, K%64==0.
// ---------------------------------------------------------------------------
#define BK 64
#define ROWW 36                       // words per smem row (72 halves = 144 B)
#define ROWB 144
#define STAGE_W ((128 + 128) * ROWW)  // 9216 words / stage
#define BOFF_W (128 * ROWW)
#define GEMM_SMEM_BYTES (3 * STAGE_W * 4)   // 110592

template<bool DO_GELU, bool DO_RESID, bool OUT_HALF>
__global__ __launch_bounds__(256, 2)
void hgemm(const __half* __restrict__ A, const __half* __restrict__ Bt,
           const float* __restrict__ bias, const float* __restrict__ resid,
           void* __restrict__ Cv, int M, int N, int K)
{
    extern __shared__ __align__(16) uint32_t smw[];

    int tid  = threadIdx.x;
    int warp = tid >> 5;
    int lane = tid & 31;
    int gr   = lane >> 2;
    int t4   = lane & 3;
    int row0 = blockIdx.y * 128;
    int col0 = blockIdx.x * 128;
    int wm   = (warp >> 2) * 64;   // 0 or 64
    int wn   = (warp & 3) * 32;    // 0,32,64,96

    uint32_t sbase = (uint32_t)__cvta_generic_to_shared(smw);
    // ldmatrix lane offsets (validated in R6)
    uint32_t aoff = (uint32_t)(wm + (lane & 15)) * ROWB + (uint32_t)(lane >> 4) * 16;
    uint32_t boff = BOFF_W * 4 +
                    (uint32_t)(wn + (lane & 7) + ((lane >> 4) << 3)) * ROWB +
                    (uint32_t)((lane >> 3) & 1) * 16;

    float acc[4][4][4];
    #pragma unroll
    for (int i = 0; i < 4; i++)
        #pragma unroll
        for (int j = 0; j < 4; j++)
            #pragma unroll
            for (int r = 0; r < 4; r++) acc[i][j][r] = 0.f;

    int ldr = tid >> 3;
    int ldc = tid & 7;

    auto load_tiles = [&](int st, int kt) {
        int k0 = kt * BK;
        const __half* Ab = A  + (size_t)row0 * K + k0;
        const __half* Bb = Bt + (size_t)col0 * K + k0;
        uint32_t* sa = &smw[st * STAGE_W];
        uint32_t* sb = &smw[st * STAGE_W + BOFF_W];
        #pragma unroll
        for (int i = 0; i < 4; i++) {
            int r = ldr + i * 32;
            cpasync16(&sa[r * ROWW + ldc * 4], Ab + (size_t)r * K + ldc * 8);
            cpasync16(&sb[r * ROWW + ldc * 4], Bb + (size_t)r * K + ldc * 8);
        }
        asm volatile("cp.async.commit_group;");
    };

    int KT = K / BK;
    load_tiles(0, 0);
    load_tiles(1, 1);

    for (int kt = 0; kt < KT; kt++) {
        if (kt + 1 < KT) asm volatile("cp.async.wait_group 1;" ::: "memory");
        else             asm volatile("cp.async.wait_group 0;" ::: "memory");
        __syncthreads();
        if (kt + 2 < KT) load_tiles((kt + 2) % 3, kt + 2);

        uint32_t stb = sbase + (uint32_t)((kt % 3) * STAGE_W * 4);
        #pragma unroll
        for (int ks = 0; ks < 4; ks++) {
            uint32_t af[4][4], bf[2][4];
            #pragma unroll
            for (int mt = 0; mt < 4; mt++)
                ldmx4(af[mt], stb + aoff + (uint32_t)(mt * 16 * ROWB + ks * 32));
            #pragma unroll
            for (int nt = 0; nt < 2; nt++)
                ldmx4(bf[nt], stb + boff + (uint32_t)(nt * 16 * ROWB + ks * 32));
            #pragma unroll
            for (int mt = 0; mt < 4; mt++) {
                mma_f16(acc[mt][0], af[mt], &bf[0][0]);
                mma_f16(acc[mt][1], af[mt], &bf[0][2]);
                mma_f16(acc[mt][2], af[mt], &bf[1][0]);
                mma_f16(acc[mt][3], af[mt], &bf[1][2]);
            }
        }
    }

    // Epilogue
    #pragma unroll
    for (int i = 0; i < 4; i++) {
        int r0 = row0 + wm + i * 16 + gr;
        #pragma unroll
        for (int j = 0; j < 4; j++) {
            int cc = col0 + wn + j * 8 + 2 * t4;
            float2 bb = *(const float2*)&bias[cc];
            float v0 = acc[i][j][0] + bb.x;
            float v1 = acc[i][j][1] + bb.y;
            float v2 = acc[i][j][2] + bb.x;
            float v3 = acc[i][j][3] + bb.y;
            if (DO_GELU) {
                v0 = 0.5f * v0 * (1.0f + erff(v0 * 0.70710678118654752f));
                v1 = 0.5f * v1 * (1.0f + erff(v1 * 0.70710678118654752f));
                v2 = 0.5f * v2 * (1.0f + erff(v2 * 0.70710678118654752f));
                v3 = 0.5f * v3 * (1.0f + erff(v3 * 0.70710678118654752f));
            }
            size_t o0 = (size_t)r0 * N + cc;
            size_t o1 = (size_t)(r0 + 8) * N + cc;
            if (DO_RESID) {
                float2 ra = *(const float2*)&resid[o0];
                float2 rb = *(const float2*)&resid[o1];
                v0 += ra.x; v1 += ra.y; v2 += rb.x; v3 += rb.y;
            }
            if (OUT_HALF) {
                uint32_t* C = (uint32_t*)Cv;
                C[o0 >> 1] = h2pack(v0, v1);
                C[o1 >> 1] = h2pack(v2, v3);
            } else {
                float* C = (float*)Cv;
                *(float2*)&C[o0] = make_float2(v0, v1);
                *(float2*)&C[o1] = make_float2(v2, v3);
            }
        }
    }
}

// ---------------------------------------------------------------------------
// FP16 flash attention v2: 128 queries x 1 head per block, 256 threads.
// ldmatrix for Q/K frags, ldmatrix.trans for V (no manual transpose),
// cp.async double-buffered K/V, P stays in registers.
// Smem (words): Q[128][36] | stage0: K[64][36] V[64][36] | stage1: K V
// ---------------------------------------------------------------------------
#define ATQ_W 0
#define ATS_W 4608                    // stage stride (K+V) in words
#define ATTN_SMEM ((4608 + 2 * 4608) * 4)   // 55296 B

__global__ __launch_bounds__(256)
void attn_h2(const __half* __restrict__ qkv, __half* __restrict__ outp)
{
    extern __shared__ __align__(16) uint32_t smq[];

    int tid  = threadIdx.x;
    int warp = tid >> 5;
    int lane = tid & 31;
    int gr   = lane >> 2;
    int t4   = lane & 3;
    int qb   = blockIdx.x * 128;
    int b    = blockIdx.y / NHEADS;
    int h    = blockIdx.y % NHEADS;
    const __half* base = qkv + (size_t)b * SEQ * C3 + h * HDIM;

    const float SCL = 0.125f * 1.4426950408889634f;
    uint32_t sbase = (uint32_t)__cvta_generic_to_shared(smq);

    auto load_kv = [&](int st, int kt) {
        const __half* kb = base + (size_t)(kt * 64) * C3 + CDIM;
        uint32_t* sk = &smq[ATS_W * (1 + st)];
        uint32_t* sv = sk + 2304;
        #pragma unroll
        for (int i = 0; i < 2; i++) {
            int idx = tid + i * 256;
            int r = idx >> 3, c8 = idx & 7;
            cpasync16(&sk[r * ROWW + c8 * 4], kb + (size_t)r * C3 + c8 * 8);
            cpasync16(&sv[r * ROWW + c8 * 4], kb + (size_t)r * C3 + CDIM + c8 * 8);
        }
        asm volatile("cp.async.commit_group;");
    };

    load_kv(0, 0);

    // Q tile: 128 rows x 64 halves
    #pragma unroll
    for (int i = 0; i < 4; i++) {
        int idx = tid + i * 256;
        int r = idx >> 3, c8 = idx & 7;
        uint4 v = *(const uint4*)(base + (size_t)(qb + r) * C3 + c8 * 8);
        *(uint4*)&smq[ATQ_W + r * ROWW + c8 * 4] = v;
    }
    __syncthreads();

    // Hoist Q fragments (A-mapping)
    uint32_t qoff = (uint32_t)(16 * warp + (lane & 15)) * ROWB + (uint32_t)(lane >> 4) * 16;
    uint32_t qf[4][4];
    #pragma unroll
    for (int ks = 0; ks < 4; ks++)
        ldmx4(qf[ks], sbase + qoff + (uint32_t)(ks * 32));

    // ldmatrix lane offsets for K (B-map) and V (trans A-map), relative to stage base
    uint32_t koff = (uint32_t)((lane & 7) + ((lane >> 4) << 3)) * ROWB +
                    (uint32_t)((lane >> 3) & 1) * 16;
    uint32_t voff = 2304u * 4 + (uint32_t)(lane & 15) * ROWB + (uint32_t)(lane >> 4) * 16;

    float m1 = -1e30f, m2 = -1e30f, l1 = 0.f, l2 = 0.f;
    float oc[8][4];
    #pragma unroll
    for (int j = 0; j < 8; j++)
        #pragma unroll
        for (int r = 0; r < 4; r++) oc[j][r] = 0.f;

    for (int kt = 0; kt < SEQ / 64; kt++) {
        asm volatile("cp.async.wait_group 0;" ::: "memory");
        __syncthreads();
        if (kt + 1 < SEQ / 64) load_kv((kt + 1) & 1, kt + 1);

        uint32_t stb = sbase + (uint32_t)(ATS_W * (1 + (kt & 1)) * 4);

        // S = Q @ K^T
        float sc[8][4];
        #pragma unroll
        for (int j = 0; j < 8; j++)
            #pragma unroll
            for (int r = 0; r < 4; r++) sc[j][r] = 0.f;

        #pragma unroll
        for (int ks = 0; ks < 4; ks++) {
            uint32_t kf[4][4];
            #pragma unroll
            for (int nt = 0; nt < 4; nt++)
                ldmx4(kf[nt], stb + koff + (uint32_t)(nt * 16 * ROWB + ks * 32));
            #pragma unroll
            for (int nt = 0; nt < 4; nt++) {
                mma_f16(sc[2*nt    ], qf[ks], &kf[nt][0]);
                mma_f16(sc[2*nt + 1], qf[ks], &kf[nt][2]);
            }
        }
        #pragma unroll
        for (int j = 0; j < 8; j++) {
            sc[j][0] *= SCL; sc[j][1] *= SCL; sc[j][2] *= SCL; sc[j][3] *= SCL;
        }

        // Online softmax (log2 domain), P in registers
        float mx1 = -1e30f, mx2 = -1e30f;
        #pragma unroll
        for (int j = 0; j < 8; j++) {
            mx1 = fmaxf(mx1, fmaxf(sc[j][0], sc[j][1]));
            mx2 = fmaxf(mx2, fmaxf(sc[j][2], sc[j][3]));
        }
        mx1 = fmaxf(mx1, __shfl_xor_sync(0xffffffffu, mx1, 1));
        mx1 = fmaxf(mx1, __shfl_xor_sync(0xffffffffu, mx1, 2));
        mx2 = fmaxf(mx2, __shfl_xor_sync(0xffffffffu, mx2, 1));
        mx2 = fmaxf(mx2, __shfl_xor_sync(0xffffffffu, mx2, 2));

        float nm1 = fmaxf(m1, mx1), nm2 = fmaxf(m2, mx2);
        float a1 = ex2f(m1 - nm1), a2 = ex2f(m2 - nm2);
        float s1 = 0.f, s2 = 0.f;
        uint32_t ph[8][2];
        #pragma unroll
        for (int j = 0; j < 8; j++) {
            float p0 = ex2f(sc[j][0] - nm1);
            float p1 = ex2f(sc[j][1] - nm1);
            float p2 = ex2f(sc[j][2] - nm2);
            float p3 = ex2f(sc[j][3] - nm2);
            s1 += p0 + p1; s2 += p2 + p3;
            ph[j][0] = h2pack(p0, p1);
            ph[j][1] = h2pack(p2, p3);
        }
        s1 += __shfl_xor_sync(0xffffffffu, s1, 1);
        s1 += __shfl_xor_sync(0xffffffffu, s1, 2);
        s2 += __shfl_xor_sync(0xffffffffu, s2, 1);
        s2 += __shfl_xor_sync(0xffffffffu, s2, 2);
        l1 = l1 * a1 + s1;  l2 = l2 * a2 + s2;
        m1 = nm1;           m2 = nm2;
        #pragma unroll
        for (int j = 0; j < 8; j++) {
            oc[j][0] *= a1; oc[j][1] *= a1;
            oc[j][2] *= a2; oc[j][3] *= a2;
        }

        // O += P @ V  (V^T frags via ldmatrix.trans)
        #pragma unroll
        for (int ks = 0; ks < 4; ks++) {
            uint32_t pf[4] = { ph[2*ks][0], ph[2*ks][1], ph[2*ks+1][0], ph[2*ks+1][1] };
            uint32_t vf[4][4];
            #pragma unroll
            for (int dt = 0; dt < 4; dt++)
                ldmx4t(vf[dt], stb + voff + (uint32_t)(ks * 16 * ROWB + dt * 32));
            #pragma unroll
            for (int dt = 0; dt < 4; dt++) {
                mma_f16(oc[2*dt    ], pf, &vf[dt][0]);
                mma_f16(oc[2*dt + 1], pf, &vf[dt][2]);
            }
        }
    }

    // Epilogue: normalize, write half. oc[j]: d = (j>>1)*16 + (j&1)*8 + 2*t4
    float il1 = 1.0f / l1, il2 = 1.0f / l2;
    int r1 = qb + 16 * warp + gr;
    uint32_t* o32 = (uint32_t*)outp;
    #pragma unroll
    for (int j = 0; j < 8; j++) {
        int cc = h * HDIM + (j >> 1) * 16 + (j & 1) * 8 + 2 * t4;
        size_t o0 = ((size_t)(b * SEQ + r1) * CDIM + cc) >> 1;
        size_t o1 = o0 + 4 * CDIM;
        o32[o0] = h2pack(oc[j][0] * il1, oc[j][1] * il1);
        o32[o1] = h2pack(oc[j][2] * il2, oc[j][3] * il2);
    }
}

// ---------------------------------------------------------------------------
// Launch
// ---------------------------------------------------------------------------
extern "C" void kernel_launch(void* const* d_in, const int* in_sizes, int n_in,
                              void* d_out, int out_size)
{
    const float* x      = (const float*)d_in[0];
    const float* ln1_g  = (const float*)d_in[1];
    const float* ln1_b  = (const float*)d_in[2];
    const float* qkv_w  = (const float*)d_in[3];
    const float* qkv_b  = (const float*)d_in[4];
    const float* proj_w = (const float*)d_in[5];
    const float* proj_b = (const float*)d_in[6];
    const float* ln2_g  = (const float*)d_in[7];
    const float* ln2_b  = (const float*)d_in[8];
    const float* fc1_w  = (const float*)d_in[9];
    const float* fc1_b  = (const float*)d_in[10];
    const float* fc2_w  = (const float*)d_in[11];
    const float* fc2_b  = (const float*)d_in[12];
    float* out = (float*)d_out;

    __half *p_xn1, *p_qkv, *p_attn, *p_hn, *p_h1;
    __half *p_wq, *p_wp, *p_w1, *p_w2;
    float  *p_x2;
    cudaGetSymbolAddress((void**)&p_xn1,  g_xn1);
    cudaGetSymbolAddress((void**)&p_qkv,  g_qkv);
    cudaGetSymbolAddress((void**)&p_attn, g_attn);
    cudaGetSymbolAddress((void**)&p_x2,   g_x2);
    cudaGetSymbolAddress((void**)&p_hn,   g_hn);
    cudaGetSymbolAddress((void**)&p_h1,   g_h1);
    cudaGetSymbolAddress((void**)&p_wq,   g_wq);
    cudaGetSymbolAddress((void**)&p_wp,   g_wp);
    cudaGetSymbolAddress((void**)&p_w1,   g_w1);
    cudaGetSymbolAddress((void**)&p_w2,   g_w2);

    cudaFuncSetAttribute(attn_h2,
                         cudaFuncAttributeMaxDynamicSharedMemorySize, ATTN_SMEM);
    cudaFuncSetAttribute(hgemm<false,false,true>,
                         cudaFuncAttributeMaxDynamicSharedMemorySize, GEMM_SMEM_BYTES);
    cudaFuncSetAttribute(hgemm<false,true,false>,
                         cudaFuncAttributeMaxDynamicSharedMemorySize, GEMM_SMEM_BYTES);
    cudaFuncSetAttribute(hgemm<true,false,true>,
                         cudaFuncAttributeMaxDynamicSharedMemorySize, GEMM_SMEM_BYTES);

    // 0) Weight prep: transpose + fp16
    wprep_kernel<<<dim3(C3/32,   CDIM/32), dim3(32,8)>>>(qkv_w,  p_wq, CDIM, C3);
    wprep_kernel<<<dim3(CDIM/32, CDIM/32), dim3(32,8)>>>(proj_w, p_wp, CDIM, CDIM);
    wprep_kernel<<<dim3(HID/32,  CDIM/32), dim3(32,8)>>>(fc1_w,  p_w1, CDIM, HID);
    wprep_kernel<<<dim3(CDIM/32, HID/32 ), dim3(32,8)>>>(fc2_w,  p_w2, HID,  CDIM);

    // 1) LN1
    ln_kernel<<<TOKENS, 256>>>(x, ln1_g, ln1_b, p_xn1);

    // 2) qkv = xn1 @ qkv_w + qkv_b  (half out)
    hgemm<false,false,true><<<dim3(C3/128, TOKENS/128), 256, GEMM_SMEM_BYTES>>>(
        p_xn1, p_wq, qkv_b, nullptr, p_qkv, TOKENS, C3, CDIM);

    // 3) attention (half out)
    attn_h2<<<dim3(SEQ/128, BATCH*NHEADS), 256, ATTN_SMEM>>>(p_qkv, p_attn);

    // 4) x2 = x + attn @ proj_w + proj_b  (fp32 out)
    hgemm<false,true,false><<<dim3(CDIM/128, TOKENS/128), 256, GEMM_SMEM_BYTES>>>(
        p_attn, p_wp, proj_b, x, p_x2, TOKENS, CDIM, CDIM);

    // 5) LN2
    ln_kernel<<<TOKENS, 256>>>(p_x2, ln2_g, ln2_b, p_hn);

    // 6) h1 = gelu(hn @ fc1_w + fc1_b)  (half out)
    hgemm<true,false,true><<<dim3(HID/128, TOKENS/128), 256, GEMM_SMEM_BYTES>>>(
        p_hn, p_w1, fc1_b, nullptr, p_h1, TOKENS, HID, CDIM);

    // 7) out = x2 + h1 @ fc2_w + fc2_b  (fp32 out)
    hgemm<false,true,false><<<dim3(CDIM/128, TOKENS/128), 256, GEMM_SMEM_BYTES>>>(
        p_h1, p_w2, fc2_b, p_x2, out, TOKENS, CDIM, HID);
}

// round 8
// speedup vs baseline: 1.2442x; 1.0319x over previous
#include <cuda_runtime.h>
#include <cuda_fp16.h>
#include <math.h>
#include <stdint.h>

// Problem constants
#define BATCH   16
#define SEQ     1024
#define TOKENS  (BATCH*SEQ)     // 16384
#define CDIM    768
#define C3      (3*CDIM)        // 2304
#define HID     3072
#define NHEADS  12
#define HDIM    64
#define LN_EPS  1e-5f

// ---------------------------------------------------------------------------
// Scratch (device globals; allocation APIs are forbidden)
// ---------------------------------------------------------------------------
__device__ __half g_xn1 [ (size_t)TOKENS * CDIM ];
__device__ __half g_qkv [ (size_t)TOKENS * C3   ];
__device__ __half g_attn[ (size_t)TOKENS * CDIM ];
__device__ float  g_x2  [ (size_t)TOKENS * CDIM ];
__device__ __half g_hn  [ (size_t)TOKENS * CDIM ];
__device__ __half g_h1  [ (size_t)TOKENS * HID  ];
// fp16, TRANSPOSED weights: wT[n][k]
__device__ __half g_wq  [ (size_t)C3   * CDIM ];
__device__ __half g_wp  [ (size_t)CDIM * CDIM ];
__device__ __half g_w1  [ (size_t)HID  * CDIM ];
__device__ __half g_w2  [ (size_t)CDIM * HID  ];

// ---------------------------------------------------------------------------
// Helpers
// ---------------------------------------------------------------------------
__device__ __forceinline__ float ex2f(float x) {
    float y;
    asm("ex2.approx.f32 %0, %1;" : "=f"(y) : "f"(x));
    return y;
}
__device__ __forceinline__ void mma_f16(float* c, const uint32_t* a, const uint32_t* b) {
    asm volatile(
        "mma.sync.aligned.m16n8k16.row.col.f32.f16.f16.f32 "
        "{%0,%1,%2,%3}, {%4,%5,%6,%7}, {%8,%9}, {%0,%1,%2,%3};"
        : "+f"(c[0]), "+f"(c[1]), "+f"(c[2]), "+f"(c[3])
        : "r"(a[0]), "r"(a[1]), "r"(a[2]), "r"(a[3]), "r"(b[0]), "r"(b[1]));
}
__device__ __forceinline__ void cpasync16(void* smem_ptr, const void* gmem_ptr) {
    uint32_t s = (uint32_t)__cvta_generic_to_shared(smem_ptr);
    asm volatile("cp.async.cg.shared.global [%0], [%1], 16;" :: "r"(s), "l"(gmem_ptr));
}
__device__ __forceinline__ void cpasync16s(uint32_t saddr, const void* gmem_ptr) {
    asm volatile("cp.async.cg.shared.global [%0], [%1], 16;" :: "r"(saddr), "l"(gmem_ptr));
}
__device__ __forceinline__ void ldmx4(uint32_t* r, uint32_t saddr) {
    asm volatile("ldmatrix.sync.aligned.m8n8.x4.shared.b16 {%0,%1,%2,%3}, [%4];"
                 : "=r"(r[0]), "=r"(r[1]), "=r"(r[2]), "=r"(r[3]) : "r"(saddr));
}
__device__ __forceinline__ void ldmx4t(uint32_t* r, uint32_t saddr) {
    asm volatile("ldmatrix.sync.aligned.m8n8.x4.trans.shared.b16 {%0,%1,%2,%3}, [%4];"
                 : "=r"(r[0]), "=r"(r[1]), "=r"(r[2]), "=r"(r[3]) : "r"(saddr));
}
__device__ __forceinline__ uint32_t h2pack(float lo, float hi) {
    __half2 h = __floats2half2_rn(lo, hi);
    return *reinterpret_cast<uint32_t*>(&h);
}

// ---------------------------------------------------------------------------
// Weight prep: transpose + fp16. out[n*K + k] = half(in[k*N + n])
// ---------------------------------------------------------------------------
__global__ __launch_bounds__(256)
void wprep_kernel(const float* __restrict__ in, __half* __restrict__ out, int K, int N)
{
    __shared__ float t[32][33];
    int n0 = blockIdx.x * 32, k0 = blockIdx.y * 32;
    int tx = threadIdx.x, ty = threadIdx.y;
    #pragma unroll
    for (int j = 0; j < 4; j++) {
        int kk = j * 8 + ty;
        t[kk][tx] = in[(size_t)(k0 + kk) * N + n0 + tx];
    }
    __syncthreads();
    #pragma unroll
    for (int j = 0; j < 4; j++) {
        int nn = j * 8 + ty;
        out[(size_t)(n0 + nn) * K + k0 + tx] = __float2half_rn(t[tx][nn]);
    }
}

// ---------------------------------------------------------------------------
// LayerNorm: fp32 in, half out
// ---------------------------------------------------------------------------
__global__ __launch_bounds__(256)
void ln_kernel(const float* __restrict__ x, const float* __restrict__ gam,
               const float* __restrict__ bet, __half* __restrict__ out)
{
    int row = blockIdx.x;
    int tid = threadIdx.x;
    const float* xr = x + (size_t)row * CDIM;

    float v0 = xr[tid], v1 = xr[tid + 256], v2 = xr[tid + 512];

    __shared__ float red[8];
    __shared__ float mu_s, rs_s;

    float s = v0 + v1 + v2;
    #pragma unroll
    for (int off = 16; off > 0; off >>= 1) s += __shfl_xor_sync(0xffffffffu, s, off);
    if ((tid & 31) == 0) red[tid >> 5] = s;
    __syncthreads();
    if (tid == 0) {
        float t = 0.f;
        #pragma unroll
        for (int i = 0; i < 8; i++) t += red[i];
        mu_s = t * (1.0f / CDIM);
    }
    __syncthreads();
    float mu = mu_s;
    float d0 = v0 - mu, d1 = v1 - mu, d2 = v2 - mu;

    float q = d0*d0 + d1*d1 + d2*d2;
    #pragma unroll
    for (int off = 16; off > 0; off >>= 1) q += __shfl_xor_sync(0xffffffffu, q, off);
    __syncthreads();
    if ((tid & 31) == 0) red[tid >> 5] = q;
    __syncthreads();
    if (tid == 0) {
        float t = 0.f;
        #pragma unroll
        for (int i = 0; i < 8; i++) t += red[i];
        rs_s = rsqrtf(t * (1.0f / CDIM) + LN_EPS);
    }
    __syncthreads();
    float rs = rs_s;

    __half* orow = out + (size_t)row * CDIM;
    orow[tid      ] = __float2half_rn(d0 * rs * gam[tid      ] + bet[tid      ]);
    orow[tid + 256] = __float2half_rn(d1 * rs * gam[tid + 256] + bet[tid + 256]);
    orow[tid + 512] = __float2half_rn(d2 * rs * gam[tid + 512] + bet[tid + 512]);
}

// ---------------------------------------------------------------------------
// FP16 tensor-core GEMM v3: 128x128x64 CTA tile, 128 threads (4 warps),
// warp tile 64x64 (2x2 grid), XOR-swizzled 128B-row smem, ldmatrix,
// 2-stage cp.async, 3 CTAs/SM. M%128==0, N%128==0, K%128==0.
// Swizzle: byte chunk c (16B) of row r stored at chunk (c ^ (r&7)).
// ---------------------------------------------------------------------------
#define BK 64
#define STGB 32768                  // bytes per stage: A 16KB + B 16KB
#define GEMM_SMEM_BYTES (2 * STGB)  // 65536

template<bool DO_GELU, bool DO_RESID, bool OUT_HALF>
__global__ __launch_bounds__(128, 3)
void hgemm(const __half* __restrict__ A, const __half* __restrict__ Bt,
           const float* __restrict__ bias, const float* __restrict__ resid,
           void* __restrict__ Cv, int M, int N, int K)
{
    extern __shared__ __align__(16) char smb[];
    uint32_t sbase = (uint32_t)__cvta_generic_to_shared(smb);

    int tid  = threadIdx.x;
    int warp = tid >> 5;
    int lane = tid & 31;
    int gr   = lane >> 2;
    int t4   = lane & 3;
    int row0 = blockIdx.y * 128;
    int col0 = blockIdx.x * 128;
    int wm   = (warp >> 1) * 64;   // 0 or 64
    int wn   = (warp & 1) * 64;    // 0 or 64

    // ldmatrix per-lane constants
    int arow = wm + (lane & 15);           // A row (mt adds 16, keeps &7)
    int ahi  = lane >> 4;                  // chunk low bit for A
    int brow = wn + (lane & 7) + ((lane >> 4) << 3);
    int bhi  = (lane >> 3) & 1;
    uint32_t abase = (uint32_t)arow * 128;
    uint32_t bbase = 16384u + (uint32_t)brow * 128;
    int ax = arow & 7;
    int bx = brow & 7;

    float acc[4][8][4];
    #pragma unroll
    for (int i = 0; i < 4; i++)
        #pragma unroll
        for (int j = 0; j < 8; j++)
            #pragma unroll
            for (int r = 0; r < 4; r++) acc[i][j][r] = 0.f;

    int ldr = tid >> 3;            // 0..15
    int ldc = tid & 7;             // chunk 0..7

    auto load_tiles = [&](int st, int kt) {
        int k0 = kt * BK;
        const __half* Ab = A  + (size_t)row0 * K + k0;
        const __half* Bb = Bt + (size_t)col0 * K + k0;
        uint32_t sa = sbase + (uint32_t)st * STGB;
        uint32_t sb = sa + 16384u;
        #pragma unroll
        for (int i = 0; i < 8; i++) {
            int r = ldr + i * 16;                 // 0..127
            uint32_t sw = (uint32_t)r * 128 + ((uint32_t)(ldc ^ (r & 7)) << 4);
            cpasync16s(sa + sw, Ab + (size_t)r * K + ldc * 8);
            cpasync16s(sb + sw, Bb + (size_t)r * K + ldc * 8);
        }
        asm volatile("cp.async.commit_group;");
    };

    int KT = K / BK;
    load_tiles(0, 0);

    for (int kt = 0; kt < KT; kt++) {
        if (kt + 1 < KT) {
            load_tiles((kt + 1) & 1, kt + 1);
            asm volatile("cp.async.wait_group 1;" ::: "memory");
        } else {
            asm volatile("cp.async.wait_group 0;" ::: "memory");
        }
        __syncthreads();

        uint32_t stg = sbase + (uint32_t)((kt & 1) * STGB);
        #pragma unroll
        for (int ks = 0; ks < 4; ks++) {
            uint32_t af[4][4];
            #pragma unroll
            for (int mt = 0; mt < 4; mt++)
                ldmx4(af[mt], stg + abase + (uint32_t)(mt * 2048)
                                  + ((uint32_t)((2 * ks + ahi) ^ ax) << 4));
            #pragma unroll
            for (int nt = 0; nt < 4; nt++) {
                uint32_t bf[4];
                ldmx4(bf, stg + bbase + (uint32_t)(nt * 2048)
                              + ((uint32_t)((2 * ks + bhi) ^ bx) << 4));
                #pragma unroll
                for (int mt = 0; mt < 4; mt++) {
                    mma_f16(acc[mt][2*nt    ], af[mt], &bf[0]);
                    mma_f16(acc[mt][2*nt + 1], af[mt], &bf[2]);
                }
            }
        }
        __syncthreads();
    }

    // Epilogue
    #pragma unroll
    for (int i = 0; i < 4; i++) {
        int r0 = row0 + wm + i * 16 + gr;
        #pragma unroll
        for (int j = 0; j < 8; j++) {
            int cc = col0 + wn + j * 8 + 2 * t4;
            float2 bb = *(const float2*)&bias[cc];
            float v0 = acc[i][j][0] + bb.x;
            float v1 = acc[i][j][1] + bb.y;
            float v2 = acc[i][j][2] + bb.x;
            float v3 = acc[i][j][3] + bb.y;
            if (DO_GELU) {
                v0 = 0.5f * v0 * (1.0f + erff(v0 * 0.70710678118654752f));
                v1 = 0.5f * v1 * (1.0f + erff(v1 * 0.70710678118654752f));
                v2 = 0.5f * v2 * (1.0f + erff(v2 * 0.70710678118654752f));
                v3 = 0.5f * v3 * (1.0f + erff(v3 * 0.70710678118654752f));
            }
            size_t o0 = (size_t)r0 * N + cc;
            size_t o1 = (size_t)(r0 + 8) * N + cc;
            if (DO_RESID) {
                float2 ra = *(const float2*)&resid[o0];
                float2 rb = *(const float2*)&resid[o1];
                v0 += ra.x; v1 += ra.y; v2 += rb.x; v3 += rb.y;
            }
            if (OUT_HALF) {
                uint32_t* C = (uint32_t*)Cv;
                C[o0 >> 1] = h2pack(v0, v1);
                C[o1 >> 1] = h2pack(v2, v3);
            } else {
                float* C = (float*)Cv;
                *(float2*)&C[o0] = make_float2(v0, v1);
                *(float2*)&C[o1] = make_float2(v2, v3);
            }
        }
    }
}

// ---------------------------------------------------------------------------
// FP16 flash attention (unchanged from R7): 128 queries x 1 head, 256 thr,
// ldmatrix Q/K, ldmatrix.trans V, cp.async double-buffered K/V.
// ---------------------------------------------------------------------------
#define ROWW 36
#define ROWB 144
#define ATQ_W 0
#define ATS_W 4608
#define ATTN_SMEM ((4608 + 2 * 4608) * 4)   // 55296 B

__global__ __launch_bounds__(256)
void attn_h2(const __half* __restrict__ qkv, __half* __restrict__ outp)
{
    extern __shared__ __align__(16) uint32_t smq[];

    int tid  = threadIdx.x;
    int warp = tid >> 5;
    int lane = tid & 31;
    int gr   = lane >> 2;
    int t4   = lane & 3;
    int qb   = blockIdx.x * 128;
    int b    = blockIdx.y / NHEADS;
    int h    = blockIdx.y % NHEADS;
    const __half* base = qkv + (size_t)b * SEQ * C3 + h * HDIM;

    const float SCL = 0.125f * 1.4426950408889634f;
    uint32_t sbase = (uint32_t)__cvta_generic_to_shared(smq);

    auto load_kv = [&](int st, int kt) {
        const __half* kb = base + (size_t)(kt * 64) * C3 + CDIM;
        uint32_t* sk = &smq[ATS_W * (1 + st)];
        uint32_t* sv = sk + 2304;
        #pragma unroll
        for (int i = 0; i < 2; i++) {
            int idx = tid + i * 256;
            int r = idx >> 3, c8 = idx & 7;
            cpasync16(&sk[r * ROWW + c8 * 4], kb + (size_t)r * C3 + c8 * 8);
            cpasync16(&sv[r * ROWW + c8 * 4], kb + (size_t)r * C3 + CDIM + c8 * 8);
        }
        asm volatile("cp.async.commit_group;");
    };

    load_kv(0, 0);

    #pragma unroll
    for (int i = 0; i < 4; i++) {
        int idx = tid + i * 256;
        int r = idx >> 3, c8 = idx & 7;
        uint4 v = *(const uint4*)(base + (size_t)(qb + r) * C3 + c8 * 8);
        *(uint4*)&smq[ATQ_W + r * ROWW + c8 * 4] = v;
    }
    __syncthreads();

    uint32_t qoff = (uint32_t)(16 * warp + (lane & 15)) * ROWB + (uint32_t)(lane >> 4) * 16;
    uint32_t qf[4][4];
    #pragma unroll
    for (int ks = 0; ks < 4; ks++)
        ldmx4(qf[ks], sbase + qoff + (uint32_t)(ks * 32));

    uint32_t koff = (uint32_t)((lane & 7) + ((lane >> 4) << 3)) * ROWB +
                    (uint32_t)((lane >> 3) & 1) * 16;
    uint32_t voff = 2304u * 4 + (uint32_t)(lane & 15) * ROWB + (uint32_t)(lane >> 4) * 16;

    float m1 = -1e30f, m2 = -1e30f, l1 = 0.f, l2 = 0.f;
    float oc[8][4];
    #pragma unroll
    for (int j = 0; j < 8; j++)
        #pragma unroll
        for (int r = 0; r < 4; r++) oc[j][r] = 0.f;

    for (int kt = 0; kt < SEQ / 64; kt++) {
        asm volatile("cp.async.wait_group 0;" ::: "memory");
        __syncthreads();
        if (kt + 1 < SEQ / 64) load_kv((kt + 1) & 1, kt + 1);

        uint32_t stb = sbase + (uint32_t)(ATS_W * (1 + (kt & 1)) * 4);

        float sc[8][4];
        #pragma unroll
        for (int j = 0; j < 8; j++)
            #pragma unroll
            for (int r = 0; r < 4; r++) sc[j][r] = 0.f;

        #pragma unroll
        for (int ks = 0; ks < 4; ks++) {
            uint32_t kf[4][4];
            #pragma unroll
            for (int nt = 0; nt < 4; nt++)
                ldmx4(kf[nt], stb + koff + (uint32_t)(nt * 16 * ROWB + ks * 32));
            #pragma unroll
            for (int nt = 0; nt < 4; nt++) {
                mma_f16(sc[2*nt    ], qf[ks], &kf[nt][0]);
                mma_f16(sc[2*nt + 1], qf[ks], &kf[nt][2]);
            }
        }
        #pragma unroll
        for (int j = 0; j < 8; j++) {
            sc[j][0] *= SCL; sc[j][1] *= SCL; sc[j][2] *= SCL; sc[j][3] *= SCL;
        }

        float mx1 = -1e30f, mx2 = -1e30f;
        #pragma unroll
        for (int j = 0; j < 8; j++) {
            mx1 = fmaxf(mx1, fmaxf(sc[j][0], sc[j][1]));
            mx2 = fmaxf(mx2, fmaxf(sc[j][2], sc[j][3]));
        }
        mx1 = fmaxf(mx1, __shfl_xor_sync(0xffffffffu, mx1, 1));
        mx1 = fmaxf(mx1, __shfl_xor_sync(0xffffffffu, mx1, 2));
        mx2 = fmaxf(mx2, __shfl_xor_sync(0xffffffffu, mx2, 1));
        mx2 = fmaxf(mx2, __shfl_xor_sync(0xffffffffu, mx2, 2));

        float nm1 = fmaxf(m1, mx1), nm2 = fmaxf(m2, mx2);
        float a1 = ex2f(m1 - nm1), a2 = ex2f(m2 - nm2);
        float s1 = 0.f, s2 = 0.f;
        uint32_t ph[8][2];
        #pragma unroll
        for (int j = 0; j < 8; j++) {
            float p0 = ex2f(sc[j][0] - nm1);
            float p1 = ex2f(sc[j][1] - nm1);
            float p2 = ex2f(sc[j][2] - nm2);
            float p3 = ex2f(sc[j][3] - nm2);
            s1 += p0 + p1; s2 += p2 + p3;
            ph[j][0] = h2pack(p0, p1);
            ph[j][1] = h2pack(p2, p3);
        }
        s1 += __shfl_xor_sync(0xffffffffu, s1, 1);
        s1 += __shfl_xor_sync(0xffffffffu, s1, 2);
        s2 += __shfl_xor_sync(0xffffffffu, s2, 1);
        s2 += __shfl_xor_sync(0xffffffffu, s2, 2);
        l1 = l1 * a1 + s1;  l2 = l2 * a2 + s2;
        m1 = nm1;           m2 = nm2;
        #pragma unroll
        for (int j = 0; j < 8; j++) {
            oc[j][0] *= a1; oc[j][1] *= a1;
            oc[j][2] *= a2; oc[j][3] *= a2;
        }

        #pragma unroll
        for (int ks = 0; ks < 4; ks++) {
            uint32_t pf[4] = { ph[2*ks][0], ph[2*ks][1], ph[2*ks+1][0], ph[2*ks+1][1] };
            uint32_t vf[4][4];
            #pragma unroll
            for (int dt = 0; dt < 4; dt++)
                ldmx4t(vf[dt], stb + voff + (uint32_t)(ks * 16 * ROWB + dt * 32));
            #pragma unroll
            for (int dt = 0; dt < 4; dt++) {
                mma_f16(oc[2*dt    ], pf, &vf[dt][0]);
                mma_f16(oc[2*dt + 1], pf, &vf[dt][2]);
            }
        }
    }

    float il1 = 1.0f / l1, il2 = 1.0f / l2;
    int r1 = qb + 16 * warp + gr;
    uint32_t* o32 = (uint32_t*)outp;
    #pragma unroll
    for (int j = 0; j < 8; j++) {
        int cc = h * HDIM + (j >> 1) * 16 + (j & 1) * 8 + 2 * t4;
        size_t o0 = ((size_t)(b * SEQ + r1) * CDIM + cc) >> 1;
        size_t o1 = o0 + 4 * CDIM;
        o32[o0] = h2pack(oc[j][0] * il1, oc[j][1] * il1);
        o32[o1] = h2pack(oc[j][2] * il2, oc[j][3] * il2);
    }
}

// ---------------------------------------------------------------------------
// Launch
// ---------------------------------------------------------------------------
extern "C" void kernel_launch(void* const* d_in, const int* in_sizes, int n_in,
                              void* d_out, int out_size)
{
    const float* x      = (const float*)d_in[0];
    const float* ln1_g  = (const float*)d_in[1];
    const float* ln1_b  = (const float*)d_in[2];
    const float* qkv_w  = (const float*)d_in[3];
    const float* qkv_b  = (const float*)d_in[4];
    const float* proj_w = (const float*)d_in[5];
    const float* proj_b = (const float*)d_in[6];
    const float* ln2_g  = (const float*)d_in[7];
    const float* ln2_b  = (const float*)d_in[8];
    const float* fc1_w  = (const float*)d_in[9];
    const float* fc1_b  = (const float*)d_in[10];
    const float* fc2_w  = (const float*)d_in[11];
    const float* fc2_b  = (const float*)d_in[12];
    float* out = (float*)d_out;

    __half *p_xn1, *p_qkv, *p_attn, *p_hn, *p_h1;
    __half *p_wq, *p_wp, *p_w1, *p_w2;
    float  *p_x2;
    cudaGetSymbolAddress((void**)&p_xn1,  g_xn1);
    cudaGetSymbolAddress((void**)&p_qkv,  g_qkv);
    cudaGetSymbolAddress((void**)&p_attn, g_attn);
    cudaGetSymbolAddress((void**)&p_x2,   g_x2);
    cudaGetSymbolAddress((void**)&p_hn,   g_hn);
    cudaGetSymbolAddress((void**)&p_h1,   g_h1);
    cudaGetSymbolAddress((void**)&p_wq,   g_wq);
    cudaGetSymbolAddress((void**)&p_wp,   g_wp);
    cudaGetSymbolAddress((void**)&p_w1,   g_w1);
    cudaGetSymbolAddress((void**)&p_w2,   g_w2);

    cudaFuncSetAttribute(attn_h2,
                         cudaFuncAttributeMaxDynamicSharedMemorySize, ATTN_SMEM);
    cudaFuncSetAttribute(hgemm<false,false,true>,
                         cudaFuncAttributeMaxDynamicSharedMemorySize, GEMM_SMEM_BYTES);
    cudaFuncSetAttribute(hgemm<false,true,false>,
                         cudaFuncAttributeMaxDynamicSharedMemorySize, GEMM_SMEM_BYTES);
    cudaFuncSetAttribute(hgemm<true,false,true>,
                         cudaFuncAttributeMaxDynamicSharedMemorySize, GEMM_SMEM_BYTES);

    // 0) Weight prep: transpose + fp16
    wprep_kernel<<<dim3(C3/32,   CDIM/32), dim3(32,8)>>>(qkv_w,  p_wq, CDIM, C3);
    wprep_kernel<<<dim3(CDIM/32, CDIM/32), dim3(32,8)>>>(proj_w, p_wp, CDIM, CDIM);
    wprep_kernel<<<dim3(HID/32,  CDIM/32), dim3(32,8)>>>(fc1_w,  p_w1, CDIM, HID);
    wprep_kernel<<<dim3(CDIM/32, HID/32 ), dim3(32,8)>>>(fc2_w,  p_w2, HID,  CDIM);

    // 1) LN1
    ln_kernel<<<TOKENS, 256>>>(x, ln1_g, ln1_b, p_xn1);

    // 2) qkv = xn1 @ qkv_w + qkv_b  (half out)
    hgemm<false,false,true><<<dim3(C3/128, TOKENS/128), 128, GEMM_SMEM_BYTES>>>(
        p_xn1, p_wq, qkv_b, nullptr, p_qkv, TOKENS, C3, CDIM);

    // 3) attention (half out)
    attn_h2<<<dim3(SEQ/128, BATCH*NHEADS), 256, ATTN_SMEM>>>(p_qkv, p_attn);

    // 4) x2 = x + attn @ proj_w + proj_b  (fp32 out)
    hgemm<false,true,false><<<dim3(CDIM/128, TOKENS/128), 128, GEMM_SMEM_BYTES>>>(
        p_attn, p_wp, proj_b, x, p_x2, TOKENS, CDIM, CDIM);

    // 5) LN2
    ln_kernel<<<TOKENS, 256>>>(p_x2, ln2_g, ln2_b, p_hn);

    // 6) h1 = gelu(hn @ fc1_w + fc1_b)  (half out)
    hgemm<true,false,true><<<dim3(HID/128, TOKENS/128), 128, GEMM_SMEM_BYTES>>>(
        p_hn, p_w1, fc1_b, nullptr, p_h1, TOKENS, HID, CDIM);

    // 7) out = x2 + h1 @ fc2_w + fc2_b  (fp32 out)
    hgemm<false,true,false><<<dim3(CDIM/128, TOKENS/128), 128, GEMM_SMEM_BYTES>>>(
        p_h1, p_w2, fc2_b, p_x2, out, TOKENS, CDIM, HID);
}

// round 9
// speedup vs baseline: 1.2676x; 1.0188x over previous
#include <cuda_runtime.h>
#include <cuda_fp16.h>
#include <math.h>
#include <stdint.h>

// Problem constants
#define BATCH   16
#define SEQ     1024
#define TOKENS  (BATCH*SEQ)     // 16384
#define CDIM    768
#define C3      (3*CDIM)        // 2304
#define HID     3072
#define NHEADS  12
#define HDIM    64
#define LN_EPS  1e-5f

// ---------------------------------------------------------------------------
// Scratch (device globals; allocation APIs are forbidden)
// ---------------------------------------------------------------------------
__device__ __half g_xn1 [ (size_t)TOKENS * CDIM ];
__device__ __half g_qkv [ (size_t)TOKENS * C3   ];
__device__ __half g_attn[ (size_t)TOKENS * CDIM ];
__device__ float  g_x2  [ (size_t)TOKENS * CDIM ];
__device__ __half g_hn  [ (size_t)TOKENS * CDIM ];
__device__ __half g_h1  [ (size_t)TOKENS * HID  ];
// fp16, TRANSPOSED weights: wT[n][k]
__device__ __half g_wq  [ (size_t)C3   * CDIM ];
__device__ __half g_wp  [ (size_t)CDIM * CDIM ];
__device__ __half g_w1  [ (size_t)HID  * CDIM ];
__device__ __half g_w2  [ (size_t)CDIM * HID  ];

// softmax scale * log2(e), folded into q at qkv-GEMM epilogue
#define QSCALE 0.18033688011112042f

// ---------------------------------------------------------------------------
// Helpers
// ---------------------------------------------------------------------------
__device__ __forceinline__ float ex2f(float x) {
    float y;
    asm("ex2.approx.f32 %0, %1;" : "=f"(y) : "f"(x));
    return y;
}
__device__ __forceinline__ void mma_f16(float* c, const uint32_t* a, const uint32_t* b) {
    asm volatile(
        "mma.sync.aligned.m16n8k16.row.col.f32.f16.f16.f32 "
        "{%0,%1,%2,%3}, {%4,%5,%6,%7}, {%8,%9}, {%0,%1,%2,%3};"
        : "+f"(c[0]), "+f"(c[1]), "+f"(c[2]), "+f"(c[3])
        : "r"(a[0]), "r"(a[1]), "r"(a[2]), "r"(a[3]), "r"(b[0]), "r"(b[1]));
}
__device__ __forceinline__ void cpasync16(void* smem_ptr, const void* gmem_ptr) {
    uint32_t s = (uint32_t)__cvta_generic_to_shared(smem_ptr);
    asm volatile("cp.async.cg.shared.global [%0], [%1], 16;" :: "r"(s), "l"(gmem_ptr));
}
__device__ __forceinline__ void cpasync16s(uint32_t saddr, const void* gmem_ptr) {
    asm volatile("cp.async.cg.shared.global [%0], [%1], 16;" :: "r"(saddr), "l"(gmem_ptr));
}
__device__ __forceinline__ void ldmx4(uint32_t* r, uint32_t saddr) {
    asm volatile("ldmatrix.sync.aligned.m8n8.x4.shared.b16 {%0,%1,%2,%3}, [%4];"
                 : "=r"(r[0]), "=r"(r[1]), "=r"(r[2]), "=r"(r[3]) : "r"(saddr));
}
__device__ __forceinline__ void ldmx4t(uint32_t* r, uint32_t saddr) {
    asm volatile("ldmatrix.sync.aligned.m8n8.x4.trans.shared.b16 {%0,%1,%2,%3}, [%4];"
                 : "=r"(r[0]), "=r"(r[1]), "=r"(r[2]), "=r"(r[3]) : "r"(saddr));
}
__device__ __forceinline__ uint32_t h2pack(float lo, float hi) {
    __half2 h = __floats2half2_rn(lo, hi);
    return *reinterpret_cast<uint32_t*>(&h);
}

// ---------------------------------------------------------------------------
// Weight prep: transpose + fp16. out[n*K + k] = half(in[k*N + n])
// ---------------------------------------------------------------------------
__global__ __launch_bounds__(256)
void wprep_kernel(const float* __restrict__ in, __half* __restrict__ out, int K, int N)
{
    __shared__ float t[32][33];
    int n0 = blockIdx.x * 32, k0 = blockIdx.y * 32;
    int tx = threadIdx.x, ty = threadIdx.y;
    #pragma unroll
    for (int j = 0; j < 4; j++) {
        int kk = j * 8 + ty;
        t[kk][tx] = in[(size_t)(k0 + kk) * N + n0 + tx];
    }
    __syncthreads();
    #pragma unroll
    for (int j = 0; j < 4; j++) {
        int nn = j * 8 + ty;
        out[(size_t)(n0 + nn) * K + k0 + tx] = __float2half_rn(t[tx][nn]);
    }
}

// ---------------------------------------------------------------------------
// LayerNorm (vectorized): 192 threads, one float4 per thread.
// ---------------------------------------------------------------------------
__global__ __launch_bounds__(192)
void ln_kernel(const float* __restrict__ x, const float* __restrict__ gam,
               const float* __restrict__ bet, __half* __restrict__ out)
{
    int row  = blockIdx.x;
    int tid  = threadIdx.x;
    int lane = tid & 31;
    int wid  = tid >> 5;              // 0..5

    float4 v = ((const float4*)(x + (size_t)row * CDIM))[tid];

    __shared__ float red[12];
    __shared__ float mu_s, rs_s;

    float s = v.x + v.y + v.z + v.w;
    #pragma unroll
    for (int off = 16; off > 0; off >>= 1) s += __shfl_xor_sync(0xffffffffu, s, off);
    if (lane == 0) red[wid] = s;
    __syncthreads();
    if (tid == 0) {
        float t = red[0] + red[1] + red[2] + red[3] + red[4] + red[5];
        mu_s = t * (1.0f / CDIM);
    }
    __syncthreads();
    float mu = mu_s;
    float d0 = v.x - mu, d1 = v.y - mu, d2 = v.z - mu, d3 = v.w - mu;

    float q = d0*d0 + d1*d1 + d2*d2 + d3*d3;
    #pragma unroll
    for (int off = 16; off > 0; off >>= 1) q += __shfl_xor_sync(0xffffffffu, q, off);
    if (lane == 0) red[6 + wid] = q;
    __syncthreads();
    if (tid == 0) {
        float t = red[6] + red[7] + red[8] + red[9] + red[10] + red[11];
        rs_s = rsqrtf(t * (1.0f / CDIM) + LN_EPS);
    }
    __syncthreads();
    float rs = rs_s;

    float4 g  = ((const float4*)gam)[tid];
    float4 be = ((const float4*)bet)[tid];
    uint2 o;
    o.x = h2pack(d0 * rs * g.x + be.x, d1 * rs * g.y + be.y);
    o.y = h2pack(d2 * rs * g.z + be.z, d3 * rs * g.w + be.w);
    ((uint2*)(out + (size_t)row * CDIM))[tid] = o;
}

// ---------------------------------------------------------------------------
// FP16 tensor-core GEMM: 128x128x64 CTA tile, 128 threads (4 warps),
// warp tile 64x64, XOR-swizzled 128B-row smem, ldmatrix, 2-stage cp.async,
// 3 CTAs/SM. DO_QSCALE: multiply columns [0,768) by QSCALE (q pre-scaling).
// ---------------------------------------------------------------------------
#define BK 64
#define STGB 32768
#define GEMM_SMEM_BYTES (2 * STGB)  // 65536

template<bool DO_GELU, bool DO_RESID, bool OUT_HALF, bool DO_QSCALE>
__global__ __launch_bounds__(128, 3)
void hgemm(const __half* __restrict__ A, const __half* __restrict__ Bt,
           const float* __restrict__ bias, const float* __restrict__ resid,
           void* __restrict__ Cv, int M, int N, int K)
{
    extern __shared__ __align__(16) char smb[];
    uint32_t sbase = (uint32_t)__cvta_generic_to_shared(smb);

    int tid  = threadIdx.x;
    int warp = tid >> 5;
    int lane = tid & 31;
    int gr   = lane >> 2;
    int t4   = lane & 3;
    int row0 = blockIdx.y * 128;
    int col0 = blockIdx.x * 128;
    int wm   = (warp >> 1) * 64;
    int wn   = (warp & 1) * 64;

    int arow = wm + (lane & 15);
    int ahi  = lane >> 4;
    int brow = wn + (lane & 7) + ((lane >> 4) << 3);
    int bhi  = (lane >> 3) & 1;
    uint32_t abase = (uint32_t)arow * 128;
    uint32_t bbase = 16384u + (uint32_t)brow * 128;
    int ax = arow & 7;
    int bx = brow & 7;

    float acc[4][8][4];
    #pragma unroll
    for (int i = 0; i < 4; i++)
        #pragma unroll
        for (int j = 0; j < 8; j++)
            #pragma unroll
            for (int r = 0; r < 4; r++) acc[i][j][r] = 0.f;

    int ldr = tid >> 3;
    int ldc = tid & 7;

    auto load_tiles = [&](int st, int kt) {
        int k0 = kt * BK;
        const __half* Ab = A  + (size_t)row0 * K + k0;
        const __half* Bb = Bt + (size_t)col0 * K + k0;
        uint32_t sa = sbase + (uint32_t)st * STGB;
        uint32_t sb = sa + 16384u;
        #pragma unroll
        for (int i = 0; i < 8; i++) {
            int r = ldr + i * 16;
            uint32_t sw = (uint32_t)r * 128 + ((uint32_t)(ldc ^ (r & 7)) << 4);
            cpasync16s(sa + sw, Ab + (size_t)r * K + ldc * 8);
            cpasync16s(sb + sw, Bb + (size_t)r * K + ldc * 8);
        }
        asm volatile("cp.async.commit_group;");
    };

    int KT = K / BK;
    load_tiles(0, 0);

    for (int kt = 0; kt < KT; kt++) {
        if (kt + 1 < KT) {
            load_tiles((kt + 1) & 1, kt + 1);
            asm volatile("cp.async.wait_group 1;" ::: "memory");
        } else {
            asm volatile("cp.async.wait_group 0;" ::: "memory");
        }
        __syncthreads();

        uint32_t stg = sbase + (uint32_t)((kt & 1) * STGB);
        #pragma unroll
        for (int ks = 0; ks < 4; ks++) {
            uint32_t af[4][4];
            #pragma unroll
            for (int mt = 0; mt < 4; mt++)
                ldmx4(af[mt], stg + abase + (uint32_t)(mt * 2048)
                                  + ((uint32_t)((2 * ks + ahi) ^ ax) << 4));
            #pragma unroll
            for (int nt = 0; nt < 4; nt++) {
                uint32_t bf[4];
                ldmx4(bf, stg + bbase + (uint32_t)(nt * 2048)
                              + ((uint32_t)((2 * ks + bhi) ^ bx) << 4));
                #pragma unroll
                for (int mt = 0; mt < 4; mt++) {
                    mma_f16(acc[mt][2*nt    ], af[mt], &bf[0]);
                    mma_f16(acc[mt][2*nt + 1], af[mt], &bf[2]);
                }
            }
        }
        __syncthreads();
    }

    // Epilogue
    #pragma unroll
    for (int i = 0; i < 4; i++) {
        int r0 = row0 + wm + i * 16 + gr;
        #pragma unroll
        for (int j = 0; j < 8; j++) {
            int cc = col0 + wn + j * 8 + 2 * t4;
            float2 bb = *(const float2*)&bias[cc];
            float v0 = acc[i][j][0] + bb.x;
            float v1 = acc[i][j][1] + bb.y;
            float v2 = acc[i][j][2] + bb.x;
            float v3 = acc[i][j][3] + bb.y;
            if (DO_GELU) {
                v0 = 0.5f * v0 * (1.0f + erff(v0 * 0.70710678118654752f));
                v1 = 0.5f * v1 * (1.0f + erff(v1 * 0.70710678118654752f));
                v2 = 0.5f * v2 * (1.0f + erff(v2 * 0.70710678118654752f));
                v3 = 0.5f * v3 * (1.0f + erff(v3 * 0.70710678118654752f));
            }
            if (DO_QSCALE && cc < CDIM) {
                v0 *= QSCALE; v1 *= QSCALE; v2 *= QSCALE; v3 *= QSCALE;
            }
            size_t o0 = (size_t)r0 * N + cc;
            size_t o1 = (size_t)(r0 + 8) * N + cc;
            if (DO_RESID) {
                float2 ra = *(const float2*)&resid[o0];
                float2 rb = *(const float2*)&resid[o1];
                v0 += ra.x; v1 += ra.y; v2 += rb.x; v3 += rb.y;
            }
            if (OUT_HALF) {
                uint32_t* C = (uint32_t*)Cv;
                C[o0 >> 1] = h2pack(v0, v1);
                C[o1 >> 1] = h2pack(v2, v3);
            } else {
                float* C = (float*)Cv;
                *(float2*)&C[o0] = make_float2(v0, v1);
                *(float2*)&C[o1] = make_float2(v2, v3);
            }
        }
    }
}

// ---------------------------------------------------------------------------
// FP16 flash attention: 128 queries x 1 head, 256 thr, 2 CTAs/SM.
// q is pre-scaled by 0.125*log2(e) at the qkv epilogue, so S is exp2-ready.
// ---------------------------------------------------------------------------
#define ROWW 36
#define ROWB 144
#define ATQ_W 0
#define ATS_W 4608
#define ATTN_SMEM ((4608 + 2 * 4608) * 4)   // 55296 B

__global__ __launch_bounds__(256, 2)
void attn_h2(const __half* __restrict__ qkv, __half* __restrict__ outp)
{
    extern __shared__ __align__(16) uint32_t smq[];

    int tid  = threadIdx.x;
    int warp = tid >> 5;
    int lane = tid & 31;
    int gr   = lane >> 2;
    int t4   = lane & 3;
    int qb   = blockIdx.x * 128;
    int b    = blockIdx.y / NHEADS;
    int h    = blockIdx.y % NHEADS;
    const __half* base = qkv + (size_t)b * SEQ * C3 + h * HDIM;

    uint32_t sbase = (uint32_t)__cvta_generic_to_shared(smq);

    auto load_kv = [&](int st, int kt) {
        const __half* kb = base + (size_t)(kt * 64) * C3 + CDIM;
        uint32_t* sk = &smq[ATS_W * (1 + st)];
        uint32_t* sv = sk + 2304;
        #pragma unroll
        for (int i = 0; i < 2; i++) {
            int idx = tid + i * 256;
            int r = idx >> 3, c8 = idx & 7;
            cpasync16(&sk[r * ROWW + c8 * 4], kb + (size_t)r * C3 + c8 * 8);
            cpasync16(&sv[r * ROWW + c8 * 4], kb + (size_t)r * C3 + CDIM + c8 * 8);
        }
        asm volatile("cp.async.commit_group;");
    };

    load_kv(0, 0);

    #pragma unroll
    for (int i = 0; i < 4; i++) {
        int idx = tid + i * 256;
        int r = idx >> 3, c8 = idx & 7;
        uint4 v = *(const uint4*)(base + (size_t)(qb + r) * C3 + c8 * 8);
        *(uint4*)&smq[ATQ_W + r * ROWW + c8 * 4] = v;
    }
    __syncthreads();

    uint32_t qoff = (uint32_t)(16 * warp + (lane & 15)) * ROWB + (uint32_t)(lane >> 4) * 16;
    uint32_t qf[4][4];
    #pragma unroll
    for (int ks = 0; ks < 4; ks++)
        ldmx4(qf[ks], sbase + qoff + (uint32_t)(ks * 32));

    uint32_t koff = (uint32_t)((lane & 7) + ((lane >> 4) << 3)) * ROWB +
                    (uint32_t)((lane >> 3) & 1) * 16;
    uint32_t voff = 2304u * 4 + (uint32_t)(lane & 15) * ROWB + (uint32_t)(lane >> 4) * 16;

    float m1 = -1e30f, m2 = -1e30f, l1 = 0.f, l2 = 0.f;
    float oc[8][4];
    #pragma unroll
    for (int j = 0; j < 8; j++)
        #pragma unroll
        for (int r = 0; r < 4; r++) oc[j][r] = 0.f;

    for (int kt = 0; kt < SEQ / 64; kt++) {
        asm volatile("cp.async.wait_group 0;" ::: "memory");
        __syncthreads();
        if (kt + 1 < SEQ / 64) load_kv((kt + 1) & 1, kt + 1);

        uint32_t stb = sbase + (uint32_t)(ATS_W * (1 + (kt & 1)) * 4);

        // S = Q @ K^T  (already in log2 domain)
        float sc[8][4];
        #pragma unroll
        for (int j = 0; j < 8; j++)
            #pragma unroll
            for (int r = 0; r < 4; r++) sc[j][r] = 0.f;

        #pragma unroll
        for (int ks = 0; ks < 4; ks++) {
            uint32_t kf[4][4];
            #pragma unroll
            for (int nt = 0; nt < 4; nt++)
                ldmx4(kf[nt], stb + koff + (uint32_t)(nt * 16 * ROWB + ks * 32));
            #pragma unroll
            for (int nt = 0; nt < 4; nt++) {
                mma_f16(sc[2*nt    ], qf[ks], &kf[nt][0]);
                mma_f16(sc[2*nt + 1], qf[ks], &kf[nt][2]);
            }
        }

        float mx1 = -1e30f, mx2 = -1e30f;
        #pragma unroll
        for (int j = 0; j < 8; j++) {
            mx1 = fmaxf(mx1, fmaxf(sc[j][0], sc[j][1]));
            mx2 = fmaxf(mx2, fmaxf(sc[j][2], sc[j][3]));
        }
        mx1 = fmaxf(mx1, __shfl_xor_sync(0xffffffffu, mx1, 1));
        mx1 = fmaxf(mx1, __shfl_xor_sync(0xffffffffu, mx1, 2));
        mx2 = fmaxf(mx2, __shfl_xor_sync(0xffffffffu, mx2, 1));
        mx2 = fmaxf(mx2, __shfl_xor_sync(0xffffffffu, mx2, 2));

        float nm1 = fmaxf(m1, mx1), nm2 = fmaxf(m2, mx2);
        float a1 = ex2f(m1 - nm1), a2 = ex2f(m2 - nm2);
        float s1 = 0.f, s2 = 0.f;
        uint32_t ph[8][2];
        #pragma unroll
        for (int j = 0; j < 8; j++) {
            float p0 = ex2f(sc[j][0] - nm1);
            float p1 = ex2f(sc[j][1] - nm1);
            float p2 = ex2f(sc[j][2] - nm2);
            float p3 = ex2f(sc[j][3] - nm2);
            s1 += p0 + p1; s2 += p2 + p3;
            ph[j][0] = h2pack(p0, p1);
            ph[j][1] = h2pack(p2, p3);
        }
        s1 += __shfl_xor_sync(0xffffffffu, s1, 1);
        s1 += __shfl_xor_sync(0xffffffffu, s1, 2);
        s2 += __shfl_xor_sync(0xffffffffu, s2, 1);
        s2 += __shfl_xor_sync(0xffffffffu, s2, 2);
        l1 = l1 * a1 + s1;  l2 = l2 * a2 + s2;
        m1 = nm1;           m2 = nm2;
        #pragma unroll
        for (int j = 0; j < 8; j++) {
            oc[j][0] *= a1; oc[j][1] *= a1;
            oc[j][2] *= a2; oc[j][3] *= a2;
        }

        #pragma unroll
        for (int ks = 0; ks < 4; ks++) {
            uint32_t pf[4] = { ph[2*ks][0], ph[2*ks][1], ph[2*ks+1][0], ph[2*ks+1][1] };
            uint32_t vf[4][4];
            #pragma unroll
            for (int dt = 0; dt < 4; dt++)
                ldmx4t(vf[dt], stb + voff + (uint32_t)(ks * 16 * ROWB + dt * 32));
            #pragma unroll
            for (int dt = 0; dt < 4; dt++) {
                mma_f16(oc[2*dt    ], pf, &vf[dt][0]);
                mma_f16(oc[2*dt + 1], pf, &vf[dt][2]);
            }
        }
    }

    float il1 = 1.0f / l1, il2 = 1.0f / l2;
    int r1 = qb + 16 * warp + gr;
    uint32_t* o32 = (uint32_t*)outp;
    #pragma unroll
    for (int j = 0; j < 8; j++) {
        int cc = h * HDIM + (j >> 1) * 16 + (j & 1) * 8 + 2 * t4;
        size_t o0 = ((size_t)(b * SEQ + r1) * CDIM + cc) >> 1;
        size_t o1 = o0 + 4 * CDIM;
        o32[o0] = h2pack(oc[j][0] * il1, oc[j][1] * il1);
        o32[o1] = h2pack(oc[j][2] * il2, oc[j][3] * il2);
    }
}

// ---------------------------------------------------------------------------
// Launch
// ---------------------------------------------------------------------------
extern "C" void kernel_launch(void* const* d_in, const int* in_sizes, int n_in,
                              void* d_out, int out_size)
{
    const float* x      = (const float*)d_in[0];
    const float* ln1_g  = (const float*)d_in[1];
    const float* ln1_b  = (const float*)d_in[2];
    const float* qkv_w  = (const float*)d_in[3];
    const float* qkv_b  = (const float*)d_in[4];
    const float* proj_w = (const float*)d_in[5];
    const float* proj_b = (const float*)d_in[6];
    const float* ln2_g  = (const float*)d_in[7];
    const float* ln2_b  = (const float*)d_in[8];
    const float* fc1_w  = (const float*)d_in[9];
    const float* fc1_b  = (const float*)d_in[10];
    const float* fc2_w  = (const float*)d_in[11];
    const float* fc2_b  = (const float*)d_in[12];
    float* out = (float*)d_out;

    __half *p_xn1, *p_qkv, *p_attn, *p_hn, *p_h1;
    __half *p_wq, *p_wp, *p_w1, *p_w2;
    float  *p_x2;
    cudaGetSymbolAddress((void**)&p_xn1,  g_xn1);
    cudaGetSymbolAddress((void**)&p_qkv,  g_qkv);
    cudaGetSymbolAddress((void**)&p_attn, g_attn);
    cudaGetSymbolAddress((void**)&p_x2,   g_x2);
    cudaGetSymbolAddress((void**)&p_hn,   g_hn);
    cudaGetSymbolAddress((void**)&p_h1,   g_h1);
    cudaGetSymbolAddress((void**)&p_wq,   g_wq);
    cudaGetSymbolAddress((void**)&p_wp,   g_wp);
    cudaGetSymbolAddress((void**)&p_w1,   g_w1);
    cudaGetSymbolAddress((void**)&p_w2,   g_w2);

    cudaFuncSetAttribute(attn_h2,
                         cudaFuncAttributeMaxDynamicSharedMemorySize, ATTN_SMEM);
    cudaFuncSetAttribute((hgemm<false,false,true,true>),
                         cudaFuncAttributeMaxDynamicSharedMemorySize, GEMM_SMEM_BYTES);
    cudaFuncSetAttribute((hgemm<false,true,false,false>),
                         cudaFuncAttributeMaxDynamicSharedMemorySize, GEMM_SMEM_BYTES);
    cudaFuncSetAttribute((hgemm<true,false,true,false>),
                         cudaFuncAttributeMaxDynamicSharedMemorySize, GEMM_SMEM_BYTES);

    // 0) Weight prep: transpose + fp16
    wprep_kernel<<<dim3(C3/32,   CDIM/32), dim3(32,8)>>>(qkv_w,  p_wq, CDIM, C3);
    wprep_kernel<<<dim3(CDIM/32, CDIM/32), dim3(32,8)>>>(proj_w, p_wp, CDIM, CDIM);
    wprep_kernel<<<dim3(HID/32,  CDIM/32), dim3(32,8)>>>(fc1_w,  p_w1, CDIM, HID);
    wprep_kernel<<<dim3(CDIM/32, HID/32 ), dim3(32,8)>>>(fc2_w,  p_w2, HID,  CDIM);

    // 1) LN1
    ln_kernel<<<TOKENS, 192>>>(x, ln1_g, ln1_b, p_xn1);

    // 2) qkv = xn1 @ qkv_w + qkv_b  (half out, q pre-scaled)
    hgemm<false,false,true,true><<<dim3(C3/128, TOKENS/128), 128, GEMM_SMEM_BYTES>>>(
        p_xn1, p_wq, qkv_b, nullptr, p_qkv, TOKENS, C3, CDIM);

    // 3) attention (half out)
    attn_h2<<<dim3(SEQ/128, BATCH*NHEADS), 256, ATTN_SMEM>>>(p_qkv, p_attn);

    // 4) x2 = x + attn @ proj_w + proj_b  (fp32 out)
    hgemm<false,true,false,false><<<dim3(CDIM/128, TOKENS/128), 128, GEMM_SMEM_BYTES>>>(
        p_attn, p_wp, proj_b, x, p_x2, TOKENS, CDIM, CDIM);

    // 5) LN2
    ln_kernel<<<TOKENS, 192>>>(p_x2, ln2_g, ln2_b, p_hn);

    // 6) h1 = gelu(hn @ fc1_w + fc1_b)  (half out)
    hgemm<true,false,true,false><<<dim3(HID/128, TOKENS/128), 128, GEMM_SMEM_BYTES>>>(
        p_hn, p_w1, fc1_b, nullptr, p_h1, TOKENS, HID, CDIM);

    // 7) out = x2 + h1 @ fc2_w + fc2_b  (fp32 out)
    hgemm<false,true,false,false><<<dim3(CDIM/128, TOKENS/128), 128, GEMM_SMEM_BYTES>>>(
        p_h1, p_w2, fc2_b, p_x2, out, TOKENS, CDIM, HID);
}

// round 10
// speedup vs baseline: 1.2850x; 1.0138x over previous
#include <cuda_runtime.h>
#include <cuda_fp16.h>
#include <math.h>
#include <stdint.h>

// Problem constants
#define BATCH   16
#define SEQ     1024
#define TOKENS  (BATCH*SEQ)     // 16384
#define CDIM    768
#define C3      (3*CDIM)        // 2304
#define HID     3072
#define NHEADS  12
#define HDIM    64
#define LN_EPS  1e-5f

// ---------------------------------------------------------------------------
// Scratch (device globals; allocation APIs are forbidden)
// ---------------------------------------------------------------------------
__device__ __half g_xn1 [ (size_t)TOKENS * CDIM ];
__device__ __half g_qkv [ (size_t)TOKENS * C3   ];
__device__ __half g_attn[ (size_t)TOKENS * CDIM ];
__device__ float  g_x2  [ (size_t)TOKENS * CDIM ];
__device__ __half g_hn  [ (size_t)TOKENS * CDIM ];
__device__ __half g_h1  [ (size_t)TOKENS * HID  ];
// fp16, TRANSPOSED weights: wT[n][k]
__device__ __half g_wq  [ (size_t)C3   * CDIM ];
__device__ __half g_wp  [ (size_t)CDIM * CDIM ];
__device__ __half g_w1  [ (size_t)HID  * CDIM ];
__device__ __half g_w2  [ (size_t)CDIM * HID  ];

// softmax scale * log2(e), folded into q at qkv-GEMM epilogue
#define QSCALE 0.18033688011112042f

// ---------------------------------------------------------------------------
// Helpers
// ---------------------------------------------------------------------------
__device__ __forceinline__ float ex2f(float x) {
    float y;
    asm("ex2.approx.f32 %0, %1;" : "=f"(y) : "f"(x));
    return y;
}
__device__ __forceinline__ void mma_f16(float* c, const uint32_t* a, const uint32_t* b) {
    asm volatile(
        "mma.sync.aligned.m16n8k16.row.col.f32.f16.f16.f32 "
        "{%0,%1,%2,%3}, {%4,%5,%6,%7}, {%8,%9}, {%0,%1,%2,%3};"
        : "+f"(c[0]), "+f"(c[1]), "+f"(c[2]), "+f"(c[3])
        : "r"(a[0]), "r"(a[1]), "r"(a[2]), "r"(a[3]), "r"(b[0]), "r"(b[1]));
}
__device__ __forceinline__ void cpasync16(void* smem_ptr, const void* gmem_ptr) {
    uint32_t s = (uint32_t)__cvta_generic_to_shared(smem_ptr);
    asm volatile("cp.async.cg.shared.global [%0], [%1], 16;" :: "r"(s), "l"(gmem_ptr));
}
__device__ __forceinline__ void cpasync16s(uint32_t saddr, const void* gmem_ptr) {
    asm volatile("cp.async.cg.shared.global [%0], [%1], 16;" :: "r"(saddr), "l"(gmem_ptr));
}
__device__ __forceinline__ void ldmx4(uint32_t* r, uint32_t saddr) {
    asm volatile("ldmatrix.sync.aligned.m8n8.x4.shared.b16 {%0,%1,%2,%3}, [%4];"
                 : "=r"(r[0]), "=r"(r[1]), "=r"(r[2]), "=r"(r[3]) : "r"(saddr));
}
__device__ __forceinline__ void ldmx4t(uint32_t* r, uint32_t saddr) {
    asm volatile("ldmatrix.sync.aligned.m8n8.x4.trans.shared.b16 {%0,%1,%2,%3}, [%4];"
                 : "=r"(r[0]), "=r"(r[1]), "=r"(r[2]), "=r"(r[3]) : "r"(saddr));
}
__device__ __forceinline__ uint32_t h2pack(float lo, float hi) {
    __half2 h = __floats2half2_rn(lo, hi);
    return *reinterpret_cast<uint32_t*>(&h);
}

// ---------------------------------------------------------------------------
// Fused weight prep: all four weights, transpose + fp16 in one launch.
// Tile = 32x32. Segments laid out by flattened tile index.
// ---------------------------------------------------------------------------
#define WQ_TILES (72*24)   // C3/32 x CDIM/32
#define WP_TILES (24*24)
#define W1_TILES (96*24)
#define W2_TILES (24*96)
#define WPREP_TILES (WQ_TILES + WP_TILES + W1_TILES + W2_TILES)

__global__ __launch_bounds__(256)
void wprep_all(const float* __restrict__ qkv_w, const float* __restrict__ proj_w,
               const float* __restrict__ fc1_w, const float* __restrict__ fc2_w,
               __half* __restrict__ wq, __half* __restrict__ wp,
               __half* __restrict__ w1, __half* __restrict__ w2)
{
    int t = blockIdx.x;
    const float* in; __half* out; int K, N, nt;
    if (t < WQ_TILES)                      { in = qkv_w;  out = wq; K = CDIM; N = C3;   nt = t; }
    else if (t < WQ_TILES + WP_TILES)      { in = proj_w; out = wp; K = CDIM; N = CDIM; nt = t - WQ_TILES; }
    else if (t < WQ_TILES + WP_TILES + W1_TILES)
                                           { in = fc1_w;  out = w1; K = CDIM; N = HID;  nt = t - WQ_TILES - WP_TILES; }
    else                                   { in = fc2_w;  out = w2; K = HID;  N = CDIM; nt = t - WQ_TILES - WP_TILES - W1_TILES; }

    int ntx = N / 32;
    int n0 = (nt % ntx) * 32;
    int k0 = (nt / ntx) * 32;

    __shared__ float tt[32][33];
    int tx = threadIdx.x & 31, ty = threadIdx.x >> 5;
    #pragma unroll
    for (int j = 0; j < 4; j++) {
        int kk = j * 8 + ty;
        tt[kk][tx] = in[(size_t)(k0 + kk) * N + n0 + tx];
    }
    __syncthreads();
    #pragma unroll
    for (int j = 0; j < 4; j++) {
        int nn = j * 8 + ty;
        out[(size_t)(n0 + nn) * K + k0 + tx] = __float2half_rn(tt[tx][nn]);
    }
}

// ---------------------------------------------------------------------------
// LayerNorm v3: warp-per-row, 8 rows per 256-thread block.
// No smem, no __syncthreads — pure shfl reductions.
// ---------------------------------------------------------------------------
__global__ __launch_bounds__(256)
void ln_kernel(const float* __restrict__ x, const float* __restrict__ gam,
               const float* __restrict__ bet, __half* __restrict__ out)
{
    int lane = threadIdx.x & 31;
    int w    = threadIdx.x >> 5;
    int row  = blockIdx.x * 8 + w;

    const float4* xr = (const float4*)(x + (size_t)row * CDIM);
    float4 v[6];
    #pragma unroll
    for (int i = 0; i < 6; i++) v[i] = xr[lane + 32 * i];

    float s = 0.f;
    #pragma unroll
    for (int i = 0; i < 6; i++) s += v[i].x + v[i].y + v[i].z + v[i].w;
    #pragma unroll
    for (int off = 16; off > 0; off >>= 1) s += __shfl_xor_sync(0xffffffffu, s, off);
    float mu = s * (1.0f / CDIM);

    float q = 0.f;
    #pragma unroll
    for (int i = 0; i < 6; i++) {
        v[i].x -= mu; v[i].y -= mu; v[i].z -= mu; v[i].w -= mu;
        q += v[i].x*v[i].x + v[i].y*v[i].y + v[i].z*v[i].z + v[i].w*v[i].w;
    }
    #pragma unroll
    for (int off = 16; off > 0; off >>= 1) q += __shfl_xor_sync(0xffffffffu, q, off);
    float rs = rsqrtf(q * (1.0f / CDIM) + LN_EPS);

    uint2* orow = (uint2*)(out + (size_t)row * CDIM);
    #pragma unroll
    for (int i = 0; i < 6; i++) {
        float4 g  = ((const float4*)gam)[lane + 32 * i];
        float4 be = ((const float4*)bet)[lane + 32 * i];
        uint2 o;
        o.x = h2pack(v[i].x * rs * g.x + be.x, v[i].y * rs * g.y + be.y);
        o.y = h2pack(v[i].z * rs * g.z + be.z, v[i].w * rs * g.w + be.w);
        orow[lane + 32 * i] = o;
    }
}

// ---------------------------------------------------------------------------
// FP16 tensor-core GEMM: 128x128x64 CTA tile, 128 threads (4 warps),
// warp tile 64x64, XOR-swizzled 128B-row smem, ldmatrix, 2-stage cp.async,
// 3 CTAs/SM. DO_QSCALE: multiply columns [0,768) by QSCALE (q pre-scaling).
// ---------------------------------------------------------------------------
#define BK 64
#define STGB 32768
#define GEMM_SMEM_BYTES (2 * STGB)  // 65536

template<bool DO_GELU, bool DO_RESID, bool OUT_HALF, bool DO_QSCALE>
__global__ __launch_bounds__(128, 3)
void hgemm(const __half* __restrict__ A, const __half* __restrict__ Bt,
           const float* __restrict__ bias, const float* __restrict__ resid,
           void* __restrict__ Cv, int M, int N, int K)
{
    extern __shared__ __align__(16) char smb[];
    uint32_t sbase = (uint32_t)__cvta_generic_to_shared(smb);

    int tid  = threadIdx.x;
    int warp = tid >> 5;
    int lane = tid & 31;
    int gr   = lane >> 2;
    int t4   = lane & 3;
    int row0 = blockIdx.y * 128;
    int col0 = blockIdx.x * 128;
    int wm   = (warp >> 1) * 64;
    int wn   = (warp & 1) * 64;

    int arow = wm + (lane & 15);
    int ahi  = lane >> 4;
    int brow = wn + (lane & 7) + ((lane >> 4) << 3);
    int bhi  = (lane >> 3) & 1;
    uint32_t abase = (uint32_t)arow * 128;
    uint32_t bbase = 16384u + (uint32_t)brow * 128;
    int ax = arow & 7;
    int bx = brow & 7;

    float acc[4][8][4];
    #pragma unroll
    for (int i = 0; i < 4; i++)
        #pragma unroll
        for (int j = 0; j < 8; j++)
            #pragma unroll
            for (int r = 0; r < 4; r++) acc[i][j][r] = 0.f;

    int ldr = tid >> 3;
    int ldc = tid & 7;

    auto load_tiles = [&](int st, int kt) {
        int k0 = kt * BK;
        const __half* Ab = A  + (size_t)row0 * K + k0;
        const __half* Bb = Bt + (size_t)col0 * K + k0;
        uint32_t sa = sbase + (uint32_t)st * STGB;
        uint32_t sb = sa + 16384u;
        #pragma unroll
        for (int i = 0; i < 8; i++) {
            int r = ldr + i * 16;
            uint32_t sw = (uint32_t)r * 128 + ((uint32_t)(ldc ^ (r & 7)) << 4);
            cpasync16s(sa + sw, Ab + (size_t)r * K + ldc * 8);
            cpasync16s(sb + sw, Bb + (size_t)r * K + ldc * 8);
        }
        asm volatile("cp.async.commit_group;");
    };

    int KT = K / BK;
    load_tiles(0, 0);

    for (int kt = 0; kt < KT; kt++) {
        if (kt + 1 < KT) {
            load_tiles((kt + 1) & 1, kt + 1);
            asm volatile("cp.async.wait_group 1;" ::: "memory");
        } else {
            asm volatile("cp.async.wait_group 0;" ::: "memory");
        }
        __syncthreads();

        uint32_t stg = sbase + (uint32_t)((kt & 1) * STGB);
        #pragma unroll
        for (int ks = 0; ks < 4; ks++) {
            uint32_t af[4][4];
            #pragma unroll
            for (int mt = 0; mt < 4; mt++)
                ldmx4(af[mt], stg + abase + (uint32_t)(mt * 2048)
                                  + ((uint32_t)((2 * ks + ahi) ^ ax) << 4));
            #pragma unroll
            for (int nt = 0; nt < 4; nt++) {
                uint32_t bf[4];
                ldmx4(bf, stg + bbase + (uint32_t)(nt * 2048)
                              + ((uint32_t)((2 * ks + bhi) ^ bx) << 4));
                #pragma unroll
                for (int mt = 0; mt < 4; mt++) {
                    mma_f16(acc[mt][2*nt    ], af[mt], &bf[0]);
                    mma_f16(acc[mt][2*nt + 1], af[mt], &bf[2]);
                }
            }
        }
        __syncthreads();
    }

    // Epilogue
    #pragma unroll
    for (int i = 0; i < 4; i++) {
        int r0 = row0 + wm + i * 16 + gr;
        #pragma unroll
        for (int j = 0; j < 8; j++) {
            int cc = col0 + wn + j * 8 + 2 * t4;
            float2 bb = *(const float2*)&bias[cc];
            float v0 = acc[i][j][0] + bb.x;
            float v1 = acc[i][j][1] + bb.y;
            float v2 = acc[i][j][2] + bb.x;
            float v3 = acc[i][j][3] + bb.y;
            if (DO_GELU) {
                v0 = 0.5f * v0 * (1.0f + erff(v0 * 0.70710678118654752f));
                v1 = 0.5f * v1 * (1.0f + erff(v1 * 0.70710678118654752f));
                v2 = 0.5f * v2 * (1.0f + erff(v2 * 0.70710678118654752f));
                v3 = 0.5f * v3 * (1.0f + erff(v3 * 0.70710678118654752f));
            }
            if (DO_QSCALE && cc < CDIM) {
                v0 *= QSCALE; v1 *= QSCALE; v2 *= QSCALE; v3 *= QSCALE;
            }
            size_t o0 = (size_t)r0 * N + cc;
            size_t o1 = (size_t)(r0 + 8) * N + cc;
            if (DO_RESID) {
                float2 ra = *(const float2*)&resid[o0];
                float2 rb = *(const float2*)&resid[o1];
                v0 += ra.x; v1 += ra.y; v2 += rb.x; v3 += rb.y;
            }
            if (OUT_HALF) {
                uint32_t* C = (uint32_t*)Cv;
                C[o0 >> 1] = h2pack(v0, v1);
                C[o1 >> 1] = h2pack(v2, v3);
            } else {
                float* C = (float*)Cv;
                *(float2*)&C[o0] = make_float2(v0, v1);
                *(float2*)&C[o1] = make_float2(v2, v3);
            }
        }
    }
}

// ---------------------------------------------------------------------------
// FP16 flash attention: 128 queries x 1 head, 256 thr, 2 CTAs/SM.
// q is pre-scaled by 0.125*log2(e) at the qkv epilogue, so S is exp2-ready.
// ---------------------------------------------------------------------------
#define ROWW 36
#define ROWB 144
#define ATQ_W 0
#define ATS_W 4608
#define ATTN_SMEM ((4608 + 2 * 4608) * 4)   // 55296 B

__global__ __launch_bounds__(256, 2)
void attn_h2(const __half* __restrict__ qkv, __half* __restrict__ outp)
{
    extern __shared__ __align__(16) uint32_t smq[];

    int tid  = threadIdx.x;
    int warp = tid >> 5;
    int lane = tid & 31;
    int gr   = lane >> 2;
    int t4   = lane & 3;
    int qb   = blockIdx.x * 128;
    int b    = blockIdx.y / NHEADS;
    int h    = blockIdx.y % NHEADS;
    const __half* base = qkv + (size_t)b * SEQ * C3 + h * HDIM;

    uint32_t sbase = (uint32_t)__cvta_generic_to_shared(smq);

    auto load_kv = [&](int st, int kt) {
        const __half* kb = base + (size_t)(kt * 64) * C3 + CDIM;
        uint32_t* sk = &smq[ATS_W * (1 + st)];
        uint32_t* sv = sk + 2304;
        #pragma unroll
        for (int i = 0; i < 2; i++) {
            int idx = tid + i * 256;
            int r = idx >> 3, c8 = idx & 7;
            cpasync16(&sk[r * ROWW + c8 * 4], kb + (size_t)r * C3 + c8 * 8);
            cpasync16(&sv[r * ROWW + c8 * 4], kb + (size_t)r * C3 + CDIM + c8 * 8);
        }
        asm volatile("cp.async.commit_group;");
    };

    load_kv(0, 0);

    #pragma unroll
    for (int i = 0; i < 4; i++) {
        int idx = tid + i * 256;
        int r = idx >> 3, c8 = idx & 7;
        uint4 v = *(const uint4*)(base + (size_t)(qb + r) * C3 + c8 * 8);
        *(uint4*)&smq[ATQ_W + r * ROWW + c8 * 4] = v;
    }
    __syncthreads();

    uint32_t qoff = (uint32_t)(16 * warp + (lane & 15)) * ROWB + (uint32_t)(lane >> 4) * 16;
    uint32_t qf[4][4];
    #pragma unroll
    for (int ks = 0; ks < 4; ks++)
        ldmx4(qf[ks], sbase + qoff + (uint32_t)(ks * 32));

    uint32_t koff = (uint32_t)((lane & 7) + ((lane >> 4) << 3)) * ROWB +
                    (uint32_t)((lane >> 3) & 1) * 16;
    uint32_t voff = 2304u * 4 + (uint32_t)(lane & 15) * ROWB + (uint32_t)(lane >> 4) * 16;

    float m1 = -1e30f, m2 = -1e30f, l1 = 0.f, l2 = 0.f;
    float oc[8][4];
    #pragma unroll
    for (int j = 0; j < 8; j++)
        #pragma unroll
        for (int r = 0; r < 4; r++) oc[j][r] = 0.f;

    for (int kt = 0; kt < SEQ / 64; kt++) {
        asm volatile("cp.async.wait_group 0;" ::: "memory");
        __syncthreads();
        if (kt + 1 < SEQ / 64) load_kv((kt + 1) & 1, kt + 1);

        uint32_t stb = sbase + (uint32_t)(ATS_W * (1 + (kt & 1)) * 4);

        float sc[8][4];
        #pragma unroll
        for (int j = 0; j < 8; j++)
            #pragma unroll
            for (int r = 0; r < 4; r++) sc[j][r] = 0.f;

        #pragma unroll
        for (int ks = 0; ks < 4; ks++) {
            uint32_t kf[4][4];
            #pragma unroll
            for (int nt = 0; nt < 4; nt++)
                ldmx4(kf[nt], stb + koff + (uint32_t)(nt * 16 * ROWB + ks * 32));
            #pragma unroll
            for (int nt = 0; nt < 4; nt++) {
                mma_f16(sc[2*nt    ], qf[ks], &kf[nt][0]);
                mma_f16(sc[2*nt + 1], qf[ks], &kf[nt][2]);
            }
        }

        float mx1 = -1e30f, mx2 = -1e30f;
        #pragma unroll
        for (int j = 0; j < 8; j++) {
            mx1 = fmaxf(mx1, fmaxf(sc[j][0], sc[j][1]));
            mx2 = fmaxf(mx2, fmaxf(sc[j][2], sc[j][3]));
        }
        mx1 = fmaxf(mx1, __shfl_xor_sync(0xffffffffu, mx1, 1));
        mx1 = fmaxf(mx1, __shfl_xor_sync(0xffffffffu, mx1, 2));
        mx2 = fmaxf(mx2, __shfl_xor_sync(0xffffffffu, mx2, 1));
        mx2 = fmaxf(mx2, __shfl_xor_sync(0xffffffffu, mx2, 2));

        float nm1 = fmaxf(m1, mx1), nm2 = fmaxf(m2, mx2);
        float a1 = ex2f(m1 - nm1), a2 = ex2f(m2 - nm2);
        float s1 = 0.f, s2 = 0.f;
        uint32_t ph[8][2];
        #pragma unroll
        for (int j = 0; j < 8; j++) {
            float p0 = ex2f(sc[j][0] - nm1);
            float p1 = ex2f(sc[j][1] - nm1);
            float p2 = ex2f(sc[j][2] - nm2);
            float p3 = ex2f(sc[j][3] - nm2);
            s1 += p0 + p1; s2 += p2 + p3;
            ph[j][0] = h2pack(p0, p1);
            ph[j][1] = h2pack(p2, p3);
        }
        s1 += __shfl_xor_sync(0xffffffffu, s1, 1);
        s1 += __shfl_xor_sync(0xffffffffu, s1, 2);
        s2 += __shfl_xor_sync(0xffffffffu, s2, 1);
        s2 += __shfl_xor_sync(0xffffffffu, s2, 2);
        l1 = l1 * a1 + s1;  l2 = l2 * a2 + s2;
        m1 = nm1;           m2 = nm2;
        #pragma unroll
        for (int j = 0; j < 8; j++) {
            oc[j][0] *= a1; oc[j][1] *= a1;
            oc[j][2] *= a2; oc[j][3] *= a2;
        }

        #pragma unroll
        for (int ks = 0; ks < 4; ks++) {
            uint32_t pf[4] = { ph[2*ks][0], ph[2*ks][1], ph[2*ks+1][0], ph[2*ks+1][1] };
            uint32_t vf[4][4];
            #pragma unroll
            for (int dt = 0; dt < 4; dt++)
                ldmx4t(vf[dt], stb + voff + (uint32_t)(ks * 16 * ROWB + dt * 32));
            #pragma unroll
            for (int dt = 0; dt < 4; dt++) {
                mma_f16(oc[2*dt    ], pf, &vf[dt][0]);
                mma_f16(oc[2*dt + 1], pf, &vf[dt][2]);
            }
        }
    }

    float il1 = 1.0f / l1, il2 = 1.0f / l2;
    int r1 = qb + 16 * warp + gr;
    uint32_t* o32 = (uint32_t*)outp;
    #pragma unroll
    for (int j = 0; j < 8; j++) {
        int cc = h * HDIM + (j >> 1) * 16 + (j & 1) * 8 + 2 * t4;
        size_t o0 = ((size_t)(b * SEQ + r1) * CDIM + cc) >> 1;
        size_t o1 = o0 + 4 * CDIM;
        o32[o0] = h2pack(oc[j][0] * il1, oc[j][1] * il1);
        o32[o1] = h2pack(oc[j][2] * il2, oc[j][3] * il2);
    }
}

// ---------------------------------------------------------------------------
// Launch
// ---------------------------------------------------------------------------
extern "C" void kernel_launch(void* const* d_in, const int* in_sizes, int n_in,
                              void* d_out, int out_size)
{
    const float* x      = (const float*)d_in[0];
    const float* ln1_g  = (const float*)d_in[1];
    const float* ln1_b  = (const float*)d_in[2];
    const float* qkv_w  = (const float*)d_in[3];
    const float* qkv_b  = (const float*)d_in[4];
    const float* proj_w = (const float*)d_in[5];
    const float* proj_b = (const float*)d_in[6];
    const float* ln2_g  = (const float*)d_in[7];
    const float* ln2_b  = (const float*)d_in[8];
    const float* fc1_w  = (const float*)d_in[9];
    const float* fc1_b  = (const float*)d_in[10];
    const float* fc2_w  = (const float*)d_in[11];
    const float* fc2_b  = (const float*)d_in[12];
    float* out = (float*)d_out;

    __half *p_xn1, *p_qkv, *p_attn, *p_hn, *p_h1;
    __half *p_wq, *p_wp, *p_w1, *p_w2;
    float  *p_x2;
    cudaGetSymbolAddress((void**)&p_xn1,  g_xn1);
    cudaGetSymbolAddress((void**)&p_qkv,  g_qkv);
    cudaGetSymbolAddress((void**)&p_attn, g_attn);
    cudaGetSymbolAddress((void**)&p_x2,   g_x2);
    cudaGetSymbolAddress((void**)&p_hn,   g_hn);
    cudaGetSymbolAddress((void**)&p_h1,   g_h1);
    cudaGetSymbolAddress((void**)&p_wq,   g_wq);
    cudaGetSymbolAddress((void**)&p_wp,   g_wp);
    cudaGetSymbolAddress((void**)&p_w1,   g_w1);
    cudaGetSymbolAddress((void**)&p_w2,   g_w2);

    cudaFuncSetAttribute(attn_h2,
                         cudaFuncAttributeMaxDynamicSharedMemorySize, ATTN_SMEM);
    cudaFuncSetAttribute((hgemm<false,false,true,true>),
                         cudaFuncAttributeMaxDynamicSharedMemorySize, GEMM_SMEM_BYTES);
    cudaFuncSetAttribute((hgemm<false,true,false,false>),
                         cudaFuncAttributeMaxDynamicSharedMemorySize, GEMM_SMEM_BYTES);
    cudaFuncSetAttribute((hgemm<true,false,true,false>),
                         cudaFuncAttributeMaxDynamicSharedMemorySize, GEMM_SMEM_BYTES);

    // 0) Weight prep (fused): transpose + fp16 for all four weights
    wprep_all<<<WPREP_TILES, 256>>>(qkv_w, proj_w, fc1_w, fc2_w,
                                    p_wq, p_wp, p_w1, p_w2);

    // 1) LN1
    ln_kernel<<<TOKENS/8, 256>>>(x, ln1_g, ln1_b, p_xn1);

    // 2) qkv = xn1 @ qkv_w + qkv_b  (half out, q pre-scaled)
    hgemm<false,false,true,true><<<dim3(C3/128, TOKENS/128), 128, GEMM_SMEM_BYTES>>>(
        p_xn1, p_wq, qkv_b, nullptr, p_qkv, TOKENS, C3, CDIM);

    // 3) attention (half out)
    attn_h2<<<dim3(SEQ/128, BATCH*NHEADS), 256, ATTN_SMEM>>>(p_qkv, p_attn);

    // 4) x2 = x + attn @ proj_w + proj_b  (fp32 out)
    hgemm<false,true,false,false><<<dim3(CDIM/128, TOKENS/128), 128, GEMM_SMEM_BYTES>>>(
        p_attn, p_wp, proj_b, x, p_x2, TOKENS, CDIM, CDIM);

    // 5) LN2
    ln_kernel<<<TOKENS/8, 256>>>(p_x2, ln2_g, ln2_b, p_hn);

    // 6) h1 = gelu(hn @ fc1_w + fc1_b)  (half out)
    hgemm<true,false,true,false><<<dim3(HID/128, TOKENS/128), 128, GEMM_SMEM_BYTES>>>(
        p_hn, p_w1, fc1_b, nullptr, p_h1, TOKENS, HID, CDIM);

    // 7) out = x2 + h1 @ fc2_w + fc2_b  (fp32 out)
    hgemm<false,true,false,false><<<dim3(CDIM/128, TOKENS/128), 128, GEMM_SMEM_BYTES>>>(
        p_h1, p_w2, fc2_b, p_x2, out, TOKENS, CDIM, HID);
}

// round 11
// speedup vs baseline: 1.2883x; 1.0026x over previous
#include <cuda_runtime.h>
#include <cuda_fp16.h>
#include <math.h>
#include <stdint.h>

// Problem constants
#define BATCH   16
#define SEQ     1024
#define TOKENS  (BATCH*SEQ)     // 16384
#define CDIM    768
#define C3      (3*CDIM)        // 2304
#define HID     3072
#define NHEADS  12
#define HDIM    64
#define LN_EPS  1e-5f

// ---------------------------------------------------------------------------
// Scratch (device globals; allocation APIs are forbidden)
// ---------------------------------------------------------------------------
__device__ __half g_xn1 [ (size_t)TOKENS * CDIM ];
__device__ __half g_qkv [ (size_t)TOKENS * C3   ];
__device__ __half g_attn[ (size_t)TOKENS * CDIM ];
__device__ float  g_x2  [ (size_t)TOKENS * CDIM ];
__device__ __half g_hn  [ (size_t)TOKENS * CDIM ];
__device__ __half g_h1  [ (size_t)TOKENS * HID  ];
// fp16, TRANSPOSED weights: wT[n][k]
__device__ __half g_wq  [ (size_t)C3   * CDIM ];
__device__ __half g_wp  [ (size_t)CDIM * CDIM ];
__device__ __half g_w1  [ (size_t)HID  * CDIM ];
__device__ __half g_w2  [ (size_t)CDIM * HID  ];

// softmax scale * log2(e), folded into q at qkv-GEMM epilogue
#define QSCALE 0.18033688011112042f
#define HONES  0x3C003C00u          // half2(1.0, 1.0)

// ---------------------------------------------------------------------------
// Helpers
// ---------------------------------------------------------------------------
__device__ __forceinline__ float ex2f(float x) {
    float y;
    asm("ex2.approx.f32 %0, %1;" : "=f"(y) : "f"(x));
    return y;
}
__device__ __forceinline__ void mma_f16(float* c, const uint32_t* a, const uint32_t* b) {
    asm volatile(
        "mma.sync.aligned.m16n8k16.row.col.f32.f16.f16.f32 "
        "{%0,%1,%2,%3}, {%4,%5,%6,%7}, {%8,%9}, {%0,%1,%2,%3};"
        : "+f"(c[0]), "+f"(c[1]), "+f"(c[2]), "+f"(c[3])
        : "r"(a[0]), "r"(a[1]), "r"(a[2]), "r"(a[3]), "r"(b[0]), "r"(b[1]));
}
__device__ __forceinline__ void cpasync16(void* smem_ptr, const void* gmem_ptr) {
    uint32_t s = (uint32_t)__cvta_generic_to_shared(smem_ptr);
    asm volatile("cp.async.cg.shared.global [%0], [%1], 16;" :: "r"(s), "l"(gmem_ptr));
}
__device__ __forceinline__ void cpasync16s(uint32_t saddr, const void* gmem_ptr) {
    asm volatile("cp.async.cg.shared.global [%0], [%1], 16;" :: "r"(saddr), "l"(gmem_ptr));
}
__device__ __forceinline__ void ldmx4(uint32_t* r, uint32_t saddr) {
    asm volatile("ldmatrix.sync.aligned.m8n8.x4.shared.b16 {%0,%1,%2,%3}, [%4];"
                 : "=r"(r[0]), "=r"(r[1]), "=r"(r[2]), "=r"(r[3]) : "r"(saddr));
}
__device__ __forceinline__ void ldmx4t(uint32_t* r, uint32_t saddr) {
    asm volatile("ldmatrix.sync.aligned.m8n8.x4.trans.shared.b16 {%0,%1,%2,%3}, [%4];"
                 : "=r"(r[0]), "=r"(r[1]), "=r"(r[2]), "=r"(r[3]) : "r"(saddr));
}
__device__ __forceinline__ uint32_t h2pack(float lo, float hi) {
    __half2 h = __floats2half2_rn(lo, hi);
    return *reinterpret_cast<uint32_t*>(&h);
}

// ---------------------------------------------------------------------------
// Fused weight prep: all four weights, transpose + fp16 in one launch.
// ---------------------------------------------------------------------------
#define WQ_TILES (72*24)
#define WP_TILES (24*24)
#define W1_TILES (96*24)
#define W2_TILES (24*96)
#define WPREP_TILES (WQ_TILES + WP_TILES + W1_TILES + W2_TILES)

__global__ __launch_bounds__(256)
void wprep_all(const float* __restrict__ qkv_w, const float* __restrict__ proj_w,
               const float* __restrict__ fc1_w, const float* __restrict__ fc2_w,
               __half* __restrict__ wq, __half* __restrict__ wp,
               __half* __restrict__ w1, __half* __restrict__ w2)
{
    int t = blockIdx.x;
    const float* in; __half* out; int K, N, nt;
    if (t < WQ_TILES)                      { in = qkv_w;  out = wq; K = CDIM; N = C3;   nt = t; }
    else if (t < WQ_TILES + WP_TILES)      { in = proj_w; out = wp; K = CDIM; N = CDIM; nt = t - WQ_TILES; }
    else if (t < WQ_TILES + WP_TILES + W1_TILES)
                                           { in = fc1_w;  out = w1; K = CDIM; N = HID;  nt = t - WQ_TILES - WP_TILES; }
    else                                   { in = fc2_w;  out = w2; K = HID;  N = CDIM; nt = t - WQ_TILES - WP_TILES - W1_TILES; }

    int ntx = N / 32;
    int n0 = (nt % ntx) * 32;
    int k0 = (nt / ntx) * 32;

    __shared__ float tt[32][33];
    int tx = threadIdx.x & 31, ty = threadIdx.x >> 5;
    #pragma unroll
    for (int j = 0; j < 4; j++) {
        int kk = j * 8 + ty;
        tt[kk][tx] = in[(size_t)(k0 + kk) * N + n0 + tx];
    }
    __syncthreads();
    #pragma unroll
    for (int j = 0; j < 4; j++) {
        int nn = j * 8 + ty;
        out[(size_t)(n0 + nn) * K + k0 + tx] = __float2half_rn(tt[tx][nn]);
    }
}

// ---------------------------------------------------------------------------
// LayerNorm: warp-per-row, 8 rows per 256-thread block. Pure shfl.
// ---------------------------------------------------------------------------
__global__ __launch_bounds__(256)
void ln_kernel(const float* __restrict__ x, const float* __restrict__ gam,
               const float* __restrict__ bet, __half* __restrict__ out)
{
    int lane = threadIdx.x & 31;
    int w    = threadIdx.x >> 5;
    int row  = blockIdx.x * 8 + w;

    const float4* xr = (const float4*)(x + (size_t)row * CDIM);
    float4 v[6];
    #pragma unroll
    for (int i = 0; i < 6; i++) v[i] = xr[lane + 32 * i];

    float s = 0.f;
    #pragma unroll
    for (int i = 0; i < 6; i++) s += v[i].x + v[i].y + v[i].z + v[i].w;
    #pragma unroll
    for (int off = 16; off > 0; off >>= 1) s += __shfl_xor_sync(0xffffffffu, s, off);
    float mu = s * (1.0f / CDIM);

    float q = 0.f;
    #pragma unroll
    for (int i = 0; i < 6; i++) {
        v[i].x -= mu; v[i].y -= mu; v[i].z -= mu; v[i].w -= mu;
        q += v[i].x*v[i].x + v[i].y*v[i].y + v[i].z*v[i].z + v[i].w*v[i].w;
    }
    #pragma unroll
    for (int off = 16; off > 0; off >>= 1) q += __shfl_xor_sync(0xffffffffu, q, off);
    float rs = rsqrtf(q * (1.0f / CDIM) + LN_EPS);

    uint2* orow = (uint2*)(out + (size_t)row * CDIM);
    #pragma unroll
    for (int i = 0; i < 6; i++) {
        float4 g  = ((const float4*)gam)[lane + 32 * i];
        float4 be = ((const float4*)bet)[lane + 32 * i];
        uint2 o;
        o.x = h2pack(v[i].x * rs * g.x + be.x, v[i].y * rs * g.y + be.y);
        o.y = h2pack(v[i].z * rs * g.z + be.z, v[i].w * rs * g.w + be.w);
        orow[lane + 32 * i] = o;
    }
}

// ---------------------------------------------------------------------------
// FP16 tensor-core GEMM: 128x128x64 CTA tile, 128 threads (4 warps),
// warp tile 64x64, XOR-swizzled smem, ldmatrix, 2-stage cp.async, 3 CTAs/SM.
// ---------------------------------------------------------------------------
#define BK 64
#define STGB 32768
#define GEMM_SMEM_BYTES (2 * STGB)  // 65536

template<bool DO_GELU, bool DO_RESID, bool OUT_HALF, bool DO_QSCALE>
__global__ __launch_bounds__(128, 3)
void hgemm(const __half* __restrict__ A, const __half* __restrict__ Bt,
           const float* __restrict__ bias, const float* __restrict__ resid,
           void* __restrict__ Cv, int M, int N, int K)
{
    extern __shared__ __align__(16) char smb[];
    uint32_t sbase = (uint32_t)__cvta_generic_to_shared(smb);

    int tid  = threadIdx.x;
    int warp = tid >> 5;
    int lane = tid & 31;
    int gr   = lane >> 2;
    int t4   = lane & 3;
    int row0 = blockIdx.y * 128;
    int col0 = blockIdx.x * 128;
    int wm   = (warp >> 1) * 64;
    int wn   = (warp & 1) * 64;

    int arow = wm + (lane & 15);
    int ahi  = lane >> 4;
    int brow = wn + (lane & 7) + ((lane >> 4) << 3);
    int bhi  = (lane >> 3) & 1;
    uint32_t abase = (uint32_t)arow * 128;
    uint32_t bbase = 16384u + (uint32_t)brow * 128;
    int ax = arow & 7;
    int bx = brow & 7;

    float acc[4][8][4];
    #pragma unroll
    for (int i = 0; i < 4; i++)
        #pragma unroll
        for (int j = 0; j < 8; j++)
            #pragma unroll
            for (int r = 0; r < 4; r++) acc[i][j][r] = 0.f;

    int ldr = tid >> 3;
    int ldc = tid & 7;

    auto load_tiles = [&](int st, int kt) {
        int k0 = kt * BK;
        const __half* Ab = A  + (size_t)row0 * K + k0;
        const __half* Bb = Bt + (size_t)col0 * K + k0;
        uint32_t sa = sbase + (uint32_t)st * STGB;
        uint32_t sb = sa + 16384u;
        #pragma unroll
        for (int i = 0; i < 8; i++) {
            int r = ldr + i * 16;
            uint32_t sw = (uint32_t)r * 128 + ((uint32_t)(ldc ^ (r & 7)) << 4);
            cpasync16s(sa + sw, Ab + (size_t)r * K + ldc * 8);
            cpasync16s(sb + sw, Bb + (size_t)r * K + ldc * 8);
        }
        asm volatile("cp.async.commit_group;");
    };

    int KT = K / BK;
    load_tiles(0, 0);

    for (int kt = 0; kt < KT; kt++) {
        if (kt + 1 < KT) {
            load_tiles((kt + 1) & 1, kt + 1);
            asm volatile("cp.async.wait_group 1;" ::: "memory");
        } else {
            asm volatile("cp.async.wait_group 0;" ::: "memory");
        }
        __syncthreads();

        uint32_t stg = sbase + (uint32_t)((kt & 1) * STGB);
        #pragma unroll
        for (int ks = 0; ks < 4; ks++) {
            uint32_t af[4][4];
            #pragma unroll
            for (int mt = 0; mt < 4; mt++)
                ldmx4(af[mt], stg + abase + (uint32_t)(mt * 2048)
                                  + ((uint32_t)((2 * ks + ahi) ^ ax) << 4));
            #pragma unroll
            for (int nt = 0; nt < 4; nt++) {
                uint32_t bf[4];
                ldmx4(bf, stg + bbase + (uint32_t)(nt * 2048)
                              + ((uint32_t)((2 * ks + bhi) ^ bx) << 4));
                #pragma unroll
                for (int mt = 0; mt < 4; mt++) {
                    mma_f16(acc[mt][2*nt    ], af[mt], &bf[0]);
                    mma_f16(acc[mt][2*nt + 1], af[mt], &bf[2]);
                }
            }
        }
        __syncthreads();
    }

    // Epilogue
    #pragma unroll
    for (int i = 0; i < 4; i++) {
        int r0 = row0 + wm + i * 16 + gr;
        #pragma unroll
        for (int j = 0; j < 8; j++) {
            int cc = col0 + wn + j * 8 + 2 * t4;
            float2 bb = *(const float2*)&bias[cc];
            float v0 = acc[i][j][0] + bb.x;
            float v1 = acc[i][j][1] + bb.y;
            float v2 = acc[i][j][2] + bb.x;
            float v3 = acc[i][j][3] + bb.y;
            if (DO_GELU) {
                v0 = 0.5f * v0 * (1.0f + erff(v0 * 0.70710678118654752f));
                v1 = 0.5f * v1 * (1.0f + erff(v1 * 0.70710678118654752f));
                v2 = 0.5f * v2 * (1.0f + erff(v2 * 0.70710678118654752f));
                v3 = 0.5f * v3 * (1.0f + erff(v3 * 0.70710678118654752f));
            }
            if (DO_QSCALE && cc < CDIM) {
                v0 *= QSCALE; v1 *= QSCALE; v2 *= QSCALE; v3 *= QSCALE;
            }
            size_t o0 = (size_t)r0 * N + cc;
            size_t o1 = (size_t)(r0 + 8) * N + cc;
            if (DO_RESID) {
                float2 ra = *(const float2*)&resid[o0];
                float2 rb = *(const float2*)&resid[o1];
                v0 += ra.x; v1 += ra.y; v2 += rb.x; v3 += rb.y;
            }
            if (OUT_HALF) {
                uint32_t* C = (uint32_t*)Cv;
                C[o0 >> 1] = h2pack(v0, v1);
                C[o1 >> 1] = h2pack(v2, v3);
            } else {
                float* C = (float*)Cv;
                *(float2*)&C[o0] = make_float2(v0, v1);
                *(float2*)&C[o1] = make_float2(v2, v3);
            }
        }
    }
}

// ---------------------------------------------------------------------------
// FP16 flash attention: 128 queries x 1 head, 256 thr, 2 CTAs/SM.
// Row sums of P computed on the TENSOR pipe via mma against all-ones B.
// ---------------------------------------------------------------------------
#define ROWW 36
#define ROWB 144
#define ATQ_W 0
#define ATS_W 4608
#define ATTN_SMEM ((4608 + 2 * 4608) * 4)   // 55296 B

__global__ __launch_bounds__(256, 2)
void attn_h2(const __half* __restrict__ qkv, __half* __restrict__ outp)
{
    extern __shared__ __align__(16) uint32_t smq[];

    int tid  = threadIdx.x;
    int warp = tid >> 5;
    int lane = tid & 31;
    int gr   = lane >> 2;
    int t4   = lane & 3;
    int qb   = blockIdx.x * 128;
    int b    = blockIdx.y / NHEADS;
    int h    = blockIdx.y % NHEADS;
    const __half* base = qkv + (size_t)b * SEQ * C3 + h * HDIM;

    uint32_t sbase = (uint32_t)__cvta_generic_to_shared(smq);

    auto load_kv = [&](int st, int kt) {
        const __half* kb = base + (size_t)(kt * 64) * C3 + CDIM;
        uint32_t* sk = &smq[ATS_W * (1 + st)];
        uint32_t* sv = sk + 2304;
        #pragma unroll
        for (int i = 0; i < 2; i++) {
            int idx = tid + i * 256;
            int r = idx >> 3, c8 = idx & 7;
            cpasync16(&sk[r * ROWW + c8 * 4], kb + (size_t)r * C3 + c8 * 8);
            cpasync16(&sv[r * ROWW + c8 * 4], kb + (size_t)r * C3 + CDIM + c8 * 8);
        }
        asm volatile("cp.async.commit_group;");
    };

    load_kv(0, 0);

    #pragma unroll
    for (int i = 0; i < 4; i++) {
        int idx = tid + i * 256;
        int r = idx >> 3, c8 = idx & 7;
        uint4 v = *(const uint4*)(base + (size_t)(qb + r) * C3 + c8 * 8);
        *(uint4*)&smq[ATQ_W + r * ROWW + c8 * 4] = v;
    }
    __syncthreads();

    uint32_t qoff = (uint32_t)(16 * warp + (lane & 15)) * ROWB + (uint32_t)(lane >> 4) * 16;
    uint32_t qf[4][4];
    #pragma unroll
    for (int ks = 0; ks < 4; ks++)
        ldmx4(qf[ks], sbase + qoff + (uint32_t)(ks * 32));

    uint32_t koff = (uint32_t)((lane & 7) + ((lane >> 4) << 3)) * ROWB +
                    (uint32_t)((lane >> 3) & 1) * 16;
    uint32_t voff = 2304u * 4 + (uint32_t)(lane & 15) * ROWB + (uint32_t)(lane >> 4) * 16;

    const uint32_t ones[2] = { HONES, HONES };

    float m1 = -1e30f, m2 = -1e30f, l1 = 0.f, l2 = 0.f;
    float oc[8][4];
    #pragma unroll
    for (int j = 0; j < 8; j++)
        #pragma unroll
        for (int r = 0; r < 4; r++) oc[j][r] = 0.f;

    for (int kt = 0; kt < SEQ / 64; kt++) {
        asm volatile("cp.async.wait_group 0;" ::: "memory");
        __syncthreads();
        if (kt + 1 < SEQ / 64) load_kv((kt + 1) & 1, kt + 1);

        uint32_t stb = sbase + (uint32_t)(ATS_W * (1 + (kt & 1)) * 4);

        // S = Q @ K^T  (already in log2 domain)
        float sc[8][4];
        #pragma unroll
        for (int j = 0; j < 8; j++)
            #pragma unroll
            for (int r = 0; r < 4; r++) sc[j][r] = 0.f;

        #pragma unroll
        for (int ks = 0; ks < 4; ks++) {
            uint32_t kf[4][4];
            #pragma unroll
            for (int nt = 0; nt < 4; nt++)
                ldmx4(kf[nt], stb + koff + (uint32_t)(nt * 16 * ROWB + ks * 32));
            #pragma unroll
            for (int nt = 0; nt < 4; nt++) {
                mma_f16(sc[2*nt    ], qf[ks], &kf[nt][0]);
                mma_f16(sc[2*nt + 1], qf[ks], &kf[nt][2]);
            }
        }

        float mx1 = -1e30f, mx2 = -1e30f;
        #pragma unroll
        for (int j = 0; j < 8; j++) {
            mx1 = fmaxf(mx1, fmaxf(sc[j][0], sc[j][1]));
            mx2 = fmaxf(mx2, fmaxf(sc[j][2], sc[j][3]));
        }
        mx1 = fmaxf(mx1, __shfl_xor_sync(0xffffffffu, mx1, 1));
        mx1 = fmaxf(mx1, __shfl_xor_sync(0xffffffffu, mx1, 2));
        mx2 = fmaxf(mx2, __shfl_xor_sync(0xffffffffu, mx2, 1));
        mx2 = fmaxf(mx2, __shfl_xor_sync(0xffffffffu, mx2, 2));

        float nm1 = fmaxf(m1, mx1), nm2 = fmaxf(m2, mx2);
        float a1 = ex2f(m1 - nm1), a2 = ex2f(m2 - nm2);
        uint32_t ph[8][2];
        #pragma unroll
        for (int j = 0; j < 8; j++) {
            float p0 = ex2f(sc[j][0] - nm1);
            float p1 = ex2f(sc[j][1] - nm1);
            float p2 = ex2f(sc[j][2] - nm2);
            float p3 = ex2f(sc[j][3] - nm2);
            ph[j][0] = h2pack(p0, p1);
            ph[j][1] = h2pack(p2, p3);
        }
        m1 = nm1;  m2 = nm2;
        #pragma unroll
        for (int j = 0; j < 8; j++) {
            oc[j][0] *= a1; oc[j][1] *= a1;
            oc[j][2] *= a2; oc[j][3] *= a2;
        }

        // Row sums of P on the tensor pipe: P @ ones  (c[0]=row sum gr, c[2]=gr+8)
        float sums[4] = {0.f, 0.f, 0.f, 0.f};
        #pragma unroll
        for (int ks = 0; ks < 4; ks++) {
            uint32_t pf[4] = { ph[2*ks][0], ph[2*ks][1], ph[2*ks+1][0], ph[2*ks+1][1] };
            mma_f16(sums, pf, ones);
        }
        l1 = l1 * a1 + sums[0];
        l2 = l2 * a2 + sums[2];

        // O += P @ V
        #pragma unroll
        for (int ks = 0; ks < 4; ks++) {
            uint32_t pf[4] = { ph[2*ks][0], ph[2*ks][1], ph[2*ks+1][0], ph[2*ks+1][1] };
            uint32_t vf[4][4];
            #pragma unroll
            for (int dt = 0; dt < 4; dt++)
                ldmx4t(vf[dt], stb + voff + (uint32_t)(ks * 16 * ROWB + dt * 32));
            #pragma unroll
            for (int dt = 0; dt < 4; dt++) {
                mma_f16(oc[2*dt    ], pf, &vf[dt][0]);
                mma_f16(oc[2*dt + 1], pf, &vf[dt][2]);
            }
        }
    }

    float il1 = 1.0f / l1, il2 = 1.0f / l2;
    int r1 = qb + 16 * warp + gr;
    uint32_t* o32 = (uint32_t*)outp;
    #pragma unroll
    for (int j = 0; j < 8; j++) {
        int cc = h * HDIM + (j >> 1) * 16 + (j & 1) * 8 + 2 * t4;
        size_t o0 = ((size_t)(b * SEQ + r1) * CDIM + cc) >> 1;
        size_t o1 = o0 + 4 * CDIM;
        o32[o0] = h2pack(oc[j][0] * il1, oc[j][1] * il1);
        o32[o1] = h2pack(oc[j][2] * il2, oc[j][3] * il2);
    }
}

// ---------------------------------------------------------------------------
// Launch
// ---------------------------------------------------------------------------
extern "C" void kernel_launch(void* const* d_in, const int* in_sizes, int n_in,
                              void* d_out, int out_size)
{
    const float* x      = (const float*)d_in[0];
    const float* ln1_g  = (const float*)d_in[1];
    const float* ln1_b  = (const float*)d_in[2];
    const float* qkv_w  = (const float*)d_in[3];
    const float* qkv_b  = (const float*)d_in[4];
    const float* proj_w = (const float*)d_in[5];
    const float* proj_b = (const float*)d_in[6];
    const float* ln2_g  = (const float*)d_in[7];
    const float* ln2_b  = (const float*)d_in[8];
    const float* fc1_w  = (const float*)d_in[9];
    const float* fc1_b  = (const float*)d_in[10];
    const float* fc2_w  = (const float*)d_in[11];
    const float* fc2_b  = (const float*)d_in[12];
    float* out = (float*)d_out;

    __half *p_xn1, *p_qkv, *p_attn, *p_hn, *p_h1;
    __half *p_wq, *p_wp, *p_w1, *p_w2;
    float  *p_x2;
    cudaGetSymbolAddress((void**)&p_xn1,  g_xn1);
    cudaGetSymbolAddress((void**)&p_qkv,  g_qkv);
    cudaGetSymbolAddress((void**)&p_attn, g_attn);
    cudaGetSymbolAddress((void**)&p_x2,   g_x2);
    cudaGetSymbolAddress((void**)&p_hn,   g_hn);
    cudaGetSymbolAddress((void**)&p_h1,   g_h1);
    cudaGetSymbolAddress((void**)&p_wq,   g_wq);
    cudaGetSymbolAddress((void**)&p_wp,   g_wp);
    cudaGetSymbolAddress((void**)&p_w1,   g_w1);
    cudaGetSymbolAddress((void**)&p_w2,   g_w2);

    cudaFuncSetAttribute(attn_h2,
                         cudaFuncAttributeMaxDynamicSharedMemorySize, ATTN_SMEM);
    cudaFuncSetAttribute((hgemm<false,false,true,true>),
                         cudaFuncAttributeMaxDynamicSharedMemorySize, GEMM_SMEM_BYTES);
    cudaFuncSetAttribute((hgemm<false,true,false,false>),
                         cudaFuncAttributeMaxDynamicSharedMemorySize, GEMM_SMEM_BYTES);
    cudaFuncSetAttribute((hgemm<true,false,true,false>),
                         cudaFuncAttributeMaxDynamicSharedMemorySize, GEMM_SMEM_BYTES);

    // 0) Weight prep (fused)
    wprep_all<<<WPREP_TILES, 256>>>(qkv_w, proj_w, fc1_w, fc2_w,
                                    p_wq, p_wp, p_w1, p_w2);

    // 1) LN1
    ln_kernel<<<TOKENS/8, 256>>>(x, ln1_g, ln1_b, p_xn1);

    // 2) qkv = xn1 @ qkv_w + qkv_b  (half out, q pre-scaled)
    hgemm<false,false,true,true><<<dim3(C3/128, TOKENS/128), 128, GEMM_SMEM_BYTES>>>(
        p_xn1, p_wq, qkv_b, nullptr, p_qkv, TOKENS, C3, CDIM);

    // 3) attention (half out)
    attn_h2<<<dim3(SEQ/128, BATCH*NHEADS), 256, ATTN_SMEM>>>(p_qkv, p_attn);

    // 4) x2 = x + attn @ proj_w + proj_b  (fp32 out)
    hgemm<false,true,false,false><<<dim3(CDIM/128, TOKENS/128), 128, GEMM_SMEM_BYTES>>>(
        p_attn, p_wp, proj_b, x, p_x2, TOKENS, CDIM, CDIM);

    // 5) LN2
    ln_kernel<<<TOKENS/8, 256>>>(p_x2, ln2_g, ln2_b, p_hn);

    // 6) h1 = gelu(hn @ fc1_w + fc1_b)  (half out)
    hgemm<true,false,true,false><<<dim3(HID/128, TOKENS/128), 128, GEMM_SMEM_BYTES>>>(
        p_hn, p_w1, fc1_b, nullptr, p_h1, TOKENS, HID, CDIM);

    // 7) out = x2 + h1 @ fc2_w + fc2_b  (fp32 out)
    hgemm<false,true,false,false><<<dim3(CDIM/128, TOKENS/128), 128, GEMM_SMEM_BYTES>>>(
        p_h1, p_w2, fc2_b, p_x2, out, TOKENS, CDIM, HID);
}

// round 12
// speedup vs baseline: 1.3107x; 1.0174x over previous
#include <cuda_runtime.h>
#include <cuda_fp16.h>
#include <math.h>
#include <stdint.h>

// Problem constants
#define BATCH   16
#define SEQ     1024
#define TOKENS  (BATCH*SEQ)     // 16384
#define CDIM    768
#define C3      (3*CDIM)        // 2304
#define HID     3072
#define NHEADS  12
#define HDIM    64
#define LN_EPS  1e-5f

// ---------------------------------------------------------------------------
// Scratch (device globals; allocation APIs are forbidden)
// ---------------------------------------------------------------------------
__device__ __half g_xn1 [ (size_t)TOKENS * CDIM ];
__device__ __half g_qkv [ (size_t)TOKENS * C3   ];
__device__ __half g_attn[ (size_t)TOKENS * CDIM ];
__device__ float  g_x2  [ (size_t)TOKENS * CDIM ];
__device__ __half g_hn  [ (size_t)TOKENS * CDIM ];
__device__ __half g_h1  [ (size_t)TOKENS * HID  ];
// fp16, TRANSPOSED weights: wT[n][k]
__device__ __half g_wq  [ (size_t)C3   * CDIM ];
__device__ __half g_wp  [ (size_t)CDIM * CDIM ];
__device__ __half g_w1  [ (size_t)HID  * CDIM ];
__device__ __half g_w2  [ (size_t)CDIM * HID  ];

// softmax scale * log2(e), folded into q at qkv-GEMM epilogue
#define QSCALE 0.18033688011112042f
#define HONES  0x3C003C00u          // half2(1.0, 1.0)

// ---------------------------------------------------------------------------
// Helpers
// ---------------------------------------------------------------------------
__device__ __forceinline__ float ex2f(float x) {
    float y;
    asm("ex2.approx.f32 %0, %1;" : "=f"(y) : "f"(x));
    return y;
}
__device__ __forceinline__ uint32_t ex2h2(uint32_t x) {
    uint32_t y;
    asm("ex2.approx.f16x2 %0, %1;" : "=r"(y) : "r"(x));
    return y;
}
__device__ __forceinline__ uint32_t hmax2(uint32_t a, uint32_t b) {
    uint32_t y;
    asm("max.f16x2 %0, %1, %2;" : "=r"(y) : "r"(a), "r"(b));
    return y;
}
__device__ __forceinline__ uint32_t hsub2(uint32_t a, uint32_t b) {
    uint32_t y;
    asm("sub.f16x2 %0, %1, %2;" : "=r"(y) : "r"(a), "r"(b));
    return y;
}
__device__ __forceinline__ void mma_f16(float* c, const uint32_t* a, const uint32_t* b) {
    asm volatile(
        "mma.sync.aligned.m16n8k16.row.col.f32.f16.f16.f32 "
        "{%0,%1,%2,%3}, {%4,%5,%6,%7}, {%8,%9}, {%0,%1,%2,%3};"
        : "+f"(c[0]), "+f"(c[1]), "+f"(c[2]), "+f"(c[3])
        : "r"(a[0]), "r"(a[1]), "r"(a[2]), "r"(a[3]), "r"(b[0]), "r"(b[1]));
}
// fp16-accumulate variant: C/D are 2x half2 regs
__device__ __forceinline__ void mma_f16h(uint32_t* c, const uint32_t* a, const uint32_t* b) {
    asm volatile(
        "mma.sync.aligned.m16n8k16.row.col.f16.f16.f16.f16 "
        "{%0,%1}, {%2,%3,%4,%5}, {%6,%7}, {%0,%1};"
        : "+r"(c[0]), "+r"(c[1])
        : "r"(a[0]), "r"(a[1]), "r"(a[2]), "r"(a[3]), "r"(b[0]), "r"(b[1]));
}
__device__ __forceinline__ void cpasync16(void* smem_ptr, const void* gmem_ptr) {
    uint32_t s = (uint32_t)__cvta_generic_to_shared(smem_ptr);
    asm volatile("cp.async.cg.shared.global [%0], [%1], 16;" :: "r"(s), "l"(gmem_ptr));
}
__device__ __forceinline__ void cpasync16s(uint32_t saddr, const void* gmem_ptr) {
    asm volatile("cp.async.cg.shared.global [%0], [%1], 16;" :: "r"(saddr), "l"(gmem_ptr));
}
__device__ __forceinline__ void ldmx4(uint32_t* r, uint32_t saddr) {
    asm volatile("ldmatrix.sync.aligned.m8n8.x4.shared.b16 {%0,%1,%2,%3}, [%4];"
                 : "=r"(r[0]), "=r"(r[1]), "=r"(r[2]), "=r"(r[3]) : "r"(saddr));
}
__device__ __forceinline__ void ldmx4t(uint32_t* r, uint32_t saddr) {
    asm volatile("ldmatrix.sync.aligned.m8n8.x4.trans.shared.b16 {%0,%1,%2,%3}, [%4];"
                 : "=r"(r[0]), "=r"(r[1]), "=r"(r[2]), "=r"(r[3]) : "r"(saddr));
}
__device__ __forceinline__ uint32_t h2pack(float lo, float hi) {
    __half2 h = __floats2half2_rn(lo, hi);
    return *reinterpret_cast<uint32_t*>(&h);
}

// ---------------------------------------------------------------------------
// Fused weight prep: all four weights, transpose + fp16 in one launch.
// ---------------------------------------------------------------------------
#define WQ_TILES (72*24)
#define WP_TILES (24*24)
#define W1_TILES (96*24)
#define W2_TILES (24*96)
#define WPREP_TILES (WQ_TILES + WP_TILES + W1_TILES + W2_TILES)

__global__ __launch_bounds__(256)
void wprep_all(const float* __restrict__ qkv_w, const float* __restrict__ proj_w,
               const float* __restrict__ fc1_w, const float* __restrict__ fc2_w,
               __half* __restrict__ wq, __half* __restrict__ wp,
               __half* __restrict__ w1, __half* __restrict__ w2)
{
    int t = blockIdx.x;
    const float* in; __half* out; int K, N, nt;
    if (t < WQ_TILES)                      { in = qkv_w;  out = wq; K = CDIM; N = C3;   nt = t; }
    else if (t < WQ_TILES + WP_TILES)      { in = proj_w; out = wp; K = CDIM; N = CDIM; nt = t - WQ_TILES; }
    else if (t < WQ_TILES + WP_TILES + W1_TILES)
                                           { in = fc1_w;  out = w1; K = CDIM; N = HID;  nt = t - WQ_TILES - WP_TILES; }
    else                                   { in = fc2_w;  out = w2; K = HID;  N = CDIM; nt = t - WQ_TILES - WP_TILES - W1_TILES; }

    int ntx = N / 32;
    int n0 = (nt % ntx) * 32;
    int k0 = (nt / ntx) * 32;

    __shared__ float tt[32][33];
    int tx = threadIdx.x & 31, ty = threadIdx.x >> 5;
    #pragma unroll
    for (int j = 0; j < 4; j++) {
        int kk = j * 8 + ty;
        tt[kk][tx] = in[(size_t)(k0 + kk) * N + n0 + tx];
    }
    __syncthreads();
    #pragma unroll
    for (int j = 0; j < 4; j++) {
        int nn = j * 8 + ty;
        out[(size_t)(n0 + nn) * K + k0 + tx] = __float2half_rn(tt[tx][nn]);
    }
}

// ---------------------------------------------------------------------------
// LayerNorm: warp-per-row, 8 rows per 256-thread block. Pure shfl.
// ---------------------------------------------------------------------------
__global__ __launch_bounds__(256)
void ln_kernel(const float* __restrict__ x, const float* __restrict__ gam,
               const float* __restrict__ bet, __half* __restrict__ out)
{
    int lane = threadIdx.x & 31;
    int w    = threadIdx.x >> 5;
    int row  = blockIdx.x * 8 + w;

    const float4* xr = (const float4*)(x + (size_t)row * CDIM);
    float4 v[6];
    #pragma unroll
    for (int i = 0; i < 6; i++) v[i] = xr[lane + 32 * i];

    float s = 0.f;
    #pragma unroll
    for (int i = 0; i < 6; i++) s += v[i].x + v[i].y + v[i].z + v[i].w;
    #pragma unroll
    for (int off = 16; off > 0; off >>= 1) s += __shfl_xor_sync(0xffffffffu, s, off);
    float mu = s * (1.0f / CDIM);

    float q = 0.f;
    #pragma unroll
    for (int i = 0; i < 6; i++) {
        v[i].x -= mu; v[i].y -= mu; v[i].z -= mu; v[i].w -= mu;
        q += v[i].x*v[i].x + v[i].y*v[i].y + v[i].z*v[i].z + v[i].w*v[i].w;
    }
    #pragma unroll
    for (int off = 16; off > 0; off >>= 1) q += __shfl_xor_sync(0xffffffffu, q, off);
    float rs = rsqrtf(q * (1.0f / CDIM) + LN_EPS);

    uint2* orow = (uint2*)(out + (size_t)row * CDIM);
    #pragma unroll
    for (int i = 0; i < 6; i++) {
        float4 g  = ((const float4*)gam)[lane + 32 * i];
        float4 be = ((const float4*)bet)[lane + 32 * i];
        uint2 o;
        o.x = h2pack(v[i].x * rs * g.x + be.x, v[i].y * rs * g.y + be.y);
        o.y = h2pack(v[i].z * rs * g.z + be.z, v[i].w * rs * g.w + be.w);
        orow[lane + 32 * i] = o;
    }
}

// ---------------------------------------------------------------------------
// FP16 tensor-core GEMM: 128x128x64 CTA tile, 128 threads (4 warps),
// warp tile 64x64, XOR-swizzled smem, ldmatrix, 2-stage cp.async, 3 CTAs/SM.
// ---------------------------------------------------------------------------
#define BK 64
#define STGB 32768
#define GEMM_SMEM_BYTES (2 * STGB)  // 65536

template<bool DO_GELU, bool DO_RESID, bool OUT_HALF, bool DO_QSCALE>
__global__ __launch_bounds__(128, 3)
void hgemm(const __half* __restrict__ A, const __half* __restrict__ Bt,
           const float* __restrict__ bias, const float* __restrict__ resid,
           void* __restrict__ Cv, int M, int N, int K)
{
    extern __shared__ __align__(16) char smb[];
    uint32_t sbase = (uint32_t)__cvta_generic_to_shared(smb);

    int tid  = threadIdx.x;
    int warp = tid >> 5;
    int lane = tid & 31;
    int gr   = lane >> 2;
    int t4   = lane & 3;
    int row0 = blockIdx.y * 128;
    int col0 = blockIdx.x * 128;
    int wm   = (warp >> 1) * 64;
    int wn   = (warp & 1) * 64;

    int arow = wm + (lane & 15);
    int ahi  = lane >> 4;
    int brow = wn + (lane & 7) + ((lane >> 4) << 3);
    int bhi  = (lane >> 3) & 1;
    uint32_t abase = (uint32_t)arow * 128;
    uint32_t bbase = 16384u + (uint32_t)brow * 128;
    int ax = arow & 7;
    int bx = brow & 7;

    float acc[4][8][4];
    #pragma unroll
    for (int i = 0; i < 4; i++)
        #pragma unroll
        for (int j = 0; j < 8; j++)
            #pragma unroll
            for (int r = 0; r < 4; r++) acc[i][j][r] = 0.f;

    int ldr = tid >> 3;
    int ldc = tid & 7;

    auto load_tiles = [&](int st, int kt) {
        int k0 = kt * BK;
        const __half* Ab = A  + (size_t)row0 * K + k0;
        const __half* Bb = Bt + (size_t)col0 * K + k0;
        uint32_t sa = sbase + (uint32_t)st * STGB;
        uint32_t sb = sa + 16384u;
        #pragma unroll
        for (int i = 0; i < 8; i++) {
            int r = ldr + i * 16;
            uint32_t sw = (uint32_t)r * 128 + ((uint32_t)(ldc ^ (r & 7)) << 4);
            cpasync16s(sa + sw, Ab + (size_t)r * K + ldc * 8);
            cpasync16s(sb + sw, Bb + (size_t)r * K + ldc * 8);
        }
        asm volatile("cp.async.commit_group;");
    };

    int KT = K / BK;
    load_tiles(0, 0);

    for (int kt = 0; kt < KT; kt++) {
        if (kt + 1 < KT) {
            load_tiles((kt + 1) & 1, kt + 1);
            asm volatile("cp.async.wait_group 1;" ::: "memory");
        } else {
            asm volatile("cp.async.wait_group 0;" ::: "memory");
        }
        __syncthreads();

        uint32_t stg = sbase + (uint32_t)((kt & 1) * STGB);
        #pragma unroll
        for (int ks = 0; ks < 4; ks++) {
            uint32_t af[4][4];
            #pragma unroll
            for (int mt = 0; mt < 4; mt++)
                ldmx4(af[mt], stg + abase + (uint32_t)(mt * 2048)
                                  + ((uint32_t)((2 * ks + ahi) ^ ax) << 4));
            #pragma unroll
            for (int nt = 0; nt < 4; nt++) {
                uint32_t bf[4];
                ldmx4(bf, stg + bbase + (uint32_t)(nt * 2048)
                              + ((uint32_t)((2 * ks + bhi) ^ bx) << 4));
                #pragma unroll
                for (int mt = 0; mt < 4; mt++) {
                    mma_f16(acc[mt][2*nt    ], af[mt], &bf[0]);
                    mma_f16(acc[mt][2*nt + 1], af[mt], &bf[2]);
                }
            }
        }
        __syncthreads();
    }

    // Epilogue
    #pragma unroll
    for (int i = 0; i < 4; i++) {
        int r0 = row0 + wm + i * 16 + gr;
        #pragma unroll
        for (int j = 0; j < 8; j++) {
            int cc = col0 + wn + j * 8 + 2 * t4;
            float2 bb = *(const float2*)&bias[cc];
            float v0 = acc[i][j][0] + bb.x;
            float v1 = acc[i][j][1] + bb.y;
            float v2 = acc[i][j][2] + bb.x;
            float v3 = acc[i][j][3] + bb.y;
            if (DO_GELU) {
                v0 = 0.5f * v0 * (1.0f + erff(v0 * 0.70710678118654752f));
                v1 = 0.5f * v1 * (1.0f + erff(v1 * 0.70710678118654752f));
                v2 = 0.5f * v2 * (1.0f + erff(v2 * 0.70710678118654752f));
                v3 = 0.5f * v3 * (1.0f + erff(v3 * 0.70710678118654752f));
            }
            if (DO_QSCALE && cc < CDIM) {
                v0 *= QSCALE; v1 *= QSCALE; v2 *= QSCALE; v3 *= QSCALE;
            }
            size_t o0 = (size_t)r0 * N + cc;
            size_t o1 = (size_t)(r0 + 8) * N + cc;
            if (DO_RESID) {
                float2 ra = *(const float2*)&resid[o0];
                float2 rb = *(const float2*)&resid[o1];
                v0 += ra.x; v1 += ra.y; v2 += rb.x; v3 += rb.y;
            }
            if (OUT_HALF) {
                uint32_t* C = (uint32_t*)Cv;
                C[o0 >> 1] = h2pack(v0, v1);
                C[o1 >> 1] = h2pack(v2, v3);
            } else {
                float* C = (float*)Cv;
                *(float2*)&C[o0] = make_float2(v0, v1);
                *(float2*)&C[o1] = make_float2(v2, v3);
            }
        }
    }
}

// ---------------------------------------------------------------------------
// FP16 flash attention: 128 queries x 1 head, 256 thr, 2 CTAs/SM.
// S accumulated in FP16 (C-frag half2 == PV A-frag words); softmax entirely
// in f16x2 (max.f16x2 / sub.f16x2 / ex2.approx.f16x2); row-sums via MMA.
// ---------------------------------------------------------------------------
#define ROWW 36
#define ROWB 144
#define ATQ_W 0
#define ATS_W 4608
#define ATTN_SMEM ((4608 + 2 * 4608) * 4)   // 55296 B

__global__ __launch_bounds__(256, 2)
void attn_h2(const __half* __restrict__ qkv, __half* __restrict__ outp)
{
    extern __shared__ __align__(16) uint32_t smq[];

    int tid  = threadIdx.x;
    int warp = tid >> 5;
    int lane = tid & 31;
    int gr   = lane >> 2;
    int t4   = lane & 3;
    int qb   = blockIdx.x * 128;
    int b    = blockIdx.y / NHEADS;
    int h    = blockIdx.y % NHEADS;
    const __half* base = qkv + (size_t)b * SEQ * C3 + h * HDIM;

    uint32_t sbase = (uint32_t)__cvta_generic_to_shared(smq);

    auto load_kv = [&](int st, int kt) {
        const __half* kb = base + (size_t)(kt * 64) * C3 + CDIM;
        uint32_t* sk = &smq[ATS_W * (1 + st)];
        uint32_t* sv = sk + 2304;
        #pragma unroll
        for (int i = 0; i < 2; i++) {
            int idx = tid + i * 256;
            int r = idx >> 3, c8 = idx & 7;
            cpasync16(&sk[r * ROWW + c8 * 4], kb + (size_t)r * C3 + c8 * 8);
            cpasync16(&sv[r * ROWW + c8 * 4], kb + (size_t)r * C3 + CDIM + c8 * 8);
        }
        asm volatile("cp.async.commit_group;");
    };

    load_kv(0, 0);

    #pragma unroll
    for (int i = 0; i < 4; i++) {
        int idx = tid + i * 256;
        int r = idx >> 3, c8 = idx & 7;
        uint4 v = *(const uint4*)(base + (size_t)(qb + r) * C3 + c8 * 8);
        *(uint4*)&smq[ATQ_W + r * ROWW + c8 * 4] = v;
    }
    __syncthreads();

    uint32_t qoff = (uint32_t)(16 * warp + (lane & 15)) * ROWB + (uint32_t)(lane >> 4) * 16;
    uint32_t qf[4][4];
    #pragma unroll
    for (int ks = 0; ks < 4; ks++)
        ldmx4(qf[ks], sbase + qoff + (uint32_t)(ks * 32));

    uint32_t koff = (uint32_t)((lane & 7) + ((lane >> 4) << 3)) * ROWB +
                    (uint32_t)((lane >> 3) & 1) * 16;
    uint32_t voff = 2304u * 4 + (uint32_t)(lane & 15) * ROWB + (uint32_t)(lane >> 4) * 16;

    const uint32_t ones[2] = { HONES, HONES };

    float m1 = -1e30f, m2 = -1e30f, l1 = 0.f, l2 = 0.f;
    float oc[8][4];
    #pragma unroll
    for (int j = 0; j < 8; j++)
        #pragma unroll
        for (int r = 0; r < 4; r++) oc[j][r] = 0.f;

    for (int kt = 0; kt < SEQ / 64; kt++) {
        asm volatile("cp.async.wait_group 0;" ::: "memory");
        __syncthreads();
        if (kt + 1 < SEQ / 64) load_kv((kt + 1) & 1, kt + 1);

        uint32_t stb = sbase + (uint32_t)(ATS_W * (1 + (kt & 1)) * 4);

        // S = Q @ K^T in fp16 accumulate. sc[j][0]=(row gr, cols 2t4..+1),
        // sc[j][1]=(row gr+8, same cols) — exactly the PV A-frag packing.
        uint32_t sc[8][2];
        #pragma unroll
        for (int j = 0; j < 8; j++) { sc[j][0] = 0u; sc[j][1] = 0u; }

        #pragma unroll
        for (int ks = 0; ks < 4; ks++) {
            uint32_t kf[4][4];
            #pragma unroll
            for (int nt = 0; nt < 4; nt++)
                ldmx4(kf[nt], stb + koff + (uint32_t)(nt * 16 * ROWB + ks * 32));
            #pragma unroll
            for (int nt = 0; nt < 4; nt++) {
                mma_f16h(sc[2*nt    ], qf[ks], &kf[nt][0]);
                mma_f16h(sc[2*nt + 1], qf[ks], &kf[nt][2]);
            }
        }

        // Row max in f16x2 (per row-group), then to f32 for m/l bookkeeping
        uint32_t mh1 = sc[0][0], mh2 = sc[0][1];
        #pragma unroll
        for (int j = 1; j < 8; j++) {
            mh1 = hmax2(mh1, sc[j][0]);
            mh2 = hmax2(mh2, sc[j][1]);
        }
        __half2 hv1 = *reinterpret_cast<__half2*>(&mh1);
        __half2 hv2 = *reinterpret_cast<__half2*>(&mh2);
        float mx1 = fmaxf(__half2float(__low2half(hv1)), __half2float(__high2half(hv1)));
        float mx2 = fmaxf(__half2float(__low2half(hv2)), __half2float(__high2half(hv2)));
        mx1 = fmaxf(mx1, __shfl_xor_sync(0xffffffffu, mx1, 1));
        mx1 = fmaxf(mx1, __shfl_xor_sync(0xffffffffu, mx1, 2));
        mx2 = fmaxf(mx2, __shfl_xor_sync(0xffffffffu, mx2, 1));
        mx2 = fmaxf(mx2, __shfl_xor_sync(0xffffffffu, mx2, 2));

        float nm1 = fmaxf(m1, mx1), nm2 = fmaxf(m2, mx2);
        float a1 = ex2f(m1 - nm1), a2 = ex2f(m2 - nm2);
        uint32_t nh1 = h2pack(nm1, nm1);
        uint32_t nh2 = h2pack(nm2, nm2);

        // P = 2^(S - m) entirely in f16x2; results ARE the PV A-frag words.
        uint32_t ph[8][2];
        #pragma unroll
        for (int j = 0; j < 8; j++) {
            ph[j][0] = ex2h2(hsub2(sc[j][0], nh1));
            ph[j][1] = ex2h2(hsub2(sc[j][1], nh2));
        }
        m1 = nm1;  m2 = nm2;
        #pragma unroll
        for (int j = 0; j < 8; j++) {
            oc[j][0] *= a1; oc[j][1] *= a1;
            oc[j][2] *= a2; oc[j][3] *= a2;
        }

        // Row sums of P on the tensor pipe: P @ ones
        float sums[4] = {0.f, 0.f, 0.f, 0.f};
        #pragma unroll
        for (int ks = 0; ks < 4; ks++) {
            uint32_t pf[4] = { ph[2*ks][0], ph[2*ks][1], ph[2*ks+1][0], ph[2*ks+1][1] };
            mma_f16(sums, pf, ones);
        }
        l1 = l1 * a1 + sums[0];
        l2 = l2 * a2 + sums[2];

        // O += P @ V
        #pragma unroll
        for (int ks = 0; ks < 4; ks++) {
            uint32_t pf[4] = { ph[2*ks][0], ph[2*ks][1], ph[2*ks+1][0], ph[2*ks+1][1] };
            uint32_t vf[4][4];
            #pragma unroll
            for (int dt = 0; dt < 4; dt++)
                ldmx4t(vf[dt], stb + voff + (uint32_t)(ks * 16 * ROWB + dt * 32));
            #pragma unroll
            for (int dt = 0; dt < 4; dt++) {
                mma_f16(oc[2*dt    ], pf, &vf[dt][0]);
                mma_f16(oc[2*dt + 1], pf, &vf[dt][2]);
            }
        }
    }

    float il1 = 1.0f / l1, il2 = 1.0f / l2;
    int r1 = qb + 16 * warp + gr;
    uint32_t* o32 = (uint32_t*)outp;
    #pragma unroll
    for (int j = 0; j < 8; j++) {
        int cc = h * HDIM + (j >> 1) * 16 + (j & 1) * 8 + 2 * t4;
        size_t o0 = ((size_t)(b * SEQ + r1) * CDIM + cc) >> 1;
        size_t o1 = o0 + 4 * CDIM;
        o32[o0] = h2pack(oc[j][0] * il1, oc[j][1] * il1);
        o32[o1] = h2pack(oc[j][2] * il2, oc[j][3] * il2);
    }
}

// ---------------------------------------------------------------------------
// Launch
// ---------------------------------------------------------------------------
extern "C" void kernel_launch(void* const* d_in, const int* in_sizes, int n_in,
                              void* d_out, int out_size)
{
    const float* x      = (const float*)d_in[0];
    const float* ln1_g  = (const float*)d_in[1];
    const float* ln1_b  = (const float*)d_in[2];
    const float* qkv_w  = (const float*)d_in[3];
    const float* qkv_b  = (const float*)d_in[4];
    const float* proj_w = (const float*)d_in[5];
    const float* proj_b = (const float*)d_in[6];
    const float* ln2_g  = (const float*)d_in[7];
    const float* ln2_b  = (const float*)d_in[8];
    const float* fc1_w  = (const float*)d_in[9];
    const float* fc1_b  = (const float*)d_in[10];
    const float* fc2_w  = (const float*)d_in[11];
    const float* fc2_b  = (const float*)d_in[12];
    float* out = (float*)d_out;

    __half *p_xn1, *p_qkv, *p_attn, *p_hn, *p_h1;
    __half *p_wq, *p_wp, *p_w1, *p_w2;
    float  *p_x2;
    cudaGetSymbolAddress((void**)&p_xn1,  g_xn1);
    cudaGetSymbolAddress((void**)&p_qkv,  g_qkv);
    cudaGetSymbolAddress((void**)&p_attn, g_attn);
    cudaGetSymbolAddress((void**)&p_x2,   g_x2);
    cudaGetSymbolAddress((void**)&p_hn,   g_hn);
    cudaGetSymbolAddress((void**)&p_h1,   g_h1);
    cudaGetSymbolAddress((void**)&p_wq,   g_wq);
    cudaGetSymbolAddress((void**)&p_wp,   g_wp);
    cudaGetSymbolAddress((void**)&p_w1,   g_w1);
    cudaGetSymbolAddress((void**)&p_w2,   g_w2);

    cudaFuncSetAttribute(attn_h2,
                         cudaFuncAttributeMaxDynamicSharedMemorySize, ATTN_SMEM);
    cudaFuncSetAttribute((hgemm<false,false,true,true>),
                         cudaFuncAttributeMaxDynamicSharedMemorySize, GEMM_SMEM_BYTES);
    cudaFuncSetAttribute((hgemm<false,true,false,false>),
                         cudaFuncAttributeMaxDynamicSharedMemorySize, GEMM_SMEM_BYTES);
    cudaFuncSetAttribute((hgemm<true,false,true,false>),
                         cudaFuncAttributeMaxDynamicSharedMemorySize, GEMM_SMEM_BYTES);

    // 0) Weight prep (fused)
    wprep_all<<<WPREP_TILES, 256>>>(qkv_w, proj_w, fc1_w, fc2_w,
                                    p_wq, p_wp, p_w1, p_w2);

    // 1) LN1
    ln_kernel<<<TOKENS/8, 256>>>(x, ln1_g, ln1_b, p_xn1);

    // 2) qkv = xn1 @ qkv_w + qkv_b  (half out, q pre-scaled)
    hgemm<false,false,true,true><<<dim3(C3/128, TOKENS/128), 128, GEMM_SMEM_BYTES>>>(
        p_xn1, p_wq, qkv_b, nullptr, p_qkv, TOKENS, C3, CDIM);

    // 3) attention (half out)
    attn_h2<<<dim3(SEQ/128, BATCH*NHEADS), 256, ATTN_SMEM>>>(p_qkv, p_attn);

    // 4) x2 = x + attn @ proj_w + proj_b  (fp32 out)
    hgemm<false,true,false,false><<<dim3(CDIM/128, TOKENS/128), 128, GEMM_SMEM_BYTES>>>(
        p_attn, p_wp, proj_b, x, p_x2, TOKENS, CDIM, CDIM);

    // 5) LN2
    ln_kernel<<<TOKENS/8, 256>>>(p_x2, ln2_g, ln2_b, p_hn);

    // 6) h1 = gelu(hn @ fc1_w + fc1_b)  (half out)
    hgemm<true,false,true,false><<<dim3(HID/128, TOKENS/128), 128, GEMM_SMEM_BYTES>>>(
        p_hn, p_w1, fc1_b, nullptr, p_h1, TOKENS, HID, CDIM);

    // 7) out = x2 + h1 @ fc2_w + fc2_b  (fp32 out)
    hgemm<false,true,false,false><<<dim3(CDIM/128, TOKENS/128), 128, GEMM_SMEM_BYTES>>>(
        p_h1, p_w2, fc2_b, p_x2, out, TOKENS, CDIM, HID);
}

// round 13
// speedup vs baseline: 1.3468x; 1.0275x over previous
#include <cuda_runtime.h>
#include <cuda_fp16.h>
#include <math.h>
#include <stdint.h>

// Problem constants
#define BATCH   16
#define SEQ     1024
#define TOKENS  (BATCH*SEQ)     // 16384
#define CDIM    768
#define C3      (3*CDIM)        // 2304
#define HID     3072
#define NHEADS  12
#define HDIM    64
#define LN_EPS  1e-5f

// ---------------------------------------------------------------------------
// Scratch (device globals; allocation APIs are forbidden)
// ---------------------------------------------------------------------------
__device__ __half g_xn1 [ (size_t)TOKENS * CDIM ];
__device__ __half g_qkv [ (size_t)TOKENS * C3   ];
__device__ __half g_attn[ (size_t)TOKENS * CDIM ];
__device__ float  g_x2  [ (size_t)TOKENS * CDIM ];
__device__ __half g_hn  [ (size_t)TOKENS * CDIM ];
__device__ __half g_h1  [ (size_t)TOKENS * HID  ];
// fp16, TRANSPOSED weights: wT[n][k]
__device__ __half g_wq  [ (size_t)C3   * CDIM ];
__device__ __half g_wp  [ (size_t)CDIM * CDIM ];
__device__ __half g_w1  [ (size_t)HID  * CDIM ];
__device__ __half g_w2  [ (size_t)CDIM * HID  ];

// softmax scale * log2(e), folded into q at qkv-GEMM epilogue
#define QSCALE 0.18033688011112042f
#define HONES  0x3C003C00u          // half2(1.0, 1.0)

// ---------------------------------------------------------------------------
// Helpers
// ---------------------------------------------------------------------------
__device__ __forceinline__ float ex2f(float x) {
    float y;
    asm("ex2.approx.f32 %0, %1;" : "=f"(y) : "f"(x));
    return y;
}
__device__ __forceinline__ float tanhaf(float x) {
    float y;
    asm("tanh.approx.f32 %0, %1;" : "=f"(y) : "f"(x));
    return y;
}
// Fast GELU: tanh form with HW tanh.approx (max abs dev from exact ~3e-4)
__device__ __forceinline__ float gelu_fast(float x) {
    float inner = x * fmaf(0.0356774081f, x * x, 0.7978845608f);
    return 0.5f * x * (1.0f + tanhaf(inner));
}
__device__ __forceinline__ uint32_t ex2h2(uint32_t x) {
    uint32_t y;
    asm("ex2.approx.f16x2 %0, %1;" : "=r"(y) : "r"(x));
    return y;
}
__device__ __forceinline__ uint32_t hmax2(uint32_t a, uint32_t b) {
    uint32_t y;
    asm("max.f16x2 %0, %1, %2;" : "=r"(y) : "r"(a), "r"(b));
    return y;
}
__device__ __forceinline__ uint32_t hsub2(uint32_t a, uint32_t b) {
    uint32_t y;
    asm("sub.f16x2 %0, %1, %2;" : "=r"(y) : "r"(a), "r"(b));
    return y;
}
__device__ __forceinline__ void mma_f16(float* c, const uint32_t* a, const uint32_t* b) {
    asm volatile(
        "mma.sync.aligned.m16n8k16.row.col.f32.f16.f16.f32 "
        "{%0,%1,%2,%3}, {%4,%5,%6,%7}, {%8,%9}, {%0,%1,%2,%3};"
        : "+f"(c[0]), "+f"(c[1]), "+f"(c[2]), "+f"(c[3])
        : "r"(a[0]), "r"(a[1]), "r"(a[2]), "r"(a[3]), "r"(b[0]), "r"(b[1]));
}
// fp16-accumulate variant: C/D are 2x half2 regs
__device__ __forceinline__ void mma_f16h(uint32_t* c, const uint32_t* a, const uint32_t* b) {
    asm volatile(
        "mma.sync.aligned.m16n8k16.row.col.f16.f16.f16.f16 "
        "{%0,%1}, {%2,%3,%4,%5}, {%6,%7}, {%0,%1};"
        : "+r"(c[0]), "+r"(c[1])
        : "r"(a[0]), "r"(a[1]), "r"(a[2]), "r"(a[3]), "r"(b[0]), "r"(b[1]));
}
__device__ __forceinline__ void cpasync16(void* smem_ptr, const void* gmem_ptr) {
    uint32_t s = (uint32_t)__cvta_generic_to_shared(smem_ptr);
    asm volatile("cp.async.cg.shared.global [%0], [%1], 16;" :: "r"(s), "l"(gmem_ptr));
}
__device__ __forceinline__ void cpasync16s(uint32_t saddr, const void* gmem_ptr) {
    asm volatile("cp.async.cg.shared.global [%0], [%1], 16;" :: "r"(saddr), "l"(gmem_ptr));
}
__device__ __forceinline__ void ldmx4(uint32_t* r, uint32_t saddr) {
    asm volatile("ldmatrix.sync.aligned.m8n8.x4.shared.b16 {%0,%1,%2,%3}, [%4];"
                 : "=r"(r[0]), "=r"(r[1]), "=r"(r[2]), "=r"(r[3]) : "r"(saddr));
}
__device__ __forceinline__ void ldmx4t(uint32_t* r, uint32_t saddr) {
    asm volatile("ldmatrix.sync.aligned.m8n8.x4.trans.shared.b16 {%0,%1,%2,%3}, [%4];"
                 : "=r"(r[0]), "=r"(r[1]), "=r"(r[2]), "=r"(r[3]) : "r"(saddr));
}
__device__ __forceinline__ uint32_t h2pack(float lo, float hi) {
    __half2 h = __floats2half2_rn(lo, hi);
    return *reinterpret_cast<uint32_t*>(&h);
}

// ---------------------------------------------------------------------------
// Fused weight prep: all four weights, transpose + fp16 in one launch.
// ---------------------------------------------------------------------------
#define WQ_TILES (72*24)
#define WP_TILES (24*24)
#define W1_TILES (96*24)
#define W2_TILES (24*96)
#define WPREP_TILES (WQ_TILES + WP_TILES + W1_TILES + W2_TILES)

__global__ __launch_bounds__(256)
void wprep_all(const float* __restrict__ qkv_w, const float* __restrict__ proj_w,
               const float* __restrict__ fc1_w, const float* __restrict__ fc2_w,
               __half* __restrict__ wq, __half* __restrict__ wp,
               __half* __restrict__ w1, __half* __restrict__ w2)
{
    int t = blockIdx.x;
    const float* in; __half* out; int K, N, nt;
    if (t < WQ_TILES)                      { in = qkv_w;  out = wq; K = CDIM; N = C3;   nt = t; }
    else if (t < WQ_TILES + WP_TILES)      { in = proj_w; out = wp; K = CDIM; N = CDIM; nt = t - WQ_TILES; }
    else if (t < WQ_TILES + WP_TILES + W1_TILES)
                                           { in = fc1_w;  out = w1; K = CDIM; N = HID;  nt = t - WQ_TILES - WP_TILES; }
    else                                   { in = fc2_w;  out = w2; K = HID;  N = CDIM; nt = t - WQ_TILES - WP_TILES - W1_TILES; }

    int ntx = N / 32;
    int n0 = (nt % ntx) * 32;
    int k0 = (nt / ntx) * 32;

    __shared__ float tt[32][33];
    int tx = threadIdx.x & 31, ty = threadIdx.x >> 5;
    #pragma unroll
    for (int j = 0; j < 4; j++) {
        int kk = j * 8 + ty;
        tt[kk][tx] = in[(size_t)(k0 + kk) * N + n0 + tx];
    }
    __syncthreads();
    #pragma unroll
    for (int j = 0; j < 4; j++) {
        int nn = j * 8 + ty;
        out[(size_t)(n0 + nn) * K + k0 + tx] = __float2half_rn(tt[tx][nn]);
    }
}

// ---------------------------------------------------------------------------
// LayerNorm: warp-per-row, 8 rows per 256-thread block. Pure shfl.
// ---------------------------------------------------------------------------
__global__ __launch_bounds__(256)
void ln_kernel(const float* __restrict__ x, const float* __restrict__ gam,
               const float* __restrict__ bet, __half* __restrict__ out)
{
    int lane = threadIdx.x & 31;
    int w    = threadIdx.x >> 5;
    int row  = blockIdx.x * 8 + w;

    const float4* xr = (const float4*)(x + (size_t)row * CDIM);
    float4 v[6];
    #pragma unroll
    for (int i = 0; i < 6; i++) v[i] = xr[lane + 32 * i];

    float s = 0.f;
    #pragma unroll
    for (int i = 0; i < 6; i++) s += v[i].x + v[i].y + v[i].z + v[i].w;
    #pragma unroll
    for (int off = 16; off > 0; off >>= 1) s += __shfl_xor_sync(0xffffffffu, s, off);
    float mu = s * (1.0f / CDIM);

    float q = 0.f;
    #pragma unroll
    for (int i = 0; i < 6; i++) {
        v[i].x -= mu; v[i].y -= mu; v[i].z -= mu; v[i].w -= mu;
        q += v[i].x*v[i].x + v[i].y*v[i].y + v[i].z*v[i].z + v[i].w*v[i].w;
    }
    #pragma unroll
    for (int off = 16; off > 0; off >>= 1) q += __shfl_xor_sync(0xffffffffu, q, off);
    float rs = rsqrtf(q * (1.0f / CDIM) + LN_EPS);

    uint2* orow = (uint2*)(out + (size_t)row * CDIM);
    #pragma unroll
    for (int i = 0; i < 6; i++) {
        float4 g  = ((const float4*)gam)[lane + 32 * i];
        float4 be = ((const float4*)bet)[lane + 32 * i];
        uint2 o;
        o.x = h2pack(v[i].x * rs * g.x + be.x, v[i].y * rs * g.y + be.y);
        o.y = h2pack(v[i].z * rs * g.z + be.z, v[i].w * rs * g.w + be.w);
        orow[lane + 32 * i] = o;
    }
}

// ---------------------------------------------------------------------------
// FP16 tensor-core GEMM: 128x128x64 CTA tile, 128 threads (4 warps),
// warp tile 64x64, XOR-swizzled smem, ldmatrix, 2-stage cp.async, 3 CTAs/SM.
// ---------------------------------------------------------------------------
#define BK 64
#define STGB 32768
#define GEMM_SMEM_BYTES (2 * STGB)  // 65536

template<bool DO_GELU, bool DO_RESID, bool OUT_HALF, bool DO_QSCALE>
__global__ __launch_bounds__(128, 3)
void hgemm(const __half* __restrict__ A, const __half* __restrict__ Bt,
           const float* __restrict__ bias, const float* __restrict__ resid,
           void* __restrict__ Cv, int M, int N, int K)
{
    extern __shared__ __align__(16) char smb[];
    uint32_t sbase = (uint32_t)__cvta_generic_to_shared(smb);

    int tid  = threadIdx.x;
    int warp = tid >> 5;
    int lane = tid & 31;
    int gr   = lane >> 2;
    int t4   = lane & 3;
    int row0 = blockIdx.y * 128;
    int col0 = blockIdx.x * 128;
    int wm   = (warp >> 1) * 64;
    int wn   = (warp & 1) * 64;

    int arow = wm + (lane & 15);
    int ahi  = lane >> 4;
    int brow = wn + (lane & 7) + ((lane >> 4) << 3);
    int bhi  = (lane >> 3) & 1;
    uint32_t abase = (uint32_t)arow * 128;
    uint32_t bbase = 16384u + (uint32_t)brow * 128;
    int ax = arow & 7;
    int bx = brow & 7;

    float acc[4][8][4];
    #pragma unroll
    for (int i = 0; i < 4; i++)
        #pragma unroll
        for (int j = 0; j < 8; j++)
            #pragma unroll
            for (int r = 0; r < 4; r++) acc[i][j][r] = 0.f;

    int ldr = tid >> 3;
    int ldc = tid & 7;

    auto load_tiles = [&](int st, int kt) {
        int k0 = kt * BK;
        const __half* Ab = A  + (size_t)row0 * K + k0;
        const __half* Bb = Bt + (size_t)col0 * K + k0;
        uint32_t sa = sbase + (uint32_t)st * STGB;
        uint32_t sb = sa + 16384u;
        #pragma unroll
        for (int i = 0; i < 8; i++) {
            int r = ldr + i * 16;
            uint32_t sw = (uint32_t)r * 128 + ((uint32_t)(ldc ^ (r & 7)) << 4);
            cpasync16s(sa + sw, Ab + (size_t)r * K + ldc * 8);
            cpasync16s(sb + sw, Bb + (size_t)r * K + ldc * 8);
        }
        asm volatile("cp.async.commit_group;");
    };

    int KT = K / BK;
    load_tiles(0, 0);

    for (int kt = 0; kt < KT; kt++) {
        if (kt + 1 < KT) {
            load_tiles((kt + 1) & 1, kt + 1);
            asm volatile("cp.async.wait_group 1;" ::: "memory");
        } else {
            asm volatile("cp.async.wait_group 0;" ::: "memory");
        }
        __syncthreads();

        uint32_t stg = sbase + (uint32_t)((kt & 1) * STGB);
        #pragma unroll
        for (int ks = 0; ks < 4; ks++) {
            uint32_t af[4][4];
            #pragma unroll
            for (int mt = 0; mt < 4; mt++)
                ldmx4(af[mt], stg + abase + (uint32_t)(mt * 2048)
                                  + ((uint32_t)((2 * ks + ahi) ^ ax) << 4));
            #pragma unroll
            for (int nt = 0; nt < 4; nt++) {
                uint32_t bf[4];
                ldmx4(bf, stg + bbase + (uint32_t)(nt * 2048)
                              + ((uint32_t)((2 * ks + bhi) ^ bx) << 4));
                #pragma unroll
                for (int mt = 0; mt < 4; mt++) {
                    mma_f16(acc[mt][2*nt    ], af[mt], &bf[0]);
                    mma_f16(acc[mt][2*nt + 1], af[mt], &bf[2]);
                }
            }
        }
        __syncthreads();
    }

    // Epilogue
    #pragma unroll
    for (int i = 0; i < 4; i++) {
        int r0 = row0 + wm + i * 16 + gr;
        #pragma unroll
        for (int j = 0; j < 8; j++) {
            int cc = col0 + wn + j * 8 + 2 * t4;
            float2 bb = *(const float2*)&bias[cc];
            float v0 = acc[i][j][0] + bb.x;
            float v1 = acc[i][j][1] + bb.y;
            float v2 = acc[i][j][2] + bb.x;
            float v3 = acc[i][j][3] + bb.y;
            if (DO_GELU) {
                v0 = gelu_fast(v0);
                v1 = gelu_fast(v1);
                v2 = gelu_fast(v2);
                v3 = gelu_fast(v3);
            }
            if (DO_QSCALE && cc < CDIM) {
                v0 *= QSCALE; v1 *= QSCALE; v2 *= QSCALE; v3 *= QSCALE;
            }
            size_t o0 = (size_t)r0 * N + cc;
            size_t o1 = (size_t)(r0 + 8) * N + cc;
            if (DO_RESID) {
                float2 ra = *(const float2*)&resid[o0];
                float2 rb = *(const float2*)&resid[o1];
                v0 += ra.x; v1 += ra.y; v2 += rb.x; v3 += rb.y;
            }
            if (OUT_HALF) {
                uint32_t* C = (uint32_t*)Cv;
                C[o0 >> 1] = h2pack(v0, v1);
                C[o1 >> 1] = h2pack(v2, v3);
            } else {
                float* C = (float*)Cv;
                *(float2*)&C[o0] = make_float2(v0, v1);
                *(float2*)&C[o1] = make_float2(v2, v3);
            }
        }
    }
}

// ---------------------------------------------------------------------------
// FP16 flash attention: 128 queries x 1 head, 256 thr, 2 CTAs/SM.
// S accumulated in FP16; softmax entirely in f16x2; row-sums via MMA.
// ---------------------------------------------------------------------------
#define ROWW 36
#define ROWB 144
#define ATQ_W 0
#define ATS_W 4608
#define ATTN_SMEM ((4608 + 2 * 4608) * 4)   // 55296 B

__global__ __launch_bounds__(256, 2)
void attn_h2(const __half* __restrict__ qkv, __half* __restrict__ outp)
{
    extern __shared__ __align__(16) uint32_t smq[];

    int tid  = threadIdx.x;
    int warp = tid >> 5;
    int lane = tid & 31;
    int gr   = lane >> 2;
    int t4   = lane & 3;
    int qb   = blockIdx.x * 128;
    int b    = blockIdx.y / NHEADS;
    int h    = blockIdx.y % NHEADS;
    const __half* base = qkv + (size_t)b * SEQ * C3 + h * HDIM;

    uint32_t sbase = (uint32_t)__cvta_generic_to_shared(smq);

    auto load_kv = [&](int st, int kt) {
        const __half* kb = base + (size_t)(kt * 64) * C3 + CDIM;
        uint32_t* sk = &smq[ATS_W * (1 + st)];
        uint32_t* sv = sk + 2304;
        #pragma unroll
        for (int i = 0; i < 2; i++) {
            int idx = tid + i * 256;
            int r = idx >> 3, c8 = idx & 7;
            cpasync16(&sk[r * ROWW + c8 * 4], kb + (size_t)r * C3 + c8 * 8);
            cpasync16(&sv[r * ROWW + c8 * 4], kb + (size_t)r * C3 + CDIM + c8 * 8);
        }
        asm volatile("cp.async.commit_group;");
    };

    load_kv(0, 0);

    #pragma unroll
    for (int i = 0; i < 4; i++) {
        int idx = tid + i * 256;
        int r = idx >> 3, c8 = idx & 7;
        uint4 v = *(const uint4*)(base + (size_t)(qb + r) * C3 + c8 * 8);
        *(uint4*)&smq[ATQ_W + r * ROWW + c8 * 4] = v;
    }
    __syncthreads();

    uint32_t qoff = (uint32_t)(16 * warp + (lane & 15)) * ROWB + (uint32_t)(lane >> 4) * 16;
    uint32_t qf[4][4];
    #pragma unroll
    for (int ks = 0; ks < 4; ks++)
        ldmx4(qf[ks], sbase + qoff + (uint32_t)(ks * 32));

    uint32_t koff = (uint32_t)((lane & 7) + ((lane >> 4) << 3)) * ROWB +
                    (uint32_t)((lane >> 3) & 1) * 16;
    uint32_t voff = 2304u * 4 + (uint32_t)(lane & 15) * ROWB + (uint32_t)(lane >> 4) * 16;

    const uint32_t ones[2] = { HONES, HONES };

    float m1 = -1e30f, m2 = -1e30f, l1 = 0.f, l2 = 0.f;
    float oc[8][4];
    #pragma unroll
    for (int j = 0; j < 8; j++)
        #pragma unroll
        for (int r = 0; r < 4; r++) oc[j][r] = 0.f;

    for (int kt = 0; kt < SEQ / 64; kt++) {
        asm volatile("cp.async.wait_group 0;" ::: "memory");
        __syncthreads();
        if (kt + 1 < SEQ / 64) load_kv((kt + 1) & 1, kt + 1);

        uint32_t stb = sbase + (uint32_t)(ATS_W * (1 + (kt & 1)) * 4);

        uint32_t sc[8][2];
        #pragma unroll
        for (int j = 0; j < 8; j++) { sc[j][0] = 0u; sc[j][1] = 0u; }

        #pragma unroll
        for (int ks = 0; ks < 4; ks++) {
            uint32_t kf[4][4];
            #pragma unroll
            for (int nt = 0; nt < 4; nt++)
                ldmx4(kf[nt], stb + koff + (uint32_t)(nt * 16 * ROWB + ks * 32));
            #pragma unroll
            for (int nt = 0; nt < 4; nt++) {
                mma_f16h(sc[2*nt    ], qf[ks], &kf[nt][0]);
                mma_f16h(sc[2*nt + 1], qf[ks], &kf[nt][2]);
            }
        }

        uint32_t mh1 = sc[0][0], mh2 = sc[0][1];
        #pragma unroll
        for (int j = 1; j < 8; j++) {
            mh1 = hmax2(mh1, sc[j][0]);
            mh2 = hmax2(mh2, sc[j][1]);
        }
        __half2 hv1 = *reinterpret_cast<__half2*>(&mh1);
        __half2 hv2 = *reinterpret_cast<__half2*>(&mh2);
        float mx1 = fmaxf(__half2float(__low2half(hv1)), __half2float(__high2half(hv1)));
        float mx2 = fmaxf(__half2float(__low2half(hv2)), __half2float(__high2half(hv2)));
        mx1 = fmaxf(mx1, __shfl_xor_sync(0xffffffffu, mx1, 1));
        mx1 = fmaxf(mx1, __shfl_xor_sync(0xffffffffu, mx1, 2));
        mx2 = fmaxf(mx2, __shfl_xor_sync(0xffffffffu, mx2, 1));
        mx2 = fmaxf(mx2, __shfl_xor_sync(0xffffffffu, mx2, 2));

        float nm1 = fmaxf(m1, mx1), nm2 = fmaxf(m2, mx2);
        float a1 = ex2f(m1 - nm1), a2 = ex2f(m2 - nm2);
        uint32_t nh1 = h2pack(nm1, nm1);
        uint32_t nh2 = h2pack(nm2, nm2);

        uint32_t ph[8][2];
        #pragma unroll
        for (int j = 0; j < 8; j++) {
            ph[j][0] = ex2h2(hsub2(sc[j][0], nh1));
            ph[j][1] = ex2h2(hsub2(sc[j][1], nh2));
        }
        m1 = nm1;  m2 = nm2;
        #pragma unroll
        for (int j = 0; j < 8; j++) {
            oc[j][0] *= a1; oc[j][1] *= a1;
            oc[j][2] *= a2; oc[j][3] *= a2;
        }

        float sums[4] = {0.f, 0.f, 0.f, 0.f};
        #pragma unroll
        for (int ks = 0; ks < 4; ks++) {
            uint32_t pf[4] = { ph[2*ks][0], ph[2*ks][1], ph[2*ks+1][0], ph[2*ks+1][1] };
            mma_f16(sums, pf, ones);
        }
        l1 = l1 * a1 + sums[0];
        l2 = l2 * a2 + sums[2];

        #pragma unroll
        for (int ks = 0; ks < 4; ks++) {
            uint32_t pf[4] = { ph[2*ks][0], ph[2*ks][1], ph[2*ks+1][0], ph[2*ks+1][1] };
            uint32_t vf[4][4];
            #pragma unroll
            for (int dt = 0; dt < 4; dt++)
                ldmx4t(vf[dt], stb + voff + (uint32_t)(ks * 16 * ROWB + dt * 32));
            #pragma unroll
            for (int dt = 0; dt < 4; dt++) {
                mma_f16(oc[2*dt    ], pf, &vf[dt][0]);
                mma_f16(oc[2*dt + 1], pf, &vf[dt][2]);
            }
        }
    }

    float il1 = 1.0f / l1, il2 = 1.0f / l2;
    int r1 = qb + 16 * warp + gr;
    uint32_t* o32 = (uint32_t*)outp;
    #pragma unroll
    for (int j = 0; j < 8; j++) {
        int cc = h * HDIM + (j >> 1) * 16 + (j & 1) * 8 + 2 * t4;
        size_t o0 = ((size_t)(b * SEQ + r1) * CDIM + cc) >> 1;
        size_t o1 = o0 + 4 * CDIM;
        o32[o0] = h2pack(oc[j][0] * il1, oc[j][1] * il1);
        o32[o1] = h2pack(oc[j][2] * il2, oc[j][3] * il2);
    }
}

// ---------------------------------------------------------------------------
// Launch
// ---------------------------------------------------------------------------
extern "C" void kernel_launch(void* const* d_in, const int* in_sizes, int n_in,
                              void* d_out, int out_size)
{
    const float* x      = (const float*)d_in[0];
    const float* ln1_g  = (const float*)d_in[1];
    const float* ln1_b  = (const float*)d_in[2];
    const float* qkv_w  = (const float*)d_in[3];
    const float* qkv_b  = (const float*)d_in[4];
    const float* proj_w = (const float*)d_in[5];
    const float* proj_b = (const float*)d_in[6];
    const float* ln2_g  = (const float*)d_in[7];
    const float* ln2_b  = (const float*)d_in[8];
    const float* fc1_w  = (const float*)d_in[9];
    const float* fc1_b  = (const float*)d_in[10];
    const float* fc2_w  = (const float*)d_in[11];
    const float* fc2_b  = (const float*)d_in[12];
    float* out = (float*)d_out;

    __half *p_xn1, *p_qkv, *p_attn, *p_hn, *p_h1;
    __half *p_wq, *p_wp, *p_w1, *p_w2;
    float  *p_x2;
    cudaGetSymbolAddress((void**)&p_xn1,  g_xn1);
    cudaGetSymbolAddress((void**)&p_qkv,  g_qkv);
    cudaGetSymbolAddress((void**)&p_attn, g_attn);
    cudaGetSymbolAddress((void**)&p_x2,   g_x2);
    cudaGetSymbolAddress((void**)&p_hn,   g_hn);
    cudaGetSymbolAddress((void**)&p_h1,   g_h1);
    cudaGetSymbolAddress((void**)&p_wq,   g_wq);
    cudaGetSymbolAddress((void**)&p_wp,   g_wp);
    cudaGetSymbolAddress((void**)&p_w1,   g_w1);
    cudaGetSymbolAddress((void**)&p_w2,   g_w2);

    cudaFuncSetAttribute(attn_h2,
                         cudaFuncAttributeMaxDynamicSharedMemorySize, ATTN_SMEM);
    cudaFuncSetAttribute((hgemm<false,false,true,true>),
                         cudaFuncAttributeMaxDynamicSharedMemorySize, GEMM_SMEM_BYTES);
    cudaFuncSetAttribute((hgemm<false,true,false,false>),
                         cudaFuncAttributeMaxDynamicSharedMemorySize, GEMM_SMEM_BYTES);
    cudaFuncSetAttribute((hgemm<true,false,true,false>),
                         cudaFuncAttributeMaxDynamicSharedMemorySize, GEMM_SMEM_BYTES);

    // 0) Weight prep (fused)
    wprep_all<<<WPREP_TILES, 256>>>(qkv_w, proj_w, fc1_w, fc2_w,
                                    p_wq, p_wp, p_w1, p_w2);

    // 1) LN1
    ln_kernel<<<TOKENS/8, 256>>>(x, ln1_g, ln1_b, p_xn1);

    // 2) qkv = xn1 @ qkv_w + qkv_b  (half out, q pre-scaled)
    hgemm<false,false,true,true><<<dim3(C3/128, TOKENS/128), 128, GEMM_SMEM_BYTES>>>(
        p_xn1, p_wq, qkv_b, nullptr, p_qkv, TOKENS, C3, CDIM);

    // 3) attention (half out)
    attn_h2<<<dim3(SEQ/128, BATCH*NHEADS), 256, ATTN_SMEM>>>(p_qkv, p_attn);

    // 4) x2 = x + attn @ proj_w + proj_b  (fp32 out)
    hgemm<false,true,false,false><<<dim3(CDIM/128, TOKENS/128), 128, GEMM_SMEM_BYTES>>>(
        p_attn, p_wp, proj_b, x, p_x2, TOKENS, CDIM, CDIM);

    // 5) LN2
    ln_kernel<<<TOKENS/8, 256>>>(p_x2, ln2_g, ln2_b, p_hn);

    // 6) h1 = gelu(hn @ fc1_w + fc1_b)  (half out, fast tanh GELU)
    hgemm<true,false,true,false><<<dim3(HID/128, TOKENS/128), 128, GEMM_SMEM_BYTES>>>(
        p_hn, p_w1, fc1_b, nullptr, p_h1, TOKENS, HID, CDIM);

    // 7) out = x2 + h1 @ fc2_w + fc2_b  (fp32 out)
    hgemm<false,true,false,false><<<dim3(CDIM/128, TOKENS/128), 128, GEMM_SMEM_BYTES>>>(
        p_h1, p_w2, fc2_b, p_x2, out, TOKENS, CDIM, HID);
}